// round 1
// baseline (speedup 1.0000x reference)
#include <cuda_runtime.h>
#include <math.h>

#define NSAMP 65536
#define HID   512
#define NGATE 2048
#define DIN   259

// ------------------------- scratch (static device globals) -------------------------
__device__ float g_Gc   [(size_t)NSAMP * NGATE];   // code @ Wc^T + b_ih   (512 MB)
__device__ float g_gates[(size_t)NSAMP * NGATE];   // per-step gates       (512 MB)
__device__ float g_h    [(size_t)NSAMP * HID];
__device__ float g_c    [(size_t)NSAMP * HID];
__device__ float g_xyz  [NSAMP * 3];
__device__ float g_act0 [(size_t)NSAMP * 256];
__device__ float g_act1 [(size_t)NSAMP * 256];
__device__ float g_w0   [256 * 3];
__device__ float g_wm   [4 * 256 * 256];

// ------------------------- TF32 tiled GEMM: C[m,n] = sum_k A[m,k]*B[n,k] + epilogue
#define BM 128
#define BN 128
#define BK 16

__device__ __forceinline__ unsigned f2tf32(float x) {
    unsigned u; asm("cvt.rna.tf32.f32 %0, %1;" : "=r"(u) : "f"(x)); return u;
}

__device__ __forceinline__ void mma8(float* d, const unsigned* a, const unsigned* b) {
    asm volatile(
        "mma.sync.aligned.m16n8k8.row.col.f32.tf32.tf32.f32 "
        "{%0,%1,%2,%3}, {%4,%5,%6,%7}, {%8,%9}, {%0,%1,%2,%3};"
        : "+f"(d[0]), "+f"(d[1]), "+f"(d[2]), "+f"(d[3])
        : "r"(a[0]), "r"(a[1]), "r"(a[2]), "r"(a[3]), "r"(b[0]), "r"(b[1]));
}

// mode 0: C = acc + bias[n]
// mode 1: C = acc + bias[n] + Gc[m,n] + xyz[m,:]·Wx[n,:]   (gates step)
// mode 2: C = relu(acc + bias[n])                           (decoder)
__global__ __launch_bounds__(256) void gemm_tf32(
    const float* __restrict__ A, int lda,
    const float* __restrict__ B, int ldb,
    float* __restrict__ C, int ldc,
    int K, int mode,
    const float* __restrict__ bias,
    const float* __restrict__ Gc,
    const float* __restrict__ xyz,
    const float* __restrict__ Wx, int ldwx)
{
    __shared__ unsigned As[BM][BK + 4];
    __shared__ unsigned Bs[BN][BK + 4];

    const int tid = threadIdx.x, lane = tid & 31, wid = tid >> 5;
    const int wm0 = (wid & 3) * 32, wn0 = (wid >> 2) * 64;   // 8 warps: 4 (m) x 2 (n)
    const int g = lane >> 2, t = lane & 3;
    const int m0 = blockIdx.y * BM, n0 = blockIdx.x * BN;

    float acc[2][8][4];
#pragma unroll
    for (int i = 0; i < 2; i++)
#pragma unroll
        for (int j = 0; j < 8; j++)
#pragma unroll
            for (int k = 0; k < 4; k++) acc[i][j][k] = 0.f;

    for (int k0 = 0; k0 < K; k0 += BK) {
        __syncthreads();
#pragma unroll
        for (int i = tid; i < BM * BK; i += 256) {
            int m = i >> 4, k = i & 15;
            As[m][k] = f2tf32(A[(size_t)(m0 + m) * lda + k0 + k]);
        }
#pragma unroll
        for (int i = tid; i < BN * BK; i += 256) {
            int n = i >> 4, k = i & 15;
            Bs[n][k] = f2tf32(B[(size_t)(n0 + n) * ldb + k0 + k]);
        }
        __syncthreads();

#pragma unroll
        for (int kk = 0; kk < BK; kk += 8) {
            unsigned af[2][4], bf[8][2];
#pragma unroll
            for (int mt = 0; mt < 2; mt++) {
                int r = wm0 + mt * 16 + g;
                af[mt][0] = As[r][kk + t];
                af[mt][1] = As[r + 8][kk + t];
                af[mt][2] = As[r][kk + t + 4];
                af[mt][3] = As[r + 8][kk + t + 4];
            }
#pragma unroll
            for (int nt = 0; nt < 8; nt++) {
                int cn = wn0 + nt * 8 + g;
                bf[nt][0] = Bs[cn][kk + t];
                bf[nt][1] = Bs[cn][kk + t + 4];
            }
#pragma unroll
            for (int mt = 0; mt < 2; mt++)
#pragma unroll
                for (int nt = 0; nt < 8; nt++)
                    mma8(acc[mt][nt], af[mt], bf[nt]);
        }
    }

    // epilogue
#pragma unroll
    for (int mt = 0; mt < 2; mt++) {
        int rbase = m0 + wm0 + mt * 16 + g;
#pragma unroll
        for (int nt = 0; nt < 8; nt++) {
            int cc = n0 + wn0 + nt * 8 + 2 * t;
#pragma unroll
            for (int rr = 0; rr < 2; rr++) {
                int r = rbase + rr * 8;
                float v0 = acc[mt][nt][rr * 2 + 0];
                float v1 = acc[mt][nt][rr * 2 + 1];
                v0 += bias[cc];
                v1 += bias[cc + 1];
                if (mode == 1) {
                    const float* gc = Gc + (size_t)r * ldc + cc;
                    v0 += gc[0]; v1 += gc[1];
                    float x0 = xyz[r * 3], x1 = xyz[r * 3 + 1], x2 = xyz[r * 3 + 2];
                    const float* wa = Wx + (size_t)cc * ldwx;
                    const float* wb = Wx + (size_t)(cc + 1) * ldwx;
                    v0 += x0 * wa[0] + x1 * wa[1] + x2 * wa[2];
                    v1 += x0 * wb[0] + x1 * wb[1] + x2 * wb[2];
                } else if (mode == 2) {
                    v0 = fmaxf(v0, 0.f);
                    v1 = fmaxf(v1, 0.f);
                }
                *(float2*)(C + (size_t)r * ldc + cc) = make_float2(v0, v1);
            }
        }
    }
}

// ------------------------- weight norm: w[i,k] = v[i,k] * g[i] / ||v[i,:]||
__global__ void wnorm(const float* __restrict__ v, const float* __restrict__ gsc,
                      float* __restrict__ w, int din)
{
    int row = blockIdx.x;
    const float* vr = v + (size_t)row * din;
    float s = 0.f;
    for (int k = threadIdx.x; k < din; k += blockDim.x) { float x = vr[k]; s += x * x; }
    __shared__ float red[4];
#pragma unroll
    for (int o = 16; o; o >>= 1) s += __shfl_xor_sync(0xffffffffu, s, o);
    if ((threadIdx.x & 31) == 0) red[threadIdx.x >> 5] = s;
    __syncthreads();
    float tot = red[0] + red[1] + red[2] + red[3];
    float scale = gsc[row] / sqrtf(tot);
    for (int k = threadIdx.x; k < din; k += blockDim.x)
        w[(size_t)row * din + k] = vr[k] * scale;
}

// ------------------------- init: h=c=0, xyz = input[:,256:259]
__global__ void init_state(const float* __restrict__ input)
{
    size_t idx = (size_t)blockIdx.x * blockDim.x + threadIdx.x;
    if (idx < (size_t)NSAMP * HID) { g_h[idx] = 0.f; g_c[idx] = 0.f; }
    if (idx < NSAMP) {
        const float* row = input + idx * DIN + 256;
        g_xyz[idx * 3 + 0] = row[0];
        g_xyz[idx * 3 + 1] = row[1];
        g_xyz[idx * 3 + 2] = row[2];
    }
}

// ------------------------- LSTM pointwise: gates -> c,h
__global__ void lstm_ew()
{
    size_t idx = (size_t)blockIdx.x * blockDim.x + threadIdx.x;
    int m = (int)(idx / HID), j = (int)(idx % HID);
    const float* gr = g_gates + (size_t)m * NGATE;
    float iv = gr[j], fv = gr[j + HID], gv = gr[j + 2 * HID], ov = gr[j + 3 * HID];
    float c = g_c[idx];
    float si = 1.f / (1.f + expf(-iv));
    float sf = 1.f / (1.f + expf(-fv));
    float so = 1.f / (1.f + expf(-ov));
    float cn = sf * c + si * tanhf(gv);
    g_c[idx] = cn;
    g_h[idx] = so * tanhf(cn);
}

// ------------------------- affine + xyz update: warp per sample
__global__ __launch_bounds__(256) void affine_xyz(const float* __restrict__ W_aff,
                                                  const float* __restrict__ b_aff)
{
    __shared__ float sW[6 * HID];
    for (int i = threadIdx.x; i < 6 * HID; i += 256) sW[i] = W_aff[i];
    __syncthreads();
    int warp = threadIdx.x >> 5, lane = threadIdx.x & 31;
    int m = blockIdx.x * 8 + warp;
    const float* h = g_h + (size_t)m * HID;
    float p0 = 0, p1 = 0, p2 = 0, p3 = 0, p4 = 0, p5 = 0;
    for (int k = lane; k < HID; k += 32) {
        float hv = h[k];
        p0 += sW[k] * hv;          p1 += sW[HID + k] * hv;
        p2 += sW[2 * HID + k] * hv; p3 += sW[3 * HID + k] * hv;
        p4 += sW[4 * HID + k] * hv; p5 += sW[5 * HID + k] * hv;
    }
#pragma unroll
    for (int o = 16; o; o >>= 1) {
        p0 += __shfl_xor_sync(0xffffffffu, p0, o);
        p1 += __shfl_xor_sync(0xffffffffu, p1, o);
        p2 += __shfl_xor_sync(0xffffffffu, p2, o);
        p3 += __shfl_xor_sync(0xffffffffu, p3, o);
        p4 += __shfl_xor_sync(0xffffffffu, p4, o);
        p5 += __shfl_xor_sync(0xffffffffu, p5, o);
    }
    if (lane == 0) {
        float a0 = p0 + b_aff[0], a1 = p1 + b_aff[1], a2 = p2 + b_aff[2];
        float a3 = p3 + b_aff[3], a4 = p4 + b_aff[4], a5 = p5 + b_aff[5];
        float x0 = g_xyz[m * 3], x1 = g_xyz[m * 3 + 1], x2 = g_xyz[m * 3 + 2];
        g_xyz[m * 3 + 0] = a3 + (1.f + a0) * x0;
        g_xyz[m * 3 + 1] = a4 + (1.f + a1) * x1;
        g_xyz[m * 3 + 2] = a5 + (1.f + a2) * x2;
    }
}

// ------------------------- decoder layer 0: (N,3)->(N,256), relu
__global__ __launch_bounds__(256) void dec0(const float* __restrict__ b0)
{
    __shared__ float sw[256 * 3];
    __shared__ float sb[256];
    for (int i = threadIdx.x; i < 768; i += 256) sw[i] = g_w0[i];
    sb[threadIdx.x] = b0[threadIdx.x];
    __syncthreads();
    size_t idx = (size_t)blockIdx.x * 256 + threadIdx.x;   // over NSAMP*256
    int m = (int)(idx >> 8), i = (int)(idx & 255);
    float x0 = g_xyz[m * 3], x1 = g_xyz[m * 3 + 1], x2 = g_xyz[m * 3 + 2];
    float v = sw[i * 3] * x0 + sw[i * 3 + 1] * x1 + sw[i * 3 + 2] * x2 + sb[i];
    g_act0[idx] = fmaxf(v, 0.f);
}

// ------------------------- final layer: (N,256)->(N,1), warp per sample
__global__ __launch_bounds__(256) void dec5(const float* __restrict__ W5,
                                            const float* __restrict__ b5,
                                            const float* __restrict__ x,
                                            float* __restrict__ out)
{
    __shared__ float sw[256];
    sw[threadIdx.x] = W5[threadIdx.x];
    __syncthreads();
    int warp = threadIdx.x >> 5, lane = threadIdx.x & 31;
    int m = blockIdx.x * 8 + warp;
    const float* xr = x + (size_t)m * 256;
    float s = 0.f;
    for (int k = lane; k < 256; k += 32) s += xr[k] * sw[k];
#pragma unroll
    for (int o = 16; o; o >>= 1) s += __shfl_xor_sync(0xffffffffu, s, o);
    if (lane == 0) out[m] = s + b5[0];
}

// ------------------------- host launcher -------------------------
extern "C" void kernel_launch(void* const* d_in, const int* in_sizes, int n_in,
                              void* d_out, int out_size)
{
    const float* input = (const float*)d_in[0];
    const float* W_ih  = (const float*)d_in[1];
    const float* b_ih  = (const float*)d_in[2];
    const float* W_hh  = (const float*)d_in[3];
    const float* b_hh  = (const float*)d_in[4];
    const float* W_aff = (const float*)d_in[5];
    const float* b_aff = (const float*)d_in[6];
    const float *v[5], *gg[5], *bb[5];
    for (int l = 0; l < 5; l++) {
        v[l]  = (const float*)d_in[7 + 3 * l];
        gg[l] = (const float*)d_in[8 + 3 * l];
        bb[l] = (const float*)d_in[9 + 3 * l];
    }
    const float* W5 = (const float*)d_in[22];
    const float* b5 = (const float*)d_in[23];

    float *Gc, *gates, *h, *xyz, *a0p, *a1p, *w0p, *wmp;
    cudaGetSymbolAddress((void**)&Gc,    g_Gc);
    cudaGetSymbolAddress((void**)&gates, g_gates);
    cudaGetSymbolAddress((void**)&h,     g_h);
    cudaGetSymbolAddress((void**)&xyz,   g_xyz);
    cudaGetSymbolAddress((void**)&a0p,   g_act0);
    cudaGetSymbolAddress((void**)&a1p,   g_act1);
    cudaGetSymbolAddress((void**)&w0p,   g_w0);
    cudaGetSymbolAddress((void**)&wmp,   g_wm);

    // weight-normalized decoder weights
    wnorm<<<256, 128>>>(v[0], gg[0], w0p, 3);
    for (int l = 1; l < 5; l++)
        wnorm<<<256, 128>>>(v[l], gg[l], wmp + (size_t)(l - 1) * 256 * 256, 256);

    // state init
    init_state<<<(NSAMP * HID) / 256, 256>>>(input);

    // Gc = code @ W_ih[:, :256]^T + b_ih
    gemm_tf32<<<dim3(NGATE / BN, NSAMP / BM), 256>>>(
        input, DIN, W_ih, DIN, Gc, NGATE,
        256, 0, b_ih, nullptr, nullptr, nullptr, 0);

    // 8 LSTM steps
    for (int s = 0; s < 8; s++) {
        gemm_tf32<<<dim3(NGATE / BN, NSAMP / BM), 256>>>(
            h, HID, W_hh, HID, gates, NGATE,
            HID, 1, b_hh, Gc, xyz, W_ih + 256, DIN);
        lstm_ew<<<(NSAMP * HID) / 256, 256>>>();
        affine_xyz<<<NSAMP / 8, 256>>>(W_aff, b_aff);
    }

    // decoder
    dec0<<<NSAMP, 256>>>(bb[0]);
    const float* bufin = a0p;
    float* bufout = a1p;
    for (int l = 1; l < 5; l++) {
        gemm_tf32<<<dim3(256 / BN, NSAMP / BM), 256>>>(
            bufin, 256, wmp + (size_t)(l - 1) * 256 * 256, 256,
            bufout, 256, 256, 2, bb[l], nullptr, nullptr, nullptr, 0);
        const float* tmp = bufout; bufout = (float*)bufin; bufin = tmp;
    }
    dec5<<<NSAMP / 8, 256>>>(W5, b5, bufin, (float*)d_out);
}

// round 2
// speedup vs baseline: 1.2980x; 1.2980x over previous
#include <cuda_runtime.h>
#include <math.h>

#define NSAMP 65536
#define HID   512
#define NGATE 2048
#define DIN   259
#define BM 128
#define BN 128
#define BK 16
#define SPAD 20

// ------------------------- scratch -------------------------
__device__ float g_Gc [(size_t)NSAMP * NGATE];   // code@Wc^T + b_ih + b_hh (512 MB)
__device__ float g_h  [(size_t)NSAMP * HID];
__device__ float g_h2 [(size_t)NSAMP * HID];
__device__ float g_c  [(size_t)NSAMP * HID];
__device__ float g_xyz[NSAMP * 3];
__device__ float g_act0[(size_t)NSAMP * 256];
__device__ float g_act1[(size_t)NSAMP * 256];
__device__ float g_w0 [256 * 3];
__device__ float g_wm [4 * 256 * 256];

__device__ __forceinline__ unsigned f2tf32(float x) {
    unsigned u; asm("cvt.rna.tf32.f32 %0, %1;" : "=r"(u) : "f"(x)); return u;
}
__device__ __forceinline__ void mma8(float* d, const unsigned* a, const unsigned* b) {
    asm volatile(
        "mma.sync.aligned.m16n8k8.row.col.f32.tf32.tf32.f32 "
        "{%0,%1,%2,%3}, {%4,%5,%6,%7}, {%8,%9}, {%0,%1,%2,%3};"
        : "+f"(d[0]), "+f"(d[1]), "+f"(d[2]), "+f"(d[3])
        : "r"(a[0]), "r"(a[1]), "r"(a[2]), "r"(a[3]), "r"(b[0]), "r"(b[1]));
}
__device__ __forceinline__ float sigm(float x) { return 1.f / (1.f + __expf(-x)); }

// =====================================================================
// TF32 GEMM, double-buffered, 8 warps = 4(m) x 2(n), warp tile 32x64.
// MODE 0: C = acc + bias[n] + bias2[n]                       (Gc build)
// MODE 1: fused LSTM step. B rows gathered so a 128-col block tile =
//         32 hidden units x 4 gates; xyz appended to K (K=515, pad 528).
//         Epilogue does the full LSTM cell update (reads Gc, c; writes c, h).
// MODE 2: C = relu(acc + bias[n])                            (decoder)
// =====================================================================
template<int MODE>
__global__ __launch_bounds__(256, 2) void gemm2(
    const float* __restrict__ A, int lda,
    const float* __restrict__ B, int ldb,
    float* __restrict__ C, int ldc,
    int kIters,
    const float* __restrict__ bias, const float* __restrict__ bias2,
    const float* __restrict__ Wih,   // MODE1: W_ih (for xyz tail cols)
    const float* __restrict__ xyz,   // MODE1
    const float* __restrict__ Gc,    // MODE1
    float* __restrict__ cst,         // MODE1: cell state (in-place)
    float* __restrict__ hout)        // MODE1: next h
{
    __shared__ unsigned As[2][BM][SPAD];
    __shared__ unsigned Bs[2][BN][SPAD];

    const int tid = threadIdx.x, lane = tid & 31, wid = tid >> 5;
    const int wm = wid & 3, wnn = wid >> 2;
    const int g = lane >> 2, t = lane & 3;
    const int m0 = blockIdx.y * BM;
    const int n0 = blockIdx.x * BN;
    const int j0 = blockIdx.x * 32;      // MODE1: hidden-unit tile

    const int lm = tid >> 4;             // 0..15
    const int lk = tid & 15;

    int aoff[8], boff[8], brow[8];
#pragma unroll
    for (int q = 0; q < 8; q++) {
        int m = lm + 16 * q;
        aoff[q] = (m0 + m) * lda;
        int n = lm + 16 * q;
        int row;
        if (MODE == 1) {
            int w = n >> 6, cw = n & 63, gate = cw >> 4, jl = (cw & 15) + (w << 4);
            row = gate * HID + j0 + jl;
        } else row = n0 + n;
        brow[q] = row;
        boff[q] = row * ldb;
    }

    float ra[8], rb[8];
    float acc[2][8][4];
#pragma unroll
    for (int i = 0; i < 2; i++)
#pragma unroll
        for (int j = 0; j < 8; j++)
#pragma unroll
            for (int k = 0; k < 4; k++) acc[i][j][k] = 0.f;

#define FETCH(K0)                                                          \
    do {                                                                   \
        int kg = (K0) + lk;                                                \
        _Pragma("unroll")                                                  \
        for (int q = 0; q < 8; q++) {                                      \
            float av, bv;                                                  \
            if (MODE == 1) {                                               \
                if (kg < HID) av = A[aoff[q] + kg];                        \
                else if (kg < HID + 3)                                     \
                    av = xyz[(m0 + lm + 16 * q) * 3 + (kg - HID)];         \
                else av = 0.f;                                             \
                if (kg < HID) bv = B[boff[q] + kg];                        \
                else if (kg < HID + 3)                                     \
                    bv = Wih[brow[q] * DIN + 256 + (kg - HID)];            \
                else bv = 0.f;                                             \
            } else {                                                       \
                av = A[aoff[q] + kg];                                      \
                bv = B[boff[q] + kg];                                      \
            }                                                              \
            ra[q] = av; rb[q] = bv;                                        \
        }                                                                  \
    } while (0)

#define STS(BUF)                                                           \
    do {                                                                   \
        _Pragma("unroll")                                                  \
        for (int q = 0; q < 8; q++) {                                      \
            As[BUF][lm + 16 * q][lk] = f2tf32(ra[q]);                      \
            Bs[BUF][lm + 16 * q][lk] = f2tf32(rb[q]);                      \
        }                                                                  \
    } while (0)

    FETCH(0);
    STS(0);

    for (int it = 0; it < kIters; ++it) {
        __syncthreads();
        if (it + 1 < kIters) FETCH((it + 1) * BK);
        const int buf = it & 1;
#pragma unroll
        for (int kk = 0; kk < BK; kk += 8) {
            unsigned af[2][4];
#pragma unroll
            for (int mt = 0; mt < 2; mt++) {
                int r = wm * 32 + mt * 16 + g;
                af[mt][0] = As[buf][r][kk + t];
                af[mt][1] = As[buf][r + 8][kk + t];
                af[mt][2] = As[buf][r][kk + t + 4];
                af[mt][3] = As[buf][r + 8][kk + t + 4];
            }
#pragma unroll
            for (int nt = 0; nt < 8; nt++) {
                unsigned bf[2];
                int cn = wnn * 64 + nt * 8 + g;
                bf[0] = Bs[buf][cn][kk + t];
                bf[1] = Bs[buf][cn][kk + t + 4];
                mma8(acc[0][nt], af[0], bf);
                mma8(acc[1][nt], af[1], bf);
            }
        }
        if (it + 1 < kIters) STS((it + 1) & 1);
    }

    // ----------------- epilogue -----------------
    if (MODE == 1) {
#pragma unroll
        for (int mt = 0; mt < 2; mt++)
#pragma unroll
            for (int rr = 0; rr < 2; rr++) {
                int r = m0 + wm * 32 + mt * 16 + g + rr * 8;
#pragma unroll
                for (int nt = 0; nt < 2; nt++) {
                    int j = j0 + wnn * 16 + nt * 8 + 2 * t;
                    const float* gcr = Gc + (size_t)r * NGATE + j;
                    float2 gi = *(const float2*)(gcr);
                    float2 gf = *(const float2*)(gcr + HID);
                    float2 gg = *(const float2*)(gcr + 2 * HID);
                    float2 go = *(const float2*)(gcr + 3 * HID);
                    float2 co = *(const float2*)(cst + (size_t)r * HID + j);
                    float2 cn, hn;
#pragma unroll
                    for (int e = 0; e < 2; e++) {
                        int a = rr * 2 + e;
                        float iv = acc[mt][nt    ][a] + (e ? gi.y : gi.x);
                        float fv = acc[mt][nt + 2][a] + (e ? gf.y : gf.x);
                        float gv = acc[mt][nt + 4][a] + (e ? gg.y : gg.x);
                        float ov = acc[mt][nt + 6][a] + (e ? go.y : go.x);
                        float cold = e ? co.y : co.x;
                        float c2 = sigm(fv) * cold + sigm(iv) * tanhf(gv);
                        float h2 = sigm(ov) * tanhf(c2);
                        if (e) { cn.y = c2; hn.y = h2; } else { cn.x = c2; hn.x = h2; }
                    }
                    *(float2*)(cst  + (size_t)r * HID + j) = cn;
                    *(float2*)(hout + (size_t)r * HID + j) = hn;
                }
            }
    } else {
#pragma unroll
        for (int mt = 0; mt < 2; mt++)
#pragma unroll
            for (int nt = 0; nt < 8; nt++) {
                int c = n0 + wnn * 64 + nt * 8 + 2 * t;
                float bb0 = bias[c], bb1 = bias[c + 1];
                if (MODE == 0) { bb0 += bias2[c]; bb1 += bias2[c + 1]; }
#pragma unroll
                for (int rr = 0; rr < 2; rr++) {
                    int r = m0 + wm * 32 + mt * 16 + g + rr * 8;
                    float v0 = acc[mt][nt][rr * 2 + 0] + bb0;
                    float v1 = acc[mt][nt][rr * 2 + 1] + bb1;
                    if (MODE == 2) { v0 = fmaxf(v0, 0.f); v1 = fmaxf(v1, 0.f); }
                    *(float2*)(C + (size_t)r * ldc + c) = make_float2(v0, v1);
                }
            }
    }
#undef FETCH
#undef STS
}

// ------------------------- weight norm -------------------------
__global__ void wnorm(const float* __restrict__ v, const float* __restrict__ gsc,
                      float* __restrict__ w, int din)
{
    int row = blockIdx.x;
    const float* vr = v + (size_t)row * din;
    float s = 0.f;
    for (int k = threadIdx.x; k < din; k += blockDim.x) { float x = vr[k]; s += x * x; }
    __shared__ float red[4];
#pragma unroll
    for (int o = 16; o; o >>= 1) s += __shfl_xor_sync(0xffffffffu, s, o);
    if ((threadIdx.x & 31) == 0) red[threadIdx.x >> 5] = s;
    __syncthreads();
    float tot = red[0] + red[1] + red[2] + red[3];
    float scale = gsc[row] / sqrtf(tot);
    for (int k = threadIdx.x; k < din; k += blockDim.x)
        w[(size_t)row * din + k] = vr[k] * scale;
}

// ------------------------- init xyz -------------------------
__global__ void init_xyz(const float* __restrict__ input)
{
    int m = blockIdx.x * blockDim.x + threadIdx.x;
    const float* row = input + (size_t)m * DIN + 256;
    g_xyz[m * 3 + 0] = row[0];
    g_xyz[m * 3 + 1] = row[1];
    g_xyz[m * 3 + 2] = row[2];
}

// ------------------------- step 0: h=c=0 so gates = Gc + xyz0*Wx ----
__global__ __launch_bounds__(256) void step0(const float* __restrict__ Wih)
{
    size_t idx = (size_t)blockIdx.x * 256 + threadIdx.x;   // NSAMP*HID
    int m = (int)(idx >> 9), j = (int)(idx & 511);
    float x0 = g_xyz[m * 3], x1 = g_xyz[m * 3 + 1], x2 = g_xyz[m * 3 + 2];
    float gv[4];
#pragma unroll
    for (int gate = 0; gate < 4; gate++) {
        int row = gate * HID + j;
        const float* wr = Wih + (size_t)row * DIN + 256;
        gv[gate] = g_Gc[(size_t)m * NGATE + row] + x0 * wr[0] + x1 * wr[1] + x2 * wr[2];
    }
    float c = sigm(gv[0]) * tanhf(gv[2]);          // f-gate * 0 drops
    float h = sigm(gv[3]) * tanhf(c);
    g_c[idx] = c;
    g_h[idx] = h;
}

// ------------------------- affine + xyz update -------------------------
__global__ __launch_bounds__(256) void affine_xyz(const float* __restrict__ h_in,
                                                  const float* __restrict__ W_aff,
                                                  const float* __restrict__ b_aff)
{
    __shared__ float sW[6 * HID];
    for (int i = threadIdx.x; i < 6 * HID; i += 256) sW[i] = W_aff[i];
    __syncthreads();
    int warp = threadIdx.x >> 5, lane = threadIdx.x & 31;
    int m = blockIdx.x * 8 + warp;
    const float* h = h_in + (size_t)m * HID;
    float p0 = 0, p1 = 0, p2 = 0, p3 = 0, p4 = 0, p5 = 0;
    for (int k = lane; k < HID; k += 32) {
        float hv = h[k];
        p0 += sW[k] * hv;           p1 += sW[HID + k] * hv;
        p2 += sW[2 * HID + k] * hv; p3 += sW[3 * HID + k] * hv;
        p4 += sW[4 * HID + k] * hv; p5 += sW[5 * HID + k] * hv;
    }
#pragma unroll
    for (int o = 16; o; o >>= 1) {
        p0 += __shfl_xor_sync(0xffffffffu, p0, o);
        p1 += __shfl_xor_sync(0xffffffffu, p1, o);
        p2 += __shfl_xor_sync(0xffffffffu, p2, o);
        p3 += __shfl_xor_sync(0xffffffffu, p3, o);
        p4 += __shfl_xor_sync(0xffffffffu, p4, o);
        p5 += __shfl_xor_sync(0xffffffffu, p5, o);
    }
    if (lane == 0) {
        float a0 = p0 + b_aff[0], a1 = p1 + b_aff[1], a2 = p2 + b_aff[2];
        float a3 = p3 + b_aff[3], a4 = p4 + b_aff[4], a5 = p5 + b_aff[5];
        float x0 = g_xyz[m * 3], x1 = g_xyz[m * 3 + 1], x2 = g_xyz[m * 3 + 2];
        g_xyz[m * 3 + 0] = a3 + (1.f + a0) * x0;
        g_xyz[m * 3 + 1] = a4 + (1.f + a1) * x1;
        g_xyz[m * 3 + 2] = a5 + (1.f + a2) * x2;
    }
}

// ------------------------- decoder layer 0: (N,3)->(N,256), relu ----
__global__ __launch_bounds__(256) void dec0(const float* __restrict__ b0)
{
    __shared__ float sw[256 * 3];
    __shared__ float sb[256];
    for (int i = threadIdx.x; i < 768; i += 256) sw[i] = g_w0[i];
    sb[threadIdx.x] = b0[threadIdx.x];
    __syncthreads();
    size_t idx = (size_t)blockIdx.x * 256 + threadIdx.x;
    int m = (int)(idx >> 8), i = (int)(idx & 255);
    float x0 = g_xyz[m * 3], x1 = g_xyz[m * 3 + 1], x2 = g_xyz[m * 3 + 2];
    float v = sw[i * 3] * x0 + sw[i * 3 + 1] * x1 + sw[i * 3 + 2] * x2 + sb[i];
    g_act0[idx] = fmaxf(v, 0.f);
}

// ------------------------- final dot -------------------------
__global__ __launch_bounds__(256) void dec5(const float* __restrict__ W5,
                                            const float* __restrict__ b5,
                                            const float* __restrict__ x,
                                            float* __restrict__ out)
{
    __shared__ float sw[256];
    sw[threadIdx.x] = W5[threadIdx.x];
    __syncthreads();
    int warp = threadIdx.x >> 5, lane = threadIdx.x & 31;
    int m = blockIdx.x * 8 + warp;
    const float* xr = x + (size_t)m * 256;
    float s = 0.f;
    for (int k = lane; k < 256; k += 32) s += xr[k] * sw[k];
#pragma unroll
    for (int o = 16; o; o >>= 1) s += __shfl_xor_sync(0xffffffffu, s, o);
    if (lane == 0) out[m] = s + b5[0];
}

// ------------------------- host launcher -------------------------
extern "C" void kernel_launch(void* const* d_in, const int* in_sizes, int n_in,
                              void* d_out, int out_size)
{
    const float* input = (const float*)d_in[0];
    const float* W_ih  = (const float*)d_in[1];
    const float* b_ih  = (const float*)d_in[2];
    const float* W_hh  = (const float*)d_in[3];
    const float* b_hh  = (const float*)d_in[4];
    const float* W_aff = (const float*)d_in[5];
    const float* b_aff = (const float*)d_in[6];
    const float *v[5], *gg[5], *bb[5];
    for (int l = 0; l < 5; l++) {
        v[l]  = (const float*)d_in[7 + 3 * l];
        gg[l] = (const float*)d_in[8 + 3 * l];
        bb[l] = (const float*)d_in[9 + 3 * l];
    }
    const float* W5 = (const float*)d_in[22];
    const float* b5 = (const float*)d_in[23];

    float *Gc, *h0, *h1, *cst, *xyz, *a0p, *a1p, *w0p, *wmp;
    cudaGetSymbolAddress((void**)&Gc,  g_Gc);
    cudaGetSymbolAddress((void**)&h0,  g_h);
    cudaGetSymbolAddress((void**)&h1,  g_h2);
    cudaGetSymbolAddress((void**)&cst, g_c);
    cudaGetSymbolAddress((void**)&xyz, g_xyz);
    cudaGetSymbolAddress((void**)&a0p, g_act0);
    cudaGetSymbolAddress((void**)&a1p, g_act1);
    cudaGetSymbolAddress((void**)&w0p, g_w0);
    cudaGetSymbolAddress((void**)&wmp, g_wm);

    // decoder WN weights
    wnorm<<<256, 128>>>(v[0], gg[0], w0p, 3);
    for (int l = 1; l < 5; l++)
        wnorm<<<256, 128>>>(v[l], gg[l], wmp + (size_t)(l - 1) * 256 * 256, 256);

    init_xyz<<<NSAMP / 256, 256>>>(input);

    // Gc = code @ W_ih[:, :256]^T + b_ih + b_hh
    gemm2<0><<<dim3(NGATE / BN, NSAMP / BM), 256>>>(
        input, DIN, W_ih, DIN, Gc, NGATE, 256 / BK,
        b_ih, b_hh, nullptr, nullptr, nullptr, nullptr, nullptr);

    // step 0 (h=c=0): elementwise
    step0<<<(NSAMP * HID) / 256, 256>>>(W_ih);
    affine_xyz<<<NSAMP / 8, 256>>>(h0, W_aff, b_aff);

    // steps 1..7: fused GEMM + LSTM cell, h ping-pong
    float* hb[2] = { h0, h1 };
    for (int s = 1; s < 8; s++) {
        const float* hin = hb[(s - 1) & 1];
        float* hnew = hb[s & 1];
        gemm2<1><<<dim3(HID / 32, NSAMP / BM), 256>>>(
            hin, HID, W_hh, HID, nullptr, 0, 33,   // K = 515 padded to 528
            nullptr, nullptr, W_ih, xyz, Gc, cst, hnew);
        affine_xyz<<<NSAMP / 8, 256>>>(hnew, W_aff, b_aff);
    }

    // decoder
    dec0<<<NSAMP, 256>>>(bb[0]);
    const float* bufin = a0p;
    float* bufout = a1p;
    for (int l = 1; l < 5; l++) {
        gemm2<2><<<dim3(256 / BN, NSAMP / BM), 256>>>(
            bufin, 256, wmp + (size_t)(l - 1) * 256 * 256, 256,
            bufout, 256, 256 / BK,
            bb[l], nullptr, nullptr, nullptr, nullptr, nullptr, nullptr);
        const float* tmp = bufout; bufout = (float*)bufin; bufin = tmp;
    }
    dec5<<<NSAMP / 8, 256>>>(W5, b5, bufin, (float*)d_out);
}

// round 3
// speedup vs baseline: 1.3189x; 1.0161x over previous
#include <cuda_runtime.h>
#include <math.h>
#include <stdint.h>

#define NSAMP 65536
#define HID   512
#define NGATE 2048
#define DIN   259
#define BM 128
#define BN 256
#define BK 16
#define PAD 20            // smem row stride in floats

// ------------------------- scratch -------------------------
__device__ float g_Gc  [(size_t)NSAMP * NGATE];   // 512 MB
__device__ float g_h   [(size_t)NSAMP * HID];
__device__ float g_h2  [(size_t)NSAMP * HID];
__device__ float g_c   [(size_t)NSAMP * HID];
__device__ float g_xyz [NSAMP * 3];
__device__ float g_code[(size_t)NSAMP * 256];     // tf32-rounded code
__device__ float g_wih [(size_t)NGATE * 256];     // tf32-rounded, packed
__device__ float g_whh [(size_t)NGATE * HID];     // tf32-rounded
__device__ float g_act0[(size_t)NSAMP * 256];
__device__ float g_act1[(size_t)NSAMP * 256];
__device__ float g_w0  [256 * 3];
__device__ float g_wm  [4 * 256 * 256];

__device__ __forceinline__ unsigned f2tf32(float x) {
    unsigned u; asm("cvt.rna.tf32.f32 %0, %1;" : "=r"(u) : "f"(x)); return u;
}
__device__ __forceinline__ float rndf(float x) { return __uint_as_float(f2tf32(x)); }
__device__ __forceinline__ void mma8(float* d, const unsigned* a, unsigned b0, unsigned b1) {
    asm volatile(
        "mma.sync.aligned.m16n8k8.row.col.f32.tf32.tf32.f32 "
        "{%0,%1,%2,%3}, {%4,%5,%6,%7}, {%8,%9}, {%0,%1,%2,%3};"
        : "+f"(d[0]), "+f"(d[1]), "+f"(d[2]), "+f"(d[3])
        : "r"(a[0]), "r"(a[1]), "r"(a[2]), "r"(a[3]), "r"(b0), "r"(b1));
}
__device__ __forceinline__ float sigm(float x) { return 1.f / (1.f + __expf(-x)); }
__device__ __forceinline__ void cp16(uint32_t d, const void* s) {
    asm volatile("cp.async.cg.shared.global [%0], [%1], 16;" :: "r"(d), "l"(s) : "memory");
}

// =====================================================================
// TF32 GEMM, cp.async double-buffered, 8 warps = 2(m) x 4(n), 64x64 each.
// MODE 0: C = acc + bias[n] + bias2[n]
// MODE 1: fused LSTM step (gathered gate columns, xyz rank-3 + Gc + cell
//         update in epilogue; writes c and tf32-rounded h)
// MODE 2: C = round(relu(acc + bias[n]))
// =====================================================================
template<int MODE>
__global__ void __launch_bounds__(256) gemm3(
    const float* __restrict__ A, int lda,
    const float* __restrict__ B, int ldb,
    float* __restrict__ C, int ldc, int kIters,
    const float* __restrict__ bias, const float* __restrict__ bias2,
    const float* __restrict__ Wih, const float* __restrict__ xyz,
    const float* __restrict__ Gc,
    float* __restrict__ cst, float* __restrict__ hout)
{
    extern __shared__ float smem[];
    float* AsF = smem;                   // [2][BM][PAD]
    float* BsF = smem + 2 * BM * PAD;    // [2][BN][PAD]

    const int tid = threadIdx.x, lane = tid & 31, wid = tid >> 5;
    const int wm = wid >> 2, wn = wid & 3;
    const int g = lane >> 2, t = lane & 3;
    const int m0 = blockIdx.y * BM;
    const int n0 = blockIdx.x * BN;
    const int j0 = blockIdx.x * 64;      // MODE1 hidden-unit tile

    // --- load-role indices ---
    const int ar = tid >> 1;                       // A row (0..127)
    const int ac = (tid & 1) * 8;                  // A col start (0 or 8)
    int brow;                                      // B global row for smem row = tid
    if (MODE == 1) {
        int w = tid >> 6, cw = tid & 63;
        int gate = cw >> 4, jl = (cw & 15) + (w << 4);
        brow = gate * HID + j0 + jl;
    } else brow = n0 + tid;

    const float* aptr = A + (size_t)(m0 + ar) * lda + ac;
    const float* bptr = B + (size_t)brow * ldb;

    const uint32_t asbase = (uint32_t)__cvta_generic_to_shared(AsF);
    const uint32_t bsbase = (uint32_t)__cvta_generic_to_shared(BsF);

    float acc[4][8][4];
#pragma unroll
    for (int i = 0; i < 4; i++)
#pragma unroll
        for (int j = 0; j < 8; j++)
#pragma unroll
            for (int k = 0; k < 4; k++) acc[i][j][k] = 0.f;

#define LOADTILE(IT, BUF)                                                     \
    do {                                                                      \
        const float* sa = aptr + (IT) * BK;                                   \
        uint32_t da = asbase + (((BUF) * BM + ar) * PAD + ac) * 4;            \
        cp16(da, sa); cp16(da + 16, sa + 4);                                  \
        const float* sb = bptr + (IT) * BK;                                   \
        uint32_t db = bsbase + (((BUF) * BN + tid) * PAD) * 4;                \
        cp16(db, sb); cp16(db + 16, sb + 4);                                  \
        cp16(db + 32, sb + 8); cp16(db + 48, sb + 12);                        \
    } while (0)

    LOADTILE(0, 0);
    asm volatile("cp.async.commit_group;" ::: "memory");

    for (int it = 0; it < kIters; ++it) {
        asm volatile("cp.async.wait_group 0;" ::: "memory");
        __syncthreads();
        if (it + 1 < kIters) {
            LOADTILE(it + 1, (it + 1) & 1);
            asm volatile("cp.async.commit_group;" ::: "memory");
        }
        const int buf = it & 1;
        const unsigned* as = (const unsigned*)(AsF + buf * BM * PAD);
        const unsigned* bs = (const unsigned*)(BsF + buf * BN * PAD);
#pragma unroll
        for (int kk = 0; kk < BK; kk += 8) {
            unsigned af[4][4];
#pragma unroll
            for (int mt = 0; mt < 4; mt++) {
                int r = wm * 64 + mt * 16 + g;
                af[mt][0] = as[r * PAD + kk + t];
                af[mt][1] = as[(r + 8) * PAD + kk + t];
                af[mt][2] = as[r * PAD + kk + t + 4];
                af[mt][3] = as[(r + 8) * PAD + kk + t + 4];
            }
#pragma unroll
            for (int nt = 0; nt < 8; nt++) {
                int cn = wn * 64 + nt * 8 + g;
                unsigned b0 = bs[cn * PAD + kk + t];
                unsigned b1 = bs[cn * PAD + kk + t + 4];
#pragma unroll
                for (int mt = 0; mt < 4; mt++)
                    mma8(acc[mt][nt], af[mt], b0, b1);
            }
        }
    }
#undef LOADTILE

    // ----------------- epilogue -----------------
    if (MODE == 1) {
#pragma unroll
        for (int q = 0; q < 2; q++) {
            const int jc = j0 + wn * 16 + q * 8 + 2 * t;
            float wt[4][2][3];
#pragma unroll
            for (int gt = 0; gt < 4; gt++)
#pragma unroll
                for (int e = 0; e < 2; e++) {
                    const float* wr = Wih + (size_t)(gt * HID + jc + e) * DIN + 256;
                    wt[gt][e][0] = wr[0]; wt[gt][e][1] = wr[1]; wt[gt][e][2] = wr[2];
                }
#pragma unroll
            for (int mt = 0; mt < 4; mt++)
#pragma unroll
                for (int rr = 0; rr < 2; rr++) {
                    int r = m0 + wm * 64 + mt * 16 + g + rr * 8;
                    float x0 = xyz[r * 3], x1 = xyz[r * 3 + 1], x2 = xyz[r * 3 + 2];
                    const float* gcr = Gc + (size_t)r * NGATE + jc;
                    float2 co = *(const float2*)(cst + (size_t)r * HID + jc);
                    float2 cn, hn;
#pragma unroll
                    for (int e = 0; e < 2; e++) {
                        int a = rr * 2 + e;
                        float iv = acc[mt][0 + q][a] + gcr[e]
                                 + x0 * wt[0][e][0] + x1 * wt[0][e][1] + x2 * wt[0][e][2];
                        float fv = acc[mt][2 + q][a] + gcr[HID + e]
                                 + x0 * wt[1][e][0] + x1 * wt[1][e][1] + x2 * wt[1][e][2];
                        float gv = acc[mt][4 + q][a] + gcr[2 * HID + e]
                                 + x0 * wt[2][e][0] + x1 * wt[2][e][1] + x2 * wt[2][e][2];
                        float ov = acc[mt][6 + q][a] + gcr[3 * HID + e]
                                 + x0 * wt[3][e][0] + x1 * wt[3][e][1] + x2 * wt[3][e][2];
                        float cold = e ? co.y : co.x;
                        float c2 = sigm(fv) * cold + sigm(iv) * tanhf(gv);
                        float h2 = rndf(sigm(ov) * tanhf(c2));
                        if (e) { cn.y = c2; hn.y = h2; } else { cn.x = c2; hn.x = h2; }
                    }
                    *(float2*)(cst  + (size_t)r * HID + jc) = cn;
                    *(float2*)(hout + (size_t)r * HID + jc) = hn;
                }
        }
    } else {
#pragma unroll
        for (int mt = 0; mt < 4; mt++)
#pragma unroll
            for (int nt = 0; nt < 8; nt++) {
                int c = n0 + wn * 64 + nt * 8 + 2 * t;
                float b0v = bias[c], b1v = bias[c + 1];
                if (MODE == 0) { b0v += bias2[c]; b1v += bias2[c + 1]; }
#pragma unroll
                for (int rr = 0; rr < 2; rr++) {
                    int r = m0 + wm * 64 + mt * 16 + g + rr * 8;
                    float v0 = acc[mt][nt][rr * 2 + 0] + b0v;
                    float v1 = acc[mt][nt][rr * 2 + 1] + b1v;
                    if (MODE == 2) {
                        v0 = rndf(fmaxf(v0, 0.f));
                        v1 = rndf(fmaxf(v1, 0.f));
                    }
                    *(float2*)(C + (size_t)r * ldc + c) = make_float2(v0, v1);
                }
            }
    }
}

// ------------------------- prep kernels -------------------------
__global__ void extract_code(const float* __restrict__ input)
{
    int m = blockIdx.x, k = threadIdx.x;
    g_code[(size_t)m * 256 + k] = rndf(input[(size_t)m * DIN + k]);
    if (k < 3) g_xyz[m * 3 + k] = input[(size_t)m * DIN + 256 + k];
}
__global__ void pack_wih(const float* __restrict__ W)
{
    int r = blockIdx.x, k = threadIdx.x;
    g_wih[(size_t)r * 256 + k] = rndf(W[(size_t)r * DIN + k]);
}
__global__ void round_whh(const float* __restrict__ W)
{
    size_t i = (size_t)blockIdx.x * 256 + threadIdx.x;
    g_whh[i] = rndf(W[i]);
}

// ------------------------- weight norm (tf32-rounded output) --------
__global__ void wnorm(const float* __restrict__ v, const float* __restrict__ gsc,
                      float* __restrict__ w, int din)
{
    int row = blockIdx.x;
    const float* vr = v + (size_t)row * din;
    float s = 0.f;
    for (int k = threadIdx.x; k < din; k += blockDim.x) { float x = vr[k]; s += x * x; }
    __shared__ float red[4];
#pragma unroll
    for (int o = 16; o; o >>= 1) s += __shfl_xor_sync(0xffffffffu, s, o);
    if ((threadIdx.x & 31) == 0) red[threadIdx.x >> 5] = s;
    __syncthreads();
    float tot = red[0] + red[1] + red[2] + red[3];
    float scale = gsc[row] / sqrtf(tot);
    for (int k = threadIdx.x; k < din; k += blockDim.x)
        w[(size_t)row * din + k] = rndf(vr[k] * scale);
}

// ------------------------- step 0 -------------------------
__global__ __launch_bounds__(256) void step0(const float* __restrict__ Wih)
{
    size_t idx = (size_t)blockIdx.x * 256 + threadIdx.x;
    int m = (int)(idx >> 9), j = (int)(idx & 511);
    float x0 = g_xyz[m * 3], x1 = g_xyz[m * 3 + 1], x2 = g_xyz[m * 3 + 2];
    float gv[4];
#pragma unroll
    for (int gate = 0; gate < 4; gate++) {
        int row = gate * HID + j;
        const float* wr = Wih + (size_t)row * DIN + 256;
        gv[gate] = g_Gc[(size_t)m * NGATE + row] + x0 * wr[0] + x1 * wr[1] + x2 * wr[2];
    }
    float c = sigm(gv[0]) * tanhf(gv[2]);
    float h = sigm(gv[3]) * tanhf(c);
    g_c[idx] = c;
    g_h[idx] = rndf(h);
}

// ------------------------- affine + xyz update -------------------------
__global__ __launch_bounds__(256) void affine_xyz(const float* __restrict__ h_in,
                                                  const float* __restrict__ W_aff,
                                                  const float* __restrict__ b_aff)
{
    __shared__ float sW[6 * HID];
    for (int i = threadIdx.x; i < 6 * HID; i += 256) sW[i] = W_aff[i];
    __syncthreads();
    int warp = threadIdx.x >> 5, lane = threadIdx.x & 31;
    int m = blockIdx.x * 8 + warp;
    const float* h = h_in + (size_t)m * HID;
    float p0 = 0, p1 = 0, p2 = 0, p3 = 0, p4 = 0, p5 = 0;
    for (int k = lane; k < HID; k += 32) {
        float hv = h[k];
        p0 += sW[k] * hv;           p1 += sW[HID + k] * hv;
        p2 += sW[2 * HID + k] * hv; p3 += sW[3 * HID + k] * hv;
        p4 += sW[4 * HID + k] * hv; p5 += sW[5 * HID + k] * hv;
    }
#pragma unroll
    for (int o = 16; o; o >>= 1) {
        p0 += __shfl_xor_sync(0xffffffffu, p0, o);
        p1 += __shfl_xor_sync(0xffffffffu, p1, o);
        p2 += __shfl_xor_sync(0xffffffffu, p2, o);
        p3 += __shfl_xor_sync(0xffffffffu, p3, o);
        p4 += __shfl_xor_sync(0xffffffffu, p4, o);
        p5 += __shfl_xor_sync(0xffffffffu, p5, o);
    }
    if (lane == 0) {
        float a0 = p0 + b_aff[0], a1 = p1 + b_aff[1], a2 = p2 + b_aff[2];
        float a3 = p3 + b_aff[3], a4 = p4 + b_aff[4], a5 = p5 + b_aff[5];
        float x0 = g_xyz[m * 3], x1 = g_xyz[m * 3 + 1], x2 = g_xyz[m * 3 + 2];
        g_xyz[m * 3 + 0] = a3 + (1.f + a0) * x0;
        g_xyz[m * 3 + 1] = a4 + (1.f + a1) * x1;
        g_xyz[m * 3 + 2] = a5 + (1.f + a2) * x2;
    }
}

// ------------------------- decoder layer 0 -------------------------
__global__ __launch_bounds__(256) void dec0(const float* __restrict__ b0)
{
    __shared__ float sw[256 * 3];
    __shared__ float sb[256];
    for (int i = threadIdx.x; i < 768; i += 256) sw[i] = g_w0[i];
    sb[threadIdx.x] = b0[threadIdx.x];
    __syncthreads();
    size_t idx = (size_t)blockIdx.x * 256 + threadIdx.x;
    int m = (int)(idx >> 8), i = (int)(idx & 255);
    float x0 = g_xyz[m * 3], x1 = g_xyz[m * 3 + 1], x2 = g_xyz[m * 3 + 2];
    float v = sw[i * 3] * x0 + sw[i * 3 + 1] * x1 + sw[i * 3 + 2] * x2 + sb[i];
    g_act0[idx] = rndf(fmaxf(v, 0.f));
}

// ------------------------- final dot -------------------------
__global__ __launch_bounds__(256) void dec5(const float* __restrict__ W5,
                                            const float* __restrict__ b5,
                                            const float* __restrict__ x,
                                            float* __restrict__ out)
{
    __shared__ float sw[256];
    sw[threadIdx.x] = W5[threadIdx.x];
    __syncthreads();
    int warp = threadIdx.x >> 5, lane = threadIdx.x & 31;
    int m = blockIdx.x * 8 + warp;
    const float* xr = x + (size_t)m * 256;
    float s = 0.f;
    for (int k = lane; k < 256; k += 32) s += xr[k] * sw[k];
#pragma unroll
    for (int o = 16; o; o >>= 1) s += __shfl_xor_sync(0xffffffffu, s, o);
    if (lane == 0) out[m] = s + b5[0];
}

// ------------------------- host launcher -------------------------
extern "C" void kernel_launch(void* const* d_in, const int* in_sizes, int n_in,
                              void* d_out, int out_size)
{
    const float* input = (const float*)d_in[0];
    const float* W_ih  = (const float*)d_in[1];
    const float* b_ih  = (const float*)d_in[2];
    const float* W_hh  = (const float*)d_in[3];
    const float* b_hh  = (const float*)d_in[4];
    const float* W_aff = (const float*)d_in[5];
    const float* b_aff = (const float*)d_in[6];
    const float *v[5], *gg[5], *bb[5];
    for (int l = 0; l < 5; l++) {
        v[l]  = (const float*)d_in[7 + 3 * l];
        gg[l] = (const float*)d_in[8 + 3 * l];
        bb[l] = (const float*)d_in[9 + 3 * l];
    }
    const float* W5 = (const float*)d_in[22];
    const float* b5 = (const float*)d_in[23];

    float *Gc, *h0, *h1, *cst, *xyz, *codep, *wihp, *whhp, *a0p, *a1p, *w0p, *wmp;
    cudaGetSymbolAddress((void**)&Gc,    g_Gc);
    cudaGetSymbolAddress((void**)&h0,    g_h);
    cudaGetSymbolAddress((void**)&h1,    g_h2);
    cudaGetSymbolAddress((void**)&cst,   g_c);
    cudaGetSymbolAddress((void**)&xyz,   g_xyz);
    cudaGetSymbolAddress((void**)&codep, g_code);
    cudaGetSymbolAddress((void**)&wihp,  g_wih);
    cudaGetSymbolAddress((void**)&whhp,  g_whh);
    cudaGetSymbolAddress((void**)&a0p,   g_act0);
    cudaGetSymbolAddress((void**)&a1p,   g_act1);
    cudaGetSymbolAddress((void**)&w0p,   g_w0);
    cudaGetSymbolAddress((void**)&wmp,   g_wm);

    const int SMEM = (2 * BM + 2 * BN) * PAD * 4;   // 61440 B
    cudaFuncSetAttribute(gemm3<0>, cudaFuncAttributeMaxDynamicSharedMemorySize, SMEM);
    cudaFuncSetAttribute(gemm3<1>, cudaFuncAttributeMaxDynamicSharedMemorySize, SMEM);
    cudaFuncSetAttribute(gemm3<2>, cudaFuncAttributeMaxDynamicSharedMemorySize, SMEM);

    // prep (launches 1-4)
    extract_code<<<NSAMP, 256>>>(input);
    pack_wih<<<NGATE, 256>>>(W_ih);
    round_whh<<<NGATE * HID / 256, 256>>>(W_hh);
    wnorm<<<256, 128>>>(v[0], gg[0], w0p, 3);

    // launch 5: Gc GEMM (profiled)
    gemm3<0><<<dim3(NGATE / BN, NSAMP / BM), 256, SMEM>>>(
        codep, 256, wihp, 256, Gc, NGATE, 256 / BK,
        b_ih, b_hh, nullptr, nullptr, nullptr, nullptr, nullptr);

    // step 0 (h=c=0)
    step0<<<(NSAMP * HID) / 256, 256>>>(W_ih);
    affine_xyz<<<NSAMP / 8, 256>>>(h0, W_aff, b_aff);

    // steps 1..7: fused GEMM + LSTM cell, h ping-pong
    float* hb[2] = { h0, h1 };
    for (int s = 1; s < 8; s++) {
        const float* hin = hb[(s - 1) & 1];
        float* hnew = hb[s & 1];
        gemm3<1><<<dim3(HID / 64, NSAMP / BM), 256, SMEM>>>(
            hin, HID, whhp, HID, nullptr, 0, HID / BK,
            nullptr, nullptr, W_ih, xyz, Gc, cst, hnew);
        affine_xyz<<<NSAMP / 8, 256>>>(hnew, W_aff, b_aff);
    }

    // decoder weights
    for (int l = 1; l < 5; l++)
        wnorm<<<256, 128>>>(v[l], gg[l], wmp + (size_t)(l - 1) * 256 * 256, 256);

    // decoder
    dec0<<<NSAMP, 256>>>(bb[0]);
    const float* bufin = a0p;
    float* bufout = a1p;
    for (int l = 1; l < 5; l++) {
        gemm3<2><<<dim3(1, NSAMP / BM), 256, SMEM>>>(
            bufin, 256, wmp + (size_t)(l - 1) * 256 * 256, 256,
            bufout, 256, 256 / BK,
            bb[l], nullptr, nullptr, nullptr, nullptr, nullptr, nullptr);
        const float* tmp = bufout; bufout = (float*)bufin; bufin = tmp;
    }
    dec5<<<NSAMP / 8, 256>>>(W5, b5, bufin, (float*)d_out);
}

// round 4
// speedup vs baseline: 1.3301x; 1.0085x over previous
#include <cuda_runtime.h>
#include <math.h>
#include <stdint.h>

#define NSAMP 65536
#define HID   512
#define NGATE 2048
#define DIN   259
#define BM 128
#define BN 256
#define BK 16
#define PAD 20            // smem row stride in floats

// ------------------------- scratch -------------------------
__device__ float g_Gc  [(size_t)NSAMP * NGATE];   // 512 MB
__device__ float g_h   [(size_t)NSAMP * HID];
__device__ float g_h2  [(size_t)NSAMP * HID];
__device__ float g_c   [(size_t)NSAMP * HID];
__device__ float g_xyz [NSAMP * 3];
__device__ float g_code[(size_t)NSAMP * 256];     // tf32-rounded code
__device__ float g_wih [(size_t)NGATE * 256];     // tf32-rounded, packed
__device__ float g_whh [(size_t)NGATE * HID];     // tf32-rounded
__device__ float g_act0[(size_t)NSAMP * 256];
__device__ float g_act1[(size_t)NSAMP * 256];
__device__ float g_w0  [256 * 3];
__device__ float g_wm  [4 * 256 * 256];

__device__ __forceinline__ unsigned f2tf32(float x) {
    unsigned u; asm("cvt.rna.tf32.f32 %0, %1;" : "=r"(u) : "f"(x)); return u;
}
__device__ __forceinline__ float rndf(float x) { return __uint_as_float(f2tf32(x)); }
__device__ __forceinline__ void mma8(float* d, const unsigned* a, unsigned b0, unsigned b1) {
    asm volatile(
        "mma.sync.aligned.m16n8k8.row.col.f32.tf32.tf32.f32 "
        "{%0,%1,%2,%3}, {%4,%5,%6,%7}, {%8,%9}, {%0,%1,%2,%3};"
        : "+f"(d[0]), "+f"(d[1]), "+f"(d[2]), "+f"(d[3])
        : "r"(a[0]), "r"(a[1]), "r"(a[2]), "r"(a[3]), "r"(b0), "r"(b1));
}
__device__ __forceinline__ float sigm(float x) { return 1.f / (1.f + __expf(-x)); }
__device__ __forceinline__ void cp16(uint32_t d, const void* s) {
    asm volatile("cp.async.cg.shared.global [%0], [%1], 16;" :: "r"(d), "l"(s) : "memory");
}

// =====================================================================
// TF32 GEMM, cp.async double-buffered, 8 warps = 2(m) x 4(n), 64x64 each.
// MODE 0: C = acc + bias[n] + bias2[n]
// MODE 1: fused LSTM step (gathered gate columns, xyz rank-3 + Gc + cell
//         update in epilogue; writes c and tf32-rounded h)
// MODE 2: C = round(relu(acc + bias[n]))
// =====================================================================
template<int MODE>
__global__ void __launch_bounds__(256) gemm3(
    const float* __restrict__ A, int lda,
    const float* __restrict__ B, int ldb,
    float* __restrict__ C, int ldc, int kIters,
    const float* __restrict__ bias, const float* __restrict__ bias2,
    const float* __restrict__ Wih, const float* __restrict__ xyz,
    const float* __restrict__ Gc,
    float* __restrict__ cst, float* __restrict__ hout)
{
    extern __shared__ float smem[];
    float* AsF = smem;                   // [2][BM][PAD]
    float* BsF = smem + 2 * BM * PAD;    // [2][BN][PAD]

    const int tid = threadIdx.x, lane = tid & 31, wid = tid >> 5;
    const int wm = wid >> 2, wn = wid & 3;
    const int g = lane >> 2, t = lane & 3;
    const int m0 = blockIdx.y * BM;
    const int n0 = blockIdx.x * BN;
    const int j0 = blockIdx.x * 64;      // MODE1 hidden-unit tile

    // --- load-role indices ---
    const int ar = tid >> 1;                       // A row (0..127)
    const int ac = (tid & 1) * 8;                  // A col start (0 or 8)
    int brow;                                      // B global row for smem row = tid
    if (MODE == 1) {
        int w = tid >> 6, cw = tid & 63;
        int gate = cw >> 4, jl = (cw & 15) + (w << 4);
        brow = gate * HID + j0 + jl;
    } else brow = n0 + tid;

    const float* aptr = A + (size_t)(m0 + ar) * lda + ac;
    const float* bptr = B + (size_t)brow * ldb;

    const uint32_t asbase = (uint32_t)__cvta_generic_to_shared(AsF);
    const uint32_t bsbase = (uint32_t)__cvta_generic_to_shared(BsF);

    float acc[4][8][4];
#pragma unroll
    for (int i = 0; i < 4; i++)
#pragma unroll
        for (int j = 0; j < 8; j++)
#pragma unroll
            for (int k = 0; k < 4; k++) acc[i][j][k] = 0.f;

#define LOADTILE(IT, BUF)                                                     \
    do {                                                                      \
        const float* sa = aptr + (IT) * BK;                                   \
        uint32_t da = asbase + (((BUF) * BM + ar) * PAD + ac) * 4;            \
        cp16(da, sa); cp16(da + 16, sa + 4);                                  \
        const float* sb = bptr + (IT) * BK;                                   \
        uint32_t db = bsbase + (((BUF) * BN + tid) * PAD) * 4;                \
        cp16(db, sb); cp16(db + 16, sb + 4);                                  \
        cp16(db + 32, sb + 8); cp16(db + 48, sb + 12);                        \
    } while (0)

    LOADTILE(0, 0);
    asm volatile("cp.async.commit_group;" ::: "memory");

    for (int it = 0; it < kIters; ++it) {
        asm volatile("cp.async.wait_group 0;" ::: "memory");
        __syncthreads();
        if (it + 1 < kIters) {
            LOADTILE(it + 1, (it + 1) & 1);
            asm volatile("cp.async.commit_group;" ::: "memory");
        }
        const int buf = it & 1;
        const unsigned* as = (const unsigned*)(AsF + buf * BM * PAD);
        const unsigned* bs = (const unsigned*)(BsF + buf * BN * PAD);
#pragma unroll
        for (int kk = 0; kk < BK; kk += 8) {
            unsigned af[4][4];
#pragma unroll
            for (int mt = 0; mt < 4; mt++) {
                int r = wm * 64 + mt * 16 + g;
                af[mt][0] = as[r * PAD + kk + t];
                af[mt][1] = as[(r + 8) * PAD + kk + t];
                af[mt][2] = as[r * PAD + kk + t + 4];
                af[mt][3] = as[(r + 8) * PAD + kk + t + 4];
            }
#pragma unroll
            for (int nt = 0; nt < 8; nt++) {
                int cn = wn * 64 + nt * 8 + g;
                unsigned b0 = bs[cn * PAD + kk + t];
                unsigned b1 = bs[cn * PAD + kk + t + 4];
#pragma unroll
                for (int mt = 0; mt < 4; mt++)
                    mma8(acc[mt][nt], af[mt], b0, b1);
            }
        }
    }
#undef LOADTILE

    // ----------------- epilogue -----------------
    if (MODE == 1) {
#pragma unroll
        for (int q = 0; q < 2; q++) {
            const int jc = j0 + wn * 16 + q * 8 + 2 * t;
            float wt[4][2][3];
#pragma unroll
            for (int gt = 0; gt < 4; gt++)
#pragma unroll
                for (int e = 0; e < 2; e++) {
                    const float* wr = Wih + (size_t)(gt * HID + jc + e) * DIN + 256;
                    wt[gt][e][0] = wr[0]; wt[gt][e][1] = wr[1]; wt[gt][e][2] = wr[2];
                }
#pragma unroll
            for (int mt = 0; mt < 4; mt++)
#pragma unroll
                for (int rr = 0; rr < 2; rr++) {
                    int r = m0 + wm * 64 + mt * 16 + g + rr * 8;
                    float x0 = xyz[r * 3], x1 = xyz[r * 3 + 1], x2 = xyz[r * 3 + 2];
                    const float* gcr = Gc + (size_t)r * NGATE + jc;
                    float2 co = *(const float2*)(cst + (size_t)r * HID + jc);
                    float2 cn, hn;
#pragma unroll
                    for (int e = 0; e < 2; e++) {
                        int a = rr * 2 + e;
                        float iv = acc[mt][0 + q][a] + gcr[e]
                                 + x0 * wt[0][e][0] + x1 * wt[0][e][1] + x2 * wt[0][e][2];
                        float fv = acc[mt][2 + q][a] + gcr[HID + e]
                                 + x0 * wt[1][e][0] + x1 * wt[1][e][1] + x2 * wt[1][e][2];
                        float gv = acc[mt][4 + q][a] + gcr[2 * HID + e]
                                 + x0 * wt[2][e][0] + x1 * wt[2][e][1] + x2 * wt[2][e][2];
                        float ov = acc[mt][6 + q][a] + gcr[3 * HID + e]
                                 + x0 * wt[3][e][0] + x1 * wt[3][e][1] + x2 * wt[3][e][2];
                        float cold = e ? co.y : co.x;
                        float c2 = sigm(fv) * cold + sigm(iv) * tanhf(gv);
                        float h2 = rndf(sigm(ov) * tanhf(c2));
                        if (e) { cn.y = c2; hn.y = h2; } else { cn.x = c2; hn.x = h2; }
                    }
                    *(float2*)(cst  + (size_t)r * HID + jc) = cn;
                    *(float2*)(hout + (size_t)r * HID + jc) = hn;
                }
        }
    } else {
#pragma unroll
        for (int mt = 0; mt < 4; mt++)
#pragma unroll
            for (int nt = 0; nt < 8; nt++) {
                int c = n0 + wn * 64 + nt * 8 + 2 * t;
                float b0v = bias[c], b1v = bias[c + 1];
                if (MODE == 0) { b0v += bias2[c]; b1v += bias2[c + 1]; }
#pragma unroll
                for (int rr = 0; rr < 2; rr++) {
                    int r = m0 + wm * 64 + mt * 16 + g + rr * 8;
                    float v0 = acc[mt][nt][rr * 2 + 0] + b0v;
                    float v1 = acc[mt][nt][rr * 2 + 1] + b1v;
                    if (MODE == 2) {
                        v0 = rndf(fmaxf(v0, 0.f));
                        v1 = rndf(fmaxf(v1, 0.f));
                    }
                    *(float2*)(C + (size_t)r * ldc + c) = make_float2(v0, v1);
                }
            }
    }
}

// ------------------------- prep kernels -------------------------
__global__ void extract_code(const float* __restrict__ input)
{
    int m = blockIdx.x, k = threadIdx.x;
    g_code[(size_t)m * 256 + k] = rndf(input[(size_t)m * DIN + k]);
    if (k < 3) g_xyz[m * 3 + k] = input[(size_t)m * DIN + 256 + k];
}
__global__ void pack_wih(const float* __restrict__ W)
{
    int r = blockIdx.x, k = threadIdx.x;
    g_wih[(size_t)r * 256 + k] = rndf(W[(size_t)r * DIN + k]);
}
__global__ void round_whh(const float* __restrict__ W)
{
    size_t i = (size_t)blockIdx.x * 256 + threadIdx.x;
    g_whh[i] = rndf(W[i]);
}

// ------------------------- weight norm (tf32-rounded output) --------
__global__ void wnorm(const float* __restrict__ v, const float* __restrict__ gsc,
                      float* __restrict__ w, int din)
{
    int row = blockIdx.x;
    const float* vr = v + (size_t)row * din;
    float s = 0.f;
    for (int k = threadIdx.x; k < din; k += blockDim.x) { float x = vr[k]; s += x * x; }
    __shared__ float red[4];
#pragma unroll
    for (int o = 16; o; o >>= 1) s += __shfl_xor_sync(0xffffffffu, s, o);
    if ((threadIdx.x & 31) == 0) red[threadIdx.x >> 5] = s;
    __syncthreads();
    float tot = red[0] + red[1] + red[2] + red[3];
    float scale = gsc[row] / sqrtf(tot);
    for (int k = threadIdx.x; k < din; k += blockDim.x)
        w[(size_t)row * din + k] = rndf(vr[k] * scale);
}

// ------------------------- step 0 -------------------------
__global__ __launch_bounds__(256) void step0(const float* __restrict__ Wih)
{
    size_t idx = (size_t)blockIdx.x * 256 + threadIdx.x;
    int m = (int)(idx >> 9), j = (int)(idx & 511);
    float x0 = g_xyz[m * 3], x1 = g_xyz[m * 3 + 1], x2 = g_xyz[m * 3 + 2];
    float gv[4];
#pragma unroll
    for (int gate = 0; gate < 4; gate++) {
        int row = gate * HID + j;
        const float* wr = Wih + (size_t)row * DIN + 256;
        gv[gate] = g_Gc[(size_t)m * NGATE + row] + x0 * wr[0] + x1 * wr[1] + x2 * wr[2];
    }
    float c = sigm(gv[0]) * tanhf(gv[2]);
    float h = sigm(gv[3]) * tanhf(c);
    g_c[idx] = c;
    g_h[idx] = rndf(h);
}

// ------------------------- affine + xyz update -------------------------
__global__ __launch_bounds__(256) void affine_xyz(const float* __restrict__ h_in,
                                                  const float* __restrict__ W_aff,
                                                  const float* __restrict__ b_aff)
{
    __shared__ float sW[6 * HID];
    for (int i = threadIdx.x; i < 6 * HID; i += 256) sW[i] = W_aff[i];
    __syncthreads();
    int warp = threadIdx.x >> 5, lane = threadIdx.x & 31;
    int m = blockIdx.x * 8 + warp;
    const float* h = h_in + (size_t)m * HID;
    float p0 = 0, p1 = 0, p2 = 0, p3 = 0, p4 = 0, p5 = 0;
    for (int k = lane; k < HID; k += 32) {
        float hv = h[k];
        p0 += sW[k] * hv;           p1 += sW[HID + k] * hv;
        p2 += sW[2 * HID + k] * hv; p3 += sW[3 * HID + k] * hv;
        p4 += sW[4 * HID + k] * hv; p5 += sW[5 * HID + k] * hv;
    }
#pragma unroll
    for (int o = 16; o; o >>= 1) {
        p0 += __shfl_xor_sync(0xffffffffu, p0, o);
        p1 += __shfl_xor_sync(0xffffffffu, p1, o);
        p2 += __shfl_xor_sync(0xffffffffu, p2, o);
        p3 += __shfl_xor_sync(0xffffffffu, p3, o);
        p4 += __shfl_xor_sync(0xffffffffu, p4, o);
        p5 += __shfl_xor_sync(0xffffffffu, p5, o);
    }
    if (lane == 0) {
        float a0 = p0 + b_aff[0], a1 = p1 + b_aff[1], a2 = p2 + b_aff[2];
        float a3 = p3 + b_aff[3], a4 = p4 + b_aff[4], a5 = p5 + b_aff[5];
        float x0 = g_xyz[m * 3], x1 = g_xyz[m * 3 + 1], x2 = g_xyz[m * 3 + 2];
        g_xyz[m * 3 + 0] = a3 + (1.f + a0) * x0;
        g_xyz[m * 3 + 1] = a4 + (1.f + a1) * x1;
        g_xyz[m * 3 + 2] = a5 + (1.f + a2) * x2;
    }
}

// ------------------------- decoder layer 0 -------------------------
__global__ __launch_bounds__(256) void dec0(const float* __restrict__ b0)
{
    __shared__ float sw[256 * 3];
    __shared__ float sb[256];
    for (int i = threadIdx.x; i < 768; i += 256) sw[i] = g_w0[i];
    sb[threadIdx.x] = b0[threadIdx.x];
    __syncthreads();
    size_t idx = (size_t)blockIdx.x * 256 + threadIdx.x;
    int m = (int)(idx >> 8), i = (int)(idx & 255);
    float x0 = g_xyz[m * 3], x1 = g_xyz[m * 3 + 1], x2 = g_xyz[m * 3 + 2];
    float v = sw[i * 3] * x0 + sw[i * 3 + 1] * x1 + sw[i * 3 + 2] * x2 + sb[i];
    g_act0[idx] = rndf(fmaxf(v, 0.f));
}

// ------------------------- final dot -------------------------
__global__ __launch_bounds__(256) void dec5(const float* __restrict__ W5,
                                            const float* __restrict__ b5,
                                            const float* __restrict__ x,
                                            float* __restrict__ out)
{
    __shared__ float sw[256];
    sw[threadIdx.x] = W5[threadIdx.x];
    __syncthreads();
    int warp = threadIdx.x >> 5, lane = threadIdx.x & 31;
    int m = blockIdx.x * 8 + warp;
    const float* xr = x + (size_t)m * 256;
    float s = 0.f;
    for (int k = lane; k < 256; k += 32) s += xr[k] * sw[k];
#pragma unroll
    for (int o = 16; o; o >>= 1) s += __shfl_xor_sync(0xffffffffu, s, o);
    if (lane == 0) out[m] = s + b5[0];
}

// ------------------------- host launcher -------------------------
extern "C" void kernel_launch(void* const* d_in, const int* in_sizes, int n_in,
                              void* d_out, int out_size)
{
    const float* input = (const float*)d_in[0];
    const float* W_ih  = (const float*)d_in[1];
    const float* b_ih  = (const float*)d_in[2];
    const float* W_hh  = (const float*)d_in[3];
    const float* b_hh  = (const float*)d_in[4];
    const float* W_aff = (const float*)d_in[5];
    const float* b_aff = (const float*)d_in[6];
    const float *v[5], *gg[5], *bb[5];
    for (int l = 0; l < 5; l++) {
        v[l]  = (const float*)d_in[7 + 3 * l];
        gg[l] = (const float*)d_in[8 + 3 * l];
        bb[l] = (const float*)d_in[9 + 3 * l];
    }
    const float* W5 = (const float*)d_in[22];
    const float* b5 = (const float*)d_in[23];

    float *Gc, *h0, *h1, *cst, *xyz, *codep, *wihp, *whhp, *a0p, *a1p, *w0p, *wmp;
    cudaGetSymbolAddress((void**)&Gc,    g_Gc);
    cudaGetSymbolAddress((void**)&h0,    g_h);
    cudaGetSymbolAddress((void**)&h1,    g_h2);
    cudaGetSymbolAddress((void**)&cst,   g_c);
    cudaGetSymbolAddress((void**)&xyz,   g_xyz);
    cudaGetSymbolAddress((void**)&codep, g_code);
    cudaGetSymbolAddress((void**)&wihp,  g_wih);
    cudaGetSymbolAddress((void**)&whhp,  g_whh);
    cudaGetSymbolAddress((void**)&a0p,   g_act0);
    cudaGetSymbolAddress((void**)&a1p,   g_act1);
    cudaGetSymbolAddress((void**)&w0p,   g_w0);
    cudaGetSymbolAddress((void**)&wmp,   g_wm);

    const int SMEM = (2 * BM + 2 * BN) * PAD * 4;   // 61440 B
    cudaFuncSetAttribute(gemm3<0>, cudaFuncAttributeMaxDynamicSharedMemorySize, SMEM);
    cudaFuncSetAttribute(gemm3<1>, cudaFuncAttributeMaxDynamicSharedMemorySize, SMEM);
    cudaFuncSetAttribute(gemm3<2>, cudaFuncAttributeMaxDynamicSharedMemorySize, SMEM);

    // prep (launches 1-4)
    extract_code<<<NSAMP, 256>>>(input);
    pack_wih<<<NGATE, 256>>>(W_ih);
    round_whh<<<NGATE * HID / 256, 256>>>(W_hh);
    wnorm<<<256, 128>>>(v[0], gg[0], w0p, 3);

    // launch 5: Gc GEMM (profiled)
    gemm3<0><<<dim3(NGATE / BN, NSAMP / BM), 256, SMEM>>>(
        codep, 256, wihp, 256, Gc, NGATE, 256 / BK,
        b_ih, b_hh, nullptr, nullptr, nullptr, nullptr, nullptr);

    // step 0 (h=c=0)
    step0<<<(NSAMP * HID) / 256, 256>>>(W_ih);
    affine_xyz<<<NSAMP / 8, 256>>>(h0, W_aff, b_aff);

    // steps 1..7: fused GEMM + LSTM cell, h ping-pong
    float* hb[2] = { h0, h1 };
    for (int s = 1; s < 8; s++) {
        const float* hin = hb[(s - 1) & 1];
        float* hnew = hb[s & 1];
        gemm3<1><<<dim3(HID / 64, NSAMP / BM), 256, SMEM>>>(
            hin, HID, whhp, HID, nullptr, 0, HID / BK,
            nullptr, nullptr, W_ih, xyz, Gc, cst, hnew);
        affine_xyz<<<NSAMP / 8, 256>>>(hnew, W_aff, b_aff);
    }

    // decoder weights
    for (int l = 1; l < 5; l++)
        wnorm<<<256, 128>>>(v[l], gg[l], wmp + (size_t)(l - 1) * 256 * 256, 256);

    // decoder
    dec0<<<NSAMP, 256>>>(bb[0]);
    const float* bufin = a0p;
    float* bufout = a1p;
    for (int l = 1; l < 5; l++) {
        gemm3<2><<<dim3(1, NSAMP / BM), 256, SMEM>>>(
            bufin, 256, wmp + (size_t)(l - 1) * 256 * 256, 256,
            bufout, 256, 256 / BK,
            bb[l], nullptr, nullptr, nullptr, nullptr, nullptr, nullptr);
        const float* tmp = bufout; bufout = (float*)bufin; bufin = tmp;
    }
    dec5<<<NSAMP / 8, 256>>>(W5, b5, bufin, (float*)d_out);
}

// round 6
// speedup vs baseline: 1.9169x; 1.4411x over previous
#include <cuda_runtime.h>
#include <cuda_fp16.h>
#include <math.h>
#include <stdint.h>

#define NSAMP 65536
#define HID   512
#define NGATE 2048
#define DIN   259
#define BM 128
#define BN 256
#define BK 16
#define RS 12      // smem row stride in 32-bit words (8 data + 4 pad)

// ------------------------- scratch -------------------------
__device__ float  g_Gc  [(size_t)NSAMP * NGATE];   // 512 MB fp32
__device__ __half g_h   [(size_t)NSAMP * HID];
__device__ __half g_h2  [(size_t)NSAMP * HID];
__device__ float  g_c   [(size_t)NSAMP * HID];
__device__ float  g_xyz [NSAMP * 3];
__device__ __half g_code[(size_t)NSAMP * 256];
__device__ __half g_wih [(size_t)NGATE * 256];
__device__ __half g_whh [(size_t)NGATE * HID];
__device__ __half g_act0[(size_t)NSAMP * 256];
__device__ __half g_act1[(size_t)NSAMP * 256];
__device__ float  g_w0  [256 * 3];
__device__ __half g_wm  [4 * 256 * 256];

__device__ __forceinline__ float sigm(float x) { return 1.f / (1.f + __expf(-x)); }
__device__ __forceinline__ void cp16(uint32_t d, const void* s) {
    asm volatile("cp.async.cg.shared.global [%0], [%1], 16;" :: "r"(d), "l"(s) : "memory");
}
__device__ __forceinline__ void mma16(float* d, const unsigned* a, unsigned b0, unsigned b1) {
    asm volatile(
        "mma.sync.aligned.m16n8k16.row.col.f32.f16.f16.f32 "
        "{%0,%1,%2,%3}, {%4,%5,%6,%7}, {%8,%9}, {%0,%1,%2,%3};"
        : "+f"(d[0]), "+f"(d[1]), "+f"(d[2]), "+f"(d[3])
        : "r"(a[0]), "r"(a[1]), "r"(a[2]), "r"(a[3]), "r"(b0), "r"(b1));
}

// =====================================================================
// FP16 GEMM (fp32 accum), cp.async double-buffered, 8 warps = 2(m) x 4(n),
// 64x64 warp tiles.
// MODE 0: Cf = acc + bias[n] + bias2[n]            (Gc build, fp32 out)
// MODE 1: fused LSTM step (gathered gate cols; epilogue: +Gc +xyz·Wx,
//         cell update; writes c fp32, h fp16)
// MODE 2: Ch = half(relu(acc + bias[n]))           (decoder)
// =====================================================================
template<int MODE>
__global__ void __launch_bounds__(256) gemm_h(
    const __half* __restrict__ A, int lda,
    const __half* __restrict__ B, int ldb,
    float* __restrict__ Cf, __half* __restrict__ Ch, int ldc, int kIters,
    const float* __restrict__ bias, const float* __restrict__ bias2,
    const float* __restrict__ Wih, const float* __restrict__ xyz,
    const float* __restrict__ Gc,
    float* __restrict__ cst, __half* __restrict__ hout)
{
    extern __shared__ uint32_t smw[];
    uint32_t* AsW = smw;                    // [2][BM][RS]
    uint32_t* BsW = smw + 2 * BM * RS;      // [2][BN][RS]

    const int tid = threadIdx.x, lane = tid & 31, wid = tid >> 5;
    const int wm = wid >> 2, wn = wid & 3;
    const int g = lane >> 2, t = lane & 3;
    const int m0 = blockIdx.y * BM;
    const int n0 = blockIdx.x * BN;
    const int j0 = blockIdx.x * 64;

    // load roles
    const int ar = tid >> 1, seg = tid & 1;
    int brow;
    if (MODE == 1) {
        int w = tid >> 6, cw = tid & 63;
        brow = (cw >> 4) * HID + j0 + (cw & 15) + (w << 4);
    } else brow = n0 + tid;

    const __half* aptr = A + (size_t)(m0 + ar) * lda + seg * 8;
    const __half* bptr = B + (size_t)brow * ldb;

    const uint32_t asb = (uint32_t)__cvta_generic_to_shared(AsW);
    const uint32_t bsb = (uint32_t)__cvta_generic_to_shared(BsW);

    float acc[4][8][4];
#pragma unroll
    for (int i = 0; i < 4; i++)
#pragma unroll
        for (int j = 0; j < 8; j++)
#pragma unroll
            for (int k = 0; k < 4; k++) acc[i][j][k] = 0.f;

#define LOADTILE(IT, BUF)                                                     \
    do {                                                                      \
        uint32_t da = asb + (((BUF) * BM + ar) * RS + seg * 4) * 4;           \
        cp16(da, aptr + (IT) * BK);                                           \
        uint32_t db = bsb + (((BUF) * BN + tid) * RS) * 4;                    \
        const __half* sb = bptr + (IT) * BK;                                  \
        cp16(db, sb); cp16(db + 16, sb + 8);                                  \
    } while (0)

    LOADTILE(0, 0);
    asm volatile("cp.async.commit_group;" ::: "memory");

    for (int it = 0; it < kIters; ++it) {
        asm volatile("cp.async.wait_group 0;" ::: "memory");
        __syncthreads();
        if (it + 1 < kIters) {
            LOADTILE(it + 1, (it + 1) & 1);
            asm volatile("cp.async.commit_group;" ::: "memory");
        }
        const int buf = it & 1;
        const uint32_t* as = AsW + buf * BM * RS;
        const uint32_t* bs = BsW + buf * BN * RS;
        unsigned af[4][4];
#pragma unroll
        for (int mt = 0; mt < 4; mt++) {
            int r = wm * 64 + mt * 16 + g;
            af[mt][0] = as[r * RS + t];
            af[mt][1] = as[(r + 8) * RS + t];
            af[mt][2] = as[r * RS + t + 4];
            af[mt][3] = as[(r + 8) * RS + t + 4];
        }
#pragma unroll
        for (int nt = 0; nt < 8; nt++) {
            int cn = wn * 64 + nt * 8 + g;
            unsigned b0 = bs[cn * RS + t];
            unsigned b1 = bs[cn * RS + t + 4];
#pragma unroll
            for (int mt = 0; mt < 4; mt++)
                mma16(acc[mt][nt], af[mt], b0, b1);
        }
    }
#undef LOADTILE

    // ----------------- epilogue -----------------
    if (MODE == 1) {
#pragma unroll
        for (int q = 0; q < 2; q++) {
            const int jc = j0 + wn * 16 + q * 8 + 2 * t;
            float wt[4][2][3];
#pragma unroll
            for (int gt = 0; gt < 4; gt++)
#pragma unroll
                for (int e = 0; e < 2; e++) {
                    const float* wr = Wih + (size_t)(gt * HID + jc + e) * DIN + 256;
                    wt[gt][e][0] = wr[0]; wt[gt][e][1] = wr[1]; wt[gt][e][2] = wr[2];
                }
#pragma unroll
            for (int mt = 0; mt < 4; mt++)
#pragma unroll
                for (int rr = 0; rr < 2; rr++) {
                    int r = m0 + wm * 64 + mt * 16 + g + rr * 8;
                    float x0 = xyz[r * 3], x1 = xyz[r * 3 + 1], x2 = xyz[r * 3 + 2];
                    const float* gcr = Gc + (size_t)r * NGATE + jc;
                    float2 co = *(const float2*)(cst + (size_t)r * HID + jc);
                    float2 cn; __half2 hn;
#pragma unroll
                    for (int e = 0; e < 2; e++) {
                        int a = rr * 2 + e;
                        float iv = acc[mt][0 + q][a] + gcr[e]
                                 + x0 * wt[0][e][0] + x1 * wt[0][e][1] + x2 * wt[0][e][2];
                        float fv = acc[mt][2 + q][a] + gcr[HID + e]
                                 + x0 * wt[1][e][0] + x1 * wt[1][e][1] + x2 * wt[1][e][2];
                        float gv = acc[mt][4 + q][a] + gcr[2 * HID + e]
                                 + x0 * wt[2][e][0] + x1 * wt[2][e][1] + x2 * wt[2][e][2];
                        float ov = acc[mt][6 + q][a] + gcr[3 * HID + e]
                                 + x0 * wt[3][e][0] + x1 * wt[3][e][1] + x2 * wt[3][e][2];
                        float cold = e ? co.y : co.x;
                        float c2 = sigm(fv) * cold + sigm(iv) * tanhf(gv);
                        __half h2 = __float2half_rn(sigm(ov) * tanhf(c2));
                        if (e) { cn.y = c2; hn.y = h2; } else { cn.x = c2; hn.x = h2; }
                    }
                    *(float2*)(cst + (size_t)r * HID + jc) = cn;
                    *(__half2*)(hout + (size_t)r * HID + jc) = hn;
                }
        }
    } else {
#pragma unroll
        for (int mt = 0; mt < 4; mt++)
#pragma unroll
            for (int nt = 0; nt < 8; nt++) {
                int c = n0 + wn * 64 + nt * 8 + 2 * t;
                float b0v = bias[c], b1v = bias[c + 1];
                if (MODE == 0) { b0v += bias2[c]; b1v += bias2[c + 1]; }
#pragma unroll
                for (int rr = 0; rr < 2; rr++) {
                    int r = m0 + wm * 64 + mt * 16 + g + rr * 8;
                    float v0 = acc[mt][nt][rr * 2 + 0] + b0v;
                    float v1 = acc[mt][nt][rr * 2 + 1] + b1v;
                    if (MODE == 0) {
                        *(float2*)(Cf + (size_t)r * ldc + c) = make_float2(v0, v1);
                    } else {
                        __half2 o;
                        o.x = __float2half_rn(fmaxf(v0, 0.f));
                        o.y = __float2half_rn(fmaxf(v1, 0.f));
                        *(__half2*)(Ch + (size_t)r * ldc + c) = o;
                    }
                }
            }
    }
}

// ------------------------- prep kernels -------------------------
__global__ void extract_code(const float* __restrict__ input)
{
    int m = blockIdx.x, k = threadIdx.x;
    g_code[(size_t)m * 256 + k] = __float2half_rn(input[(size_t)m * DIN + k]);
    if (k < 3) g_xyz[m * 3 + k] = input[(size_t)m * DIN + 256 + k];
}
__global__ void pack_wih(const float* __restrict__ W)
{
    int r = blockIdx.x, k = threadIdx.x;
    g_wih[(size_t)r * 256 + k] = __float2half_rn(W[(size_t)r * DIN + k]);
}
__global__ void round_whh(const float* __restrict__ W)
{
    size_t i = (size_t)blockIdx.x * 256 + threadIdx.x;
    g_whh[i] = __float2half_rn(W[i]);
}
__global__ void wnorm_f(const float* __restrict__ v, const float* __restrict__ gsc,
                        float* __restrict__ w, int din)
{
    int row = blockIdx.x;
    const float* vr = v + (size_t)row * din;
    float s = 0.f;
    for (int k = threadIdx.x; k < din; k += blockDim.x) { float x = vr[k]; s += x * x; }
    __shared__ float red[4];
#pragma unroll
    for (int o = 16; o; o >>= 1) s += __shfl_xor_sync(0xffffffffu, s, o);
    if ((threadIdx.x & 31) == 0) red[threadIdx.x >> 5] = s;
    __syncthreads();
    float scale = gsc[row] / sqrtf(red[0] + red[1] + red[2] + red[3]);
    for (int k = threadIdx.x; k < din; k += blockDim.x)
        w[(size_t)row * din + k] = vr[k] * scale;
}
__global__ void wnorm_h(const float* __restrict__ v, const float* __restrict__ gsc,
                        __half* __restrict__ w, int din)
{
    int row = blockIdx.x;
    const float* vr = v + (size_t)row * din;
    float s = 0.f;
    for (int k = threadIdx.x; k < din; k += blockDim.x) { float x = vr[k]; s += x * x; }
    __shared__ float red[4];
#pragma unroll
    for (int o = 16; o; o >>= 1) s += __shfl_xor_sync(0xffffffffu, s, o);
    if ((threadIdx.x & 31) == 0) red[threadIdx.x >> 5] = s;
    __syncthreads();
    float scale = gsc[row] / sqrtf(red[0] + red[1] + red[2] + red[3]);
    for (int k = threadIdx.x; k < din; k += blockDim.x)
        w[(size_t)row * din + k] = __float2half_rn(vr[k] * scale);
}

// ------------------------- step 0 -------------------------
__global__ __launch_bounds__(256) void step0(const float* __restrict__ Wih)
{
    size_t idx = (size_t)blockIdx.x * 256 + threadIdx.x;
    int m = (int)(idx >> 9), j = (int)(idx & 511);
    float x0 = g_xyz[m * 3], x1 = g_xyz[m * 3 + 1], x2 = g_xyz[m * 3 + 2];
    float gv[4];
#pragma unroll
    for (int gate = 0; gate < 4; gate++) {
        int row = gate * HID + j;
        const float* wr = Wih + (size_t)row * DIN + 256;
        gv[gate] = g_Gc[(size_t)m * NGATE + row] + x0 * wr[0] + x1 * wr[1] + x2 * wr[2];
    }
    float c = sigm(gv[0]) * tanhf(gv[2]);
    float h = sigm(gv[3]) * tanhf(c);
    g_c[idx] = c;
    g_h[idx] = __float2half_rn(h);
}

// ------------------------- affine + xyz update -------------------------
__global__ __launch_bounds__(256) void affine_xyz(const __half* __restrict__ h_in,
                                                  const float* __restrict__ W_aff,
                                                  const float* __restrict__ b_aff)
{
    __shared__ float sW[6 * HID];
    for (int i = threadIdx.x; i < 6 * HID; i += 256) sW[i] = W_aff[i];
    __syncthreads();
    int warp = threadIdx.x >> 5, lane = threadIdx.x & 31;
    int m = blockIdx.x * 8 + warp;
    const __half* h = h_in + (size_t)m * HID;
    float p0 = 0, p1 = 0, p2 = 0, p3 = 0, p4 = 0, p5 = 0;
    for (int k = lane; k < HID; k += 32) {
        float hv = __half2float(h[k]);
        p0 += sW[k] * hv;           p1 += sW[HID + k] * hv;
        p2 += sW[2 * HID + k] * hv; p3 += sW[3 * HID + k] * hv;
        p4 += sW[4 * HID + k] * hv; p5 += sW[5 * HID + k] * hv;
    }
#pragma unroll
    for (int o = 16; o; o >>= 1) {
        p0 += __shfl_xor_sync(0xffffffffu, p0, o);
        p1 += __shfl_xor_sync(0xffffffffu, p1, o);
        p2 += __shfl_xor_sync(0xffffffffu, p2, o);
        p3 += __shfl_xor_sync(0xffffffffu, p3, o);
        p4 += __shfl_xor_sync(0xffffffffu, p4, o);
        p5 += __shfl_xor_sync(0xffffffffu, p5, o);
    }
    if (lane == 0) {
        float a0 = p0 + b_aff[0], a1 = p1 + b_aff[1], a2 = p2 + b_aff[2];
        float a3 = p3 + b_aff[3], a4 = p4 + b_aff[4], a5 = p5 + b_aff[5];
        float x0 = g_xyz[m * 3], x1 = g_xyz[m * 3 + 1], x2 = g_xyz[m * 3 + 2];
        g_xyz[m * 3 + 0] = a3 + (1.f + a0) * x0;
        g_xyz[m * 3 + 1] = a4 + (1.f + a1) * x1;
        g_xyz[m * 3 + 2] = a5 + (1.f + a2) * x2;
    }
}

// ------------------------- decoder layer 0 -------------------------
__global__ __launch_bounds__(256) void dec0(const float* __restrict__ b0)
{
    __shared__ float sw[768];
    __shared__ float sb[256];
    for (int i = threadIdx.x; i < 768; i += 256) sw[i] = g_w0[i];
    sb[threadIdx.x] = b0[threadIdx.x];
    __syncthreads();
    size_t idx = (size_t)blockIdx.x * 256 + threadIdx.x;
    int m = (int)(idx >> 8), i = (int)(idx & 255);
    float v = sw[i * 3] * g_xyz[m * 3] + sw[i * 3 + 1] * g_xyz[m * 3 + 1]
            + sw[i * 3 + 2] * g_xyz[m * 3 + 2] + sb[i];
    g_act0[idx] = __float2half_rn(fmaxf(v, 0.f));
}

// ------------------------- final dot -------------------------
__global__ __launch_bounds__(256) void dec5(const float* __restrict__ W5,
                                            const float* __restrict__ b5,
                                            const __half* __restrict__ x,
                                            float* __restrict__ out)
{
    __shared__ float sw[256];
    sw[threadIdx.x] = W5[threadIdx.x];
    __syncthreads();
    int warp = threadIdx.x >> 5, lane = threadIdx.x & 31;
    int m = blockIdx.x * 8 + warp;
    const __half* xr = x + (size_t)m * 256;
    float s = 0.f;
    for (int k = lane; k < 256; k += 32) s += __half2float(xr[k]) * sw[k];
#pragma unroll
    for (int o = 16; o; o >>= 1) s += __shfl_xor_sync(0xffffffffu, s, o);
    if (lane == 0) out[m] = s + b5[0];
}

// ------------------------- host launcher -------------------------
extern "C" void kernel_launch(void* const* d_in, const int* in_sizes, int n_in,
                              void* d_out, int out_size)
{
    const float* input = (const float*)d_in[0];
    const float* W_ih  = (const float*)d_in[1];
    const float* b_ih  = (const float*)d_in[2];
    const float* W_hh  = (const float*)d_in[3];
    const float* b_hh  = (const float*)d_in[4];
    const float* W_aff = (const float*)d_in[5];
    const float* b_aff = (const float*)d_in[6];
    const float *v[5], *gg[5], *bb[5];
    for (int l = 0; l < 5; l++) {
        v[l]  = (const float*)d_in[7 + 3 * l];
        gg[l] = (const float*)d_in[8 + 3 * l];
        bb[l] = (const float*)d_in[9 + 3 * l];
    }
    const float* W5 = (const float*)d_in[22];
    const float* b5 = (const float*)d_in[23];

    float *Gc, *cst, *xyz, *w0p;
    __half *h0, *h1, *codep, *wihp, *whhp, *a0p, *a1p, *wmp;
    cudaGetSymbolAddress((void**)&Gc,    g_Gc);
    cudaGetSymbolAddress((void**)&h0,    g_h);
    cudaGetSymbolAddress((void**)&h1,    g_h2);
    cudaGetSymbolAddress((void**)&cst,   g_c);
    cudaGetSymbolAddress((void**)&xyz,   g_xyz);
    cudaGetSymbolAddress((void**)&codep, g_code);
    cudaGetSymbolAddress((void**)&wihp,  g_wih);
    cudaGetSymbolAddress((void**)&whhp,  g_whh);
    cudaGetSymbolAddress((void**)&a0p,   g_act0);
    cudaGetSymbolAddress((void**)&a1p,   g_act1);
    cudaGetSymbolAddress((void**)&w0p,   g_w0);
    cudaGetSymbolAddress((void**)&wmp,   g_wm);

    const int SMEM = 2 * (BM + BN) * RS * 4;   // 36864 B
    cudaFuncSetAttribute(gemm_h<0>, cudaFuncAttributeMaxDynamicSharedMemorySize, SMEM);
    cudaFuncSetAttribute(gemm_h<1>, cudaFuncAttributeMaxDynamicSharedMemorySize, SMEM);
    cudaFuncSetAttribute(gemm_h<2>, cudaFuncAttributeMaxDynamicSharedMemorySize, SMEM);

    // prep (launches 1-4)
    extract_code<<<NSAMP, 256>>>(input);
    pack_wih<<<NGATE, 256>>>(W_ih);
    round_whh<<<NGATE * HID / 256, 256>>>(W_hh);
    wnorm_f<<<256, 128>>>(v[0], gg[0], w0p, 3);

    // launch 5 (profiled): Gc = code @ W_ih[:, :256]^T + b_ih + b_hh
    gemm_h<0><<<dim3(NGATE / BN, NSAMP / BM), 256, SMEM>>>(
        codep, 256, wihp, 256, Gc, nullptr, NGATE, 256 / BK,
        b_ih, b_hh, nullptr, nullptr, nullptr, nullptr, nullptr);

    // step 0 (h=c=0)
    step0<<<(NSAMP * HID) / 256, 256>>>(W_ih);
    affine_xyz<<<NSAMP / 8, 256>>>(h0, W_aff, b_aff);

    // steps 1..7: fused GEMM + LSTM cell, h ping-pong
    __half* hb[2] = { h0, h1 };
    for (int s = 1; s < 8; s++) {
        const __half* hin = hb[(s - 1) & 1];
        __half* hnew = hb[s & 1];
        gemm_h<1><<<dim3(HID / 64, NSAMP / BM), 256, SMEM>>>(
            hin, HID, whhp, HID, nullptr, nullptr, 0, HID / BK,
            nullptr, nullptr, W_ih, xyz, Gc, cst, hnew);
        affine_xyz<<<NSAMP / 8, 256>>>(hnew, W_aff, b_aff);
    }

    // decoder weights
    for (int l = 1; l < 5; l++)
        wnorm_h<<<256, 128>>>(v[l], gg[l], wmp + (size_t)(l - 1) * 256 * 256, 256);

    // decoder
    dec0<<<NSAMP, 256>>>(bb[0]);
    const __half* bufin = a0p;
    __half* bufout = a1p;
    for (int l = 1; l < 5; l++) {
        gemm_h<2><<<dim3(1, NSAMP / BM), 256, SMEM>>>(
            bufin, 256, wmp + (size_t)(l - 1) * 256 * 256, 256,
            nullptr, bufout, 256, 256 / BK,
            bb[l], nullptr, nullptr, nullptr, nullptr, nullptr, nullptr);
        const __half* tmp = bufout; bufout = (__half*)bufin; bufin = tmp;
    }
    dec5<<<NSAMP / 8, 256>>>(W5, b5, bufin, (float*)d_out);
}

// round 7
// speedup vs baseline: 1.9682x; 1.0268x over previous
#include <cuda_runtime.h>
#include <cuda_fp16.h>
#include <math.h>
#include <stdint.h>

#define NSAMP 65536
#define HID   512
#define NGATE 2048
#define DIN   259
#define BM 128
#define BN 256
#define BK 16
#define RS 12      // smem row stride in 32-bit words (8 data + 4 pad)

// ------------------------- scratch -------------------------
__device__ float  g_Gc  [(size_t)NSAMP * NGATE];
__device__ __half g_h   [(size_t)NSAMP * HID];
__device__ __half g_h2  [(size_t)NSAMP * HID];
__device__ float  g_c   [(size_t)NSAMP * HID];
__device__ float  g_xyz [NSAMP * 3];
__device__ __half g_code[(size_t)NSAMP * 256];
__device__ __half g_wih [(size_t)NGATE * 256];
__device__ __half g_whh [(size_t)NGATE * HID];
__device__ __half g_act0[(size_t)NSAMP * 256];
__device__ __half g_act1[(size_t)NSAMP * 256];
__device__ float  g_w0  [256 * 3];
__device__ __half g_wm  [4 * 256 * 256];

__device__ __forceinline__ float sigm(float x) { return 1.f / (1.f + __expf(-x)); }
__device__ __forceinline__ void cp16(uint32_t d, const void* s) {
    asm volatile("cp.async.cg.shared.global [%0], [%1], 16;" :: "r"(d), "l"(s) : "memory");
}
__device__ __forceinline__ void mma16(float* d, const unsigned* a, unsigned b0, unsigned b1) {
    asm volatile(
        "mma.sync.aligned.m16n8k16.row.col.f32.f16.f16.f32 "
        "{%0,%1,%2,%3}, {%4,%5,%6,%7}, {%8,%9}, {%0,%1,%2,%3};"
        : "+f"(d[0]), "+f"(d[1]), "+f"(d[2]), "+f"(d[3])
        : "r"(a[0]), "r"(a[1]), "r"(a[2]), "r"(a[3]), "r"(b0), "r"(b1));
}
#define LDSM4(R, ADDR)                                                         \
    asm volatile("ldmatrix.sync.aligned.m8n8.x4.shared.b16 {%0,%1,%2,%3}, [%4];" \
        : "=r"((R)[0]), "=r"((R)[1]), "=r"((R)[2]), "=r"((R)[3]) : "r"(ADDR))

// =====================================================================
// FP16 GEMM (fp32 accum), cp.async double-buffered, ldmatrix fragments,
// 8 warps = 2(m) x 4(n), 64x64 warp tiles.
// MODE 0: Gc build + step-0 cell init (gathered gate cols; epilogue stores
//         Gc = acc + b_ih + b_hh, then c = sig(i)*tanh(g), h = sig(o)*tanh(c)
//         with gates = Gc + xyz0·Wx)
// MODE 1: LSTM step s>=1 (gathered gate cols; epilogue: +Gc +xyz·Wx, cell
//         update; writes c fp32, h fp16)
// MODE 2: Ch = half(relu(acc + bias[n]))   (decoder)
// =====================================================================
template<int MODE>
__global__ void __launch_bounds__(256) gemm_h(
    const __half* __restrict__ A, int lda,
    const __half* __restrict__ B, int ldb,
    float* __restrict__ Cf, __half* __restrict__ Ch, int ldc, int kIters,
    const float* __restrict__ bias, const float* __restrict__ bias2,
    const float* __restrict__ Wih, const float* __restrict__ xyz,
    const float* __restrict__ Gc,
    float* __restrict__ cst, __half* __restrict__ hout)
{
    extern __shared__ uint32_t smw[];
    uint32_t* AsW = smw;                    // [2][BM][RS]
    uint32_t* BsW = smw + 2 * BM * RS;      // [2][BN][RS]

    const int tid = threadIdx.x, lane = tid & 31, wid = tid >> 5;
    const int wm = wid >> 2, wn = wid & 3;
    const int g = lane >> 2, t = lane & 3;
    const int m0 = blockIdx.y * BM;
    const int n0 = blockIdx.x * BN;
    const int j0 = blockIdx.x * 64;

    const int ar = tid >> 1, seg = tid & 1;
    int brow;
    if (MODE == 0 || MODE == 1) {
        int w = tid >> 6, cw = tid & 63;
        brow = (cw >> 4) * HID + j0 + (cw & 15) + (w << 4);
    } else brow = n0 + tid;

    const __half* aptr = A + (size_t)(m0 + ar) * lda + seg * 8;
    const __half* bptr = B + (size_t)brow * ldb;

    const uint32_t asb = (uint32_t)__cvta_generic_to_shared(AsW);
    const uint32_t bsb = (uint32_t)__cvta_generic_to_shared(BsW);

    float acc[4][8][4];
#pragma unroll
    for (int i = 0; i < 4; i++)
#pragma unroll
        for (int j = 0; j < 8; j++)
#pragma unroll
            for (int k = 0; k < 4; k++) acc[i][j][k] = 0.f;

#define LOADTILE(IT, BUF)                                                     \
    do {                                                                      \
        uint32_t da = asb + (((BUF) * BM + ar) * RS + seg * 4) * 4;           \
        cp16(da, aptr + (IT) * BK);                                           \
        uint32_t db = bsb + (((BUF) * BN + tid) * RS) * 4;                    \
        const __half* sb = bptr + (IT) * BK;                                  \
        cp16(db, sb); cp16(db + 16, sb + 8);                                  \
    } while (0)

    LOADTILE(0, 0);
    asm volatile("cp.async.commit_group;" ::: "memory");

    const int l8 = lane & 7, lh8 = ((lane >> 3) & 1) * 8, lw4 = (lane >> 4) * 4;

    for (int it = 0; it < kIters; ++it) {
        asm volatile("cp.async.wait_group 0;" ::: "memory");
        __syncthreads();
        if (it + 1 < kIters) {
            LOADTILE(it + 1, (it + 1) & 1);
            asm volatile("cp.async.commit_group;" ::: "memory");
        }
        const int buf = it & 1;
        const uint32_t asbuf = asb + buf * BM * RS * 4;
        const uint32_t bsbuf = bsb + buf * BN * RS * 4;
        unsigned af[4][4];
#pragma unroll
        for (int mt = 0; mt < 4; mt++)
            LDSM4(af[mt], asbuf + (uint32_t)(((wm * 64 + mt * 16 + l8 + lh8) * RS + lw4) * 4));
#pragma unroll
        for (int p = 0; p < 4; p++) {
            unsigned bb[4];
            LDSM4(bb, bsbuf + (uint32_t)(((wn * 64 + p * 16 + l8 + lh8) * RS + lw4) * 4));
#pragma unroll
            for (int mt = 0; mt < 4; mt++) {
                mma16(acc[mt][2 * p],     af[mt], bb[0], bb[2]);
                mma16(acc[mt][2 * p + 1], af[mt], bb[1], bb[3]);
            }
        }
    }
#undef LOADTILE

    // ----------------- epilogue -----------------
    if (MODE == 0 || MODE == 1) {
#pragma unroll
        for (int q = 0; q < 2; q++) {
            const int jc = j0 + wn * 16 + q * 8 + 2 * t;
            float wt[4][2][3];
            float bi[4][2];
#pragma unroll
            for (int gt = 0; gt < 4; gt++)
#pragma unroll
                for (int e = 0; e < 2; e++) {
                    const float* wr = Wih + (size_t)(gt * HID + jc + e) * DIN + 256;
                    wt[gt][e][0] = wr[0]; wt[gt][e][1] = wr[1]; wt[gt][e][2] = wr[2];
                    if (MODE == 0)
                        bi[gt][e] = bias[gt * HID + jc + e] + bias2[gt * HID + jc + e];
                }
#pragma unroll
            for (int mt = 0; mt < 4; mt++)
#pragma unroll
                for (int rr = 0; rr < 2; rr++) {
                    int r = m0 + wm * 64 + mt * 16 + g + rr * 8;
                    float x0 = xyz[r * 3], x1 = xyz[r * 3 + 1], x2 = xyz[r * 3 + 2];
                    float2 cn; __half2 hn;
                    if (MODE == 0) {
                        float* gco = Cf + (size_t)r * NGATE + jc;
                        float2 gcs[4];
#pragma unroll
                        for (int e = 0; e < 2; e++) {
                            int a = rr * 2 + e;
                            float gcv[4], gate[4];
#pragma unroll
                            for (int gt = 0; gt < 4; gt++) {
                                gcv[gt] = acc[mt][2 * gt + q][a] + bi[gt][e];
                                gate[gt] = gcv[gt] + x0 * wt[gt][e][0]
                                         + x1 * wt[gt][e][1] + x2 * wt[gt][e][2];
                            }
                            float c2 = sigm(gate[0]) * tanhf(gate[2]);
                            __half h2 = __float2half_rn(sigm(gate[3]) * tanhf(c2));
                            if (e) {
                                cn.y = c2; hn.y = h2;
                                gcs[0].y = gcv[0]; gcs[1].y = gcv[1];
                                gcs[2].y = gcv[2]; gcs[3].y = gcv[3];
                            } else {
                                cn.x = c2; hn.x = h2;
                                gcs[0].x = gcv[0]; gcs[1].x = gcv[1];
                                gcs[2].x = gcv[2]; gcs[3].x = gcv[3];
                            }
                        }
#pragma unroll
                        for (int gt = 0; gt < 4; gt++)
                            *(float2*)(gco + gt * HID) = gcs[gt];
                    } else {
                        const float* gcr = Gc + (size_t)r * NGATE + jc;
                        float2 co = *(const float2*)(cst + (size_t)r * HID + jc);
#pragma unroll
                        for (int e = 0; e < 2; e++) {
                            int a = rr * 2 + e;
                            float iv = acc[mt][0 + q][a] + gcr[e]
                                     + x0 * wt[0][e][0] + x1 * wt[0][e][1] + x2 * wt[0][e][2];
                            float fv = acc[mt][2 + q][a] + gcr[HID + e]
                                     + x0 * wt[1][e][0] + x1 * wt[1][e][1] + x2 * wt[1][e][2];
                            float gv = acc[mt][4 + q][a] + gcr[2 * HID + e]
                                     + x0 * wt[2][e][0] + x1 * wt[2][e][1] + x2 * wt[2][e][2];
                            float ov = acc[mt][6 + q][a] + gcr[3 * HID + e]
                                     + x0 * wt[3][e][0] + x1 * wt[3][e][1] + x2 * wt[3][e][2];
                            float cold = e ? co.y : co.x;
                            float c2 = sigm(fv) * cold + sigm(iv) * tanhf(gv);
                            __half h2 = __float2half_rn(sigm(ov) * tanhf(c2));
                            if (e) { cn.y = c2; hn.y = h2; } else { cn.x = c2; hn.x = h2; }
                        }
                    }
                    *(float2*)(cst + (size_t)r * HID + jc) = cn;
                    *(__half2*)(hout + (size_t)r * HID + jc) = hn;
                }
        }
    } else {
#pragma unroll
        for (int mt = 0; mt < 4; mt++)
#pragma unroll
            for (int nt = 0; nt < 8; nt++) {
                int c = n0 + wn * 64 + nt * 8 + 2 * t;
                float b0v = bias[c], b1v = bias[c + 1];
#pragma unroll
                for (int rr = 0; rr < 2; rr++) {
                    int r = m0 + wm * 64 + mt * 16 + g + rr * 8;
                    __half2 o;
                    o.x = __float2half_rn(fmaxf(acc[mt][nt][rr * 2 + 0] + b0v, 0.f));
                    o.y = __float2half_rn(fmaxf(acc[mt][nt][rr * 2 + 1] + b1v, 0.f));
                    *(__half2*)(Ch + (size_t)r * ldc + c) = o;
                }
            }
    }
}

// ------------------------- prep kernels -------------------------
__global__ void extract_code(const float* __restrict__ input)
{
    int m = blockIdx.x, k = threadIdx.x;
    g_code[(size_t)m * 256 + k] = __float2half_rn(input[(size_t)m * DIN + k]);
    if (k < 3) g_xyz[m * 3 + k] = input[(size_t)m * DIN + 256 + k];
}
__global__ void prep_weights(const float* __restrict__ W_ih, const float* __restrict__ W_hh)
{
    int r = blockIdx.x, t = threadIdx.x;
    g_wih[(size_t)r * 256 + t] = __float2half_rn(W_ih[(size_t)r * DIN + t]);
    g_whh[(size_t)r * HID + t]       = __float2half_rn(W_hh[(size_t)r * HID + t]);
    g_whh[(size_t)r * HID + 256 + t] = __float2half_rn(W_hh[(size_t)r * HID + 256 + t]);
}
struct WnArgs { const float* v[5]; const float* g[5]; };
__global__ void wnorm_all(WnArgs wa)
{
    int layer = blockIdx.x >> 8, row = blockIdx.x & 255;
    int din = (layer == 0) ? 3 : 256;
    const float* vr = wa.v[layer] + (size_t)row * din;
    float s = 0.f;
    for (int k = threadIdx.x; k < din; k += blockDim.x) { float x = vr[k]; s += x * x; }
    __shared__ float red[4];
#pragma unroll
    for (int o = 16; o; o >>= 1) s += __shfl_xor_sync(0xffffffffu, s, o);
    if ((threadIdx.x & 31) == 0) red[threadIdx.x >> 5] = s;
    __syncthreads();
    float scale = wa.g[layer][row] / sqrtf(red[0] + red[1] + red[2] + red[3]);
    if (layer == 0) {
        for (int k = threadIdx.x; k < din; k += blockDim.x)
            g_w0[(size_t)row * din + k] = vr[k] * scale;
    } else {
        __half* w = g_wm + (size_t)(layer - 1) * 256 * 256 + (size_t)row * 256;
        for (int k = threadIdx.x; k < din; k += blockDim.x)
            w[k] = __float2half_rn(vr[k] * scale);
    }
}

// ------------------------- affine + xyz update -------------------------
__global__ __launch_bounds__(256) void affine_xyz(const __half* __restrict__ h_in,
                                                  const float* __restrict__ W_aff,
                                                  const float* __restrict__ b_aff)
{
    __shared__ float sW[6 * HID];
    for (int i = threadIdx.x; i < 6 * HID; i += 256) sW[i] = W_aff[i];
    __syncthreads();
    int warp = threadIdx.x >> 5, lane = threadIdx.x & 31;
    int m = blockIdx.x * 8 + warp;
    const __half* h = h_in + (size_t)m * HID;
    float p0 = 0, p1 = 0, p2 = 0, p3 = 0, p4 = 0, p5 = 0;
    for (int k = lane; k < HID; k += 32) {
        float hv = __half2float(h[k]);
        p0 += sW[k] * hv;           p1 += sW[HID + k] * hv;
        p2 += sW[2 * HID + k] * hv; p3 += sW[3 * HID + k] * hv;
        p4 += sW[4 * HID + k] * hv; p5 += sW[5 * HID + k] * hv;
    }
#pragma unroll
    for (int o = 16; o; o >>= 1) {
        p0 += __shfl_xor_sync(0xffffffffu, p0, o);
        p1 += __shfl_xor_sync(0xffffffffu, p1, o);
        p2 += __shfl_xor_sync(0xffffffffu, p2, o);
        p3 += __shfl_xor_sync(0xffffffffu, p3, o);
        p4 += __shfl_xor_sync(0xffffffffu, p4, o);
        p5 += __shfl_xor_sync(0xffffffffu, p5, o);
    }
    if (lane == 0) {
        float a0 = p0 + b_aff[0], a1 = p1 + b_aff[1], a2 = p2 + b_aff[2];
        float a3 = p3 + b_aff[3], a4 = p4 + b_aff[4], a5 = p5 + b_aff[5];
        float x0 = g_xyz[m * 3], x1 = g_xyz[m * 3 + 1], x2 = g_xyz[m * 3 + 2];
        g_xyz[m * 3 + 0] = a3 + (1.f + a0) * x0;
        g_xyz[m * 3 + 1] = a4 + (1.f + a1) * x1;
        g_xyz[m * 3 + 2] = a5 + (1.f + a2) * x2;
    }
}

// ------------------------- decoder layer 0 -------------------------
__global__ __launch_bounds__(256) void dec0(const float* __restrict__ b0)
{
    __shared__ float sw[768];
    __shared__ float sb[256];
    for (int i = threadIdx.x; i < 768; i += 256) sw[i] = g_w0[i];
    sb[threadIdx.x] = b0[threadIdx.x];
    __syncthreads();
    size_t idx = (size_t)blockIdx.x * 256 + threadIdx.x;
    int m = (int)(idx >> 8), i = (int)(idx & 255);
    float v = sw[i * 3] * g_xyz[m * 3] + sw[i * 3 + 1] * g_xyz[m * 3 + 1]
            + sw[i * 3 + 2] * g_xyz[m * 3 + 2] + sb[i];
    g_act0[idx] = __float2half_rn(fmaxf(v, 0.f));
}

// ------------------------- final dot -------------------------
__global__ __launch_bounds__(256) void dec5(const float* __restrict__ W5,
                                            const float* __restrict__ b5,
                                            const __half* __restrict__ x,
                                            float* __restrict__ out)
{
    __shared__ float sw[256];
    sw[threadIdx.x] = W5[threadIdx.x];
    __syncthreads();
    int warp = threadIdx.x >> 5, lane = threadIdx.x & 31;
    int m = blockIdx.x * 8 + warp;
    const __half* xr = x + (size_t)m * 256;
    float s = 0.f;
    for (int k = lane; k < 256; k += 32) s += __half2float(xr[k]) * sw[k];
#pragma unroll
    for (int o = 16; o; o >>= 1) s += __shfl_xor_sync(0xffffffffu, s, o);
    if (lane == 0) out[m] = s + b5[0];
}

// ------------------------- host launcher -------------------------
extern "C" void kernel_launch(void* const* d_in, const int* in_sizes, int n_in,
                              void* d_out, int out_size)
{
    const float* input = (const float*)d_in[0];
    const float* W_ih  = (const float*)d_in[1];
    const float* b_ih  = (const float*)d_in[2];
    const float* W_hh  = (const float*)d_in[3];
    const float* b_hh  = (const float*)d_in[4];
    const float* W_aff = (const float*)d_in[5];
    const float* b_aff = (const float*)d_in[6];
    WnArgs wa;
    const float* bb[5];
    for (int l = 0; l < 5; l++) {
        wa.v[l] = (const float*)d_in[7 + 3 * l];
        wa.g[l] = (const float*)d_in[8 + 3 * l];
        bb[l]   = (const float*)d_in[9 + 3 * l];
    }
    const float* W5 = (const float*)d_in[22];
    const float* b5 = (const float*)d_in[23];

    float *Gc, *cst, *xyz;
    __half *h0, *h1, *codep, *wihp, *whhp, *a0p, *a1p, *wmp;
    cudaGetSymbolAddress((void**)&Gc,    g_Gc);
    cudaGetSymbolAddress((void**)&h0,    g_h);
    cudaGetSymbolAddress((void**)&h1,    g_h2);
    cudaGetSymbolAddress((void**)&cst,   g_c);
    cudaGetSymbolAddress((void**)&xyz,   g_xyz);
    cudaGetSymbolAddress((void**)&codep, g_code);
    cudaGetSymbolAddress((void**)&wihp,  g_wih);
    cudaGetSymbolAddress((void**)&whhp,  g_whh);
    cudaGetSymbolAddress((void**)&a0p,   g_act0);
    cudaGetSymbolAddress((void**)&a1p,   g_act1);
    cudaGetSymbolAddress((void**)&wmp,   g_wm);

    const int SMEM = 2 * (BM + BN) * RS * 4;   // 36864 B
    cudaFuncSetAttribute(gemm_h<0>, cudaFuncAttributeMaxDynamicSharedMemorySize, SMEM);
    cudaFuncSetAttribute(gemm_h<1>, cudaFuncAttributeMaxDynamicSharedMemorySize, SMEM);
    cudaFuncSetAttribute(gemm_h<2>, cudaFuncAttributeMaxDynamicSharedMemorySize, SMEM);

    // launches 0-2: prep
    extract_code<<<NSAMP, 256>>>(input);
    prep_weights<<<NGATE, 256>>>(W_ih, W_hh);
    wnorm_all<<<1280, 128>>>(wa);

    // launch 3 (profiled): fused Gc GEMM + step-0 cell init
    gemm_h<0><<<dim3(NGATE / BN, NSAMP / BM), 256, SMEM>>>(
        codep, 256, wihp, 256, Gc, nullptr, 0, 256 / BK,
        b_ih, b_hh, W_ih, xyz, nullptr, cst, h0);

    affine_xyz<<<NSAMP / 8, 256>>>(h0, W_aff, b_aff);

    // steps 1..7: fused GEMM + LSTM cell, h ping-pong
    __half* hb[2] = { h0, h1 };
    for (int s = 1; s < 8; s++) {
        const __half* hin = hb[(s - 1) & 1];
        __half* hnew = hb[s & 1];
        gemm_h<1><<<dim3(HID / 64, NSAMP / BM), 256, SMEM>>>(
            hin, HID, whhp, HID, nullptr, nullptr, 0, HID / BK,
            nullptr, nullptr, W_ih, xyz, Gc, cst, hnew);
        affine_xyz<<<NSAMP / 8, 256>>>(hnew, W_aff, b_aff);
    }

    // decoder
    dec0<<<NSAMP, 256>>>(bb[0]);
    const __half* bufin = a0p;
    __half* bufout = a1p;
    for (int l = 1; l < 5; l++) {
        gemm_h<2><<<dim3(1, NSAMP / BM), 256, SMEM>>>(
            bufin, 256, wmp + (size_t)(l - 1) * 256 * 256, 256,
            nullptr, bufout, 256, 256 / BK,
            bb[l], nullptr, nullptr, nullptr, nullptr, nullptr, nullptr);
        const __half* tmp = bufout; bufout = (__half*)bufin; bufin = tmp;
    }
    dec5<<<NSAMP / 8, 256>>>(W5, b5, bufin, (float*)d_out);
}

// round 8
// speedup vs baseline: 2.7833x; 1.4141x over previous
#include <cuda_runtime.h>
#include <cuda_fp16.h>
#include <math.h>
#include <stdint.h>

#define NSAMP 65536
#define HID   512
#define NGATE 2048
#define DIN   259
#define BM 128
#define BN 256
#define BK 32
#define RS 20              // smem row stride in words (16 data + 4 pad)
#define ABUF (BM * RS * 4) // bytes per A buffer
#define BBUF (BN * RS * 4)

// ------------------------- scratch -------------------------
__device__ float  g_Gc  [(size_t)NSAMP * NGATE];
__device__ __half g_h   [(size_t)NSAMP * HID];
__device__ __half g_h2  [(size_t)NSAMP * HID];
__device__ float  g_c   [(size_t)NSAMP * HID];
__device__ float  g_xyz [NSAMP * 3];
__device__ __half g_code[(size_t)NSAMP * 256];
__device__ __half g_wih [(size_t)NGATE * 256];
__device__ __half g_whh [(size_t)NGATE * HID];
__device__ __half g_act0[(size_t)NSAMP * 256];
__device__ __half g_act1[(size_t)NSAMP * 256];
__device__ float  g_w0  [256 * 3];
__device__ __half g_wm  [4 * 256 * 256];

__device__ __forceinline__ float sigm(float x) { return 1.f / (1.f + __expf(-x)); }
__device__ __forceinline__ void cp16(uint32_t d, const void* s) {
    asm volatile("cp.async.cg.shared.global [%0], [%1], 16;" :: "r"(d), "l"(s) : "memory");
}
__device__ __forceinline__ void mma16(float* d, const unsigned* a, unsigned b0, unsigned b1) {
    asm volatile(
        "mma.sync.aligned.m16n8k16.row.col.f32.f16.f16.f32 "
        "{%0,%1,%2,%3}, {%4,%5,%6,%7}, {%8,%9}, {%0,%1,%2,%3};"
        : "+f"(d[0]), "+f"(d[1]), "+f"(d[2]), "+f"(d[3])
        : "r"(a[0]), "r"(a[1]), "r"(a[2]), "r"(a[3]), "r"(b0), "r"(b1));
}
#define LDSM4(R, ADDR)                                                         \
    asm volatile("ldmatrix.sync.aligned.m8n8.x4.shared.b16 {%0,%1,%2,%3}, [%4];" \
        : "=r"((R)[0]), "=r"((R)[1]), "=r"((R)[2]), "=r"((R)[3]) : "r"(ADDR))

// =====================================================================
// FP16 GEMM (fp32 accum), 512 threads = 16 warps (4m x 4n), warp tile
// 32x64, BK=32 double-buffered cp.async, ldmatrix fragments.
// MODE 0: Gc build + step-0 cell init    MODE 1: LSTM step s>=1
// MODE 2: decoder relu layer
// =====================================================================
template<int MODE>
__global__ void __launch_bounds__(512, 1) gemm_h(
    const __half* __restrict__ A, int lda,
    const __half* __restrict__ B, int ldb,
    float* __restrict__ Cf, __half* __restrict__ Ch, int ldc, int kIters,
    const float* __restrict__ bias, const float* __restrict__ bias2,
    const float* __restrict__ Wih, const float* __restrict__ xyz,
    const float* __restrict__ Gc,
    float* __restrict__ cst, __half* __restrict__ hout)
{
    extern __shared__ uint32_t smw[];
    const int tid = threadIdx.x, lane = tid & 31, wid = tid >> 5;
    const int wm = wid >> 2, wn = wid & 3;
    const int g = lane >> 2, t = lane & 3;
    const int m0 = blockIdx.y * BM;
    const int n0 = blockIdx.x * BN;
    const int j0 = blockIdx.x * 64;

    // ---- load roles ----
    const int arow = tid >> 2, aseg = tid & 3;          // A: 1 cp16/thread
    const int br = tid >> 1, bseg2 = (tid & 1) * 2;     // B: 2 cp16/thread
    int brow;
    if (MODE == 0 || MODE == 1) {
        int w = br >> 6, cw = br & 63;
        brow = (cw >> 4) * HID + j0 + (cw & 15) + (w << 4);
    } else brow = n0 + br;

    const __half* aptr = A + (size_t)(m0 + arow) * lda + aseg * 8;
    const __half* bptr = B + (size_t)brow * ldb + bseg2 * 8;

    const uint32_t asb = (uint32_t)__cvta_generic_to_shared(smw);
    const uint32_t bsb = asb + 2 * ABUF;
    const uint32_t aoff = asb + (arow * RS + aseg * 4) * 4;
    const uint32_t boff = bsb + (br * RS + bseg2 * 4) * 4;

    // ---- fragment addresses (loop-invariant) ----
    const int lr = lane & 15, lw = (lane >> 4) * 16;    // bytes within row
    uint32_t aadr[2], badr[4];
#pragma unroll
    for (int mt = 0; mt < 2; mt++)
        aadr[mt] = asb + (uint32_t)((wm * 32 + mt * 16 + lr) * RS * 4) + lw;
#pragma unroll
    for (int p = 0; p < 4; p++)
        badr[p] = bsb + (uint32_t)((wn * 64 + p * 16 + lr) * RS * 4) + lw;

    float acc[2][8][4];
#pragma unroll
    for (int i = 0; i < 2; i++)
#pragma unroll
        for (int j = 0; j < 8; j++)
#pragma unroll
            for (int k = 0; k < 4; k++) acc[i][j][k] = 0.f;

#define LOADTILE(IT, BUF)                                                     \
    do {                                                                      \
        cp16(aoff + (BUF) * ABUF, aptr + (IT) * BK);                          \
        cp16(boff + (BUF) * BBUF, bptr + (IT) * BK);                          \
        cp16(boff + (BUF) * BBUF + 16, bptr + (IT) * BK + 8);                 \
    } while (0)

    LOADTILE(0, 0);
    asm volatile("cp.async.commit_group;" ::: "memory");

    for (int it = 0; it < kIters; ++it) {
        asm volatile("cp.async.wait_group 0;" ::: "memory");
        __syncthreads();
        if (it + 1 < kIters) {
            LOADTILE(it + 1, (it + 1) & 1);
            asm volatile("cp.async.commit_group;" ::: "memory");
        }
        const uint32_t ao = (it & 1) * ABUF, bo = (it & 1) * BBUF;
#pragma unroll
        for (int ks = 0; ks < 2; ks++) {
            unsigned af[2][4];
            LDSM4(af[0], aadr[0] + ao + ks * 32);
            LDSM4(af[1], aadr[1] + ao + ks * 32);
#pragma unroll
            for (int p = 0; p < 4; p++) {
                unsigned bb[4];
                LDSM4(bb, badr[p] + bo + ks * 32);
                mma16(acc[0][2 * p],     af[0], bb[0], bb[2]);
                mma16(acc[0][2 * p + 1], af[0], bb[1], bb[3]);
                mma16(acc[1][2 * p],     af[1], bb[0], bb[2]);
                mma16(acc[1][2 * p + 1], af[1], bb[1], bb[3]);
            }
        }
    }
#undef LOADTILE

    // ----------------- epilogue -----------------
    if (MODE == 0 || MODE == 1) {
#pragma unroll
        for (int q = 0; q < 2; q++) {
            const int jc = j0 + wn * 16 + q * 8 + 2 * t;
            float wt[4][2][3];
            float bi[4][2];
#pragma unroll
            for (int gt = 0; gt < 4; gt++)
#pragma unroll
                for (int e = 0; e < 2; e++) {
                    const float* wr = Wih + (size_t)(gt * HID + jc + e) * DIN + 256;
                    wt[gt][e][0] = wr[0]; wt[gt][e][1] = wr[1]; wt[gt][e][2] = wr[2];
                    if (MODE == 0)
                        bi[gt][e] = bias[gt * HID + jc + e] + bias2[gt * HID + jc + e];
                }
#pragma unroll
            for (int mt = 0; mt < 2; mt++)
#pragma unroll
                for (int rr = 0; rr < 2; rr++) {
                    int r = m0 + wm * 32 + mt * 16 + g + rr * 8;
                    float x0 = xyz[r * 3], x1 = xyz[r * 3 + 1], x2 = xyz[r * 3 + 2];
                    float2 cn; __half2 hn;
                    if (MODE == 0) {
                        float* gco = Cf + (size_t)r * NGATE + jc;
                        float2 gcs[4];
#pragma unroll
                        for (int e = 0; e < 2; e++) {
                            int a = rr * 2 + e;
                            float gcv[4], gate[4];
#pragma unroll
                            for (int gt = 0; gt < 4; gt++) {
                                gcv[gt] = acc[mt][2 * gt + q][a] + bi[gt][e];
                                gate[gt] = gcv[gt] + x0 * wt[gt][e][0]
                                         + x1 * wt[gt][e][1] + x2 * wt[gt][e][2];
                            }
                            float c2 = sigm(gate[0]) * tanhf(gate[2]);
                            __half h2 = __float2half_rn(sigm(gate[3]) * tanhf(c2));
                            if (e) {
                                cn.y = c2; hn.y = h2;
                                gcs[0].y = gcv[0]; gcs[1].y = gcv[1];
                                gcs[2].y = gcv[2]; gcs[3].y = gcv[3];
                            } else {
                                cn.x = c2; hn.x = h2;
                                gcs[0].x = gcv[0]; gcs[1].x = gcv[1];
                                gcs[2].x = gcv[2]; gcs[3].x = gcv[3];
                            }
                        }
#pragma unroll
                        for (int gt = 0; gt < 4; gt++)
                            *(float2*)(gco + gt * HID) = gcs[gt];
                    } else {
                        const float* gcr = Gc + (size_t)r * NGATE + jc;
                        float2 co = *(const float2*)(cst + (size_t)r * HID + jc);
#pragma unroll
                        for (int e = 0; e < 2; e++) {
                            int a = rr * 2 + e;
                            float iv = acc[mt][0 + q][a] + gcr[e]
                                     + x0 * wt[0][e][0] + x1 * wt[0][e][1] + x2 * wt[0][e][2];
                            float fv = acc[mt][2 + q][a] + gcr[HID + e]
                                     + x0 * wt[1][e][0] + x1 * wt[1][e][1] + x2 * wt[1][e][2];
                            float gv = acc[mt][4 + q][a] + gcr[2 * HID + e]
                                     + x0 * wt[2][e][0] + x1 * wt[2][e][1] + x2 * wt[2][e][2];
                            float ov = acc[mt][6 + q][a] + gcr[3 * HID + e]
                                     + x0 * wt[3][e][0] + x1 * wt[3][e][1] + x2 * wt[3][e][2];
                            float cold = e ? co.y : co.x;
                            float c2 = sigm(fv) * cold + sigm(iv) * tanhf(gv);
                            __half h2 = __float2half_rn(sigm(ov) * tanhf(c2));
                            if (e) { cn.y = c2; hn.y = h2; } else { cn.x = c2; hn.x = h2; }
                        }
                    }
                    *(float2*)(cst + (size_t)r * HID + jc) = cn;
                    *(__half2*)(hout + (size_t)r * HID + jc) = hn;
                }
        }
    } else {
#pragma unroll
        for (int mt = 0; mt < 2; mt++)
#pragma unroll
            for (int nt = 0; nt < 8; nt++) {
                int c = n0 + wn * 64 + nt * 8 + 2 * t;
                float b0v = bias[c], b1v = bias[c + 1];
#pragma unroll
                for (int rr = 0; rr < 2; rr++) {
                    int r = m0 + wm * 32 + mt * 16 + g + rr * 8;
                    __half2 o;
                    o.x = __float2half_rn(fmaxf(acc[mt][nt][rr * 2 + 0] + b0v, 0.f));
                    o.y = __float2half_rn(fmaxf(acc[mt][nt][rr * 2 + 1] + b1v, 0.f));
                    *(__half2*)(Ch + (size_t)r * ldc + c) = o;
                }
            }
    }
}

// ------------------------- prep kernels -------------------------
__global__ void extract_code(const float* __restrict__ input)
{
    int m = blockIdx.x, k = threadIdx.x;
    g_code[(size_t)m * 256 + k] = __float2half_rn(input[(size_t)m * DIN + k]);
    if (k < 3) g_xyz[m * 3 + k] = input[(size_t)m * DIN + 256 + k];
}
__global__ void prep_weights(const float* __restrict__ W_ih, const float* __restrict__ W_hh)
{
    int r = blockIdx.x, t = threadIdx.x;
    g_wih[(size_t)r * 256 + t] = __float2half_rn(W_ih[(size_t)r * DIN + t]);
    g_whh[(size_t)r * HID + t]       = __float2half_rn(W_hh[(size_t)r * HID + t]);
    g_whh[(size_t)r * HID + 256 + t] = __float2half_rn(W_hh[(size_t)r * HID + 256 + t]);
}
struct WnArgs { const float* v[5]; const float* g[5]; };
__global__ void wnorm_all(WnArgs wa)
{
    int layer = blockIdx.x >> 8, row = blockIdx.x & 255;
    int din = (layer == 0) ? 3 : 256;
    const float* vr = wa.v[layer] + (size_t)row * din;
    float s = 0.f;
    for (int k = threadIdx.x; k < din; k += blockDim.x) { float x = vr[k]; s += x * x; }
    __shared__ float red[4];
#pragma unroll
    for (int o = 16; o; o >>= 1) s += __shfl_xor_sync(0xffffffffu, s, o);
    if ((threadIdx.x & 31) == 0) red[threadIdx.x >> 5] = s;
    __syncthreads();
    float scale = wa.g[layer][row] / sqrtf(red[0] + red[1] + red[2] + red[3]);
    if (layer == 0) {
        for (int k = threadIdx.x; k < din; k += blockDim.x)
            g_w0[(size_t)row * din + k] = vr[k] * scale;
    } else {
        __half* w = g_wm + (size_t)(layer - 1) * 256 * 256 + (size_t)row * 256;
        for (int k = threadIdx.x; k < din; k += blockDim.x)
            w[k] = __float2half_rn(vr[k] * scale);
    }
}

// ------------------------- affine + xyz update -------------------------
__global__ __launch_bounds__(256) void affine_xyz(const __half* __restrict__ h_in,
                                                  const float* __restrict__ W_aff,
                                                  const float* __restrict__ b_aff)
{
    __shared__ float sW[6 * HID];
    for (int i = threadIdx.x; i < 6 * HID; i += 256) sW[i] = W_aff[i];
    __syncthreads();
    int warp = threadIdx.x >> 5, lane = threadIdx.x & 31;
    int m = blockIdx.x * 8 + warp;
    const __half* h = h_in + (size_t)m * HID;
    float p0 = 0, p1 = 0, p2 = 0, p3 = 0, p4 = 0, p5 = 0;
    for (int k = lane; k < HID; k += 32) {
        float hv = __half2float(h[k]);
        p0 += sW[k] * hv;           p1 += sW[HID + k] * hv;
        p2 += sW[2 * HID + k] * hv; p3 += sW[3 * HID + k] * hv;
        p4 += sW[4 * HID + k] * hv; p5 += sW[5 * HID + k] * hv;
    }
#pragma unroll
    for (int o = 16; o; o >>= 1) {
        p0 += __shfl_xor_sync(0xffffffffu, p0, o);
        p1 += __shfl_xor_sync(0xffffffffu, p1, o);
        p2 += __shfl_xor_sync(0xffffffffu, p2, o);
        p3 += __shfl_xor_sync(0xffffffffu, p3, o);
        p4 += __shfl_xor_sync(0xffffffffu, p4, o);
        p5 += __shfl_xor_sync(0xffffffffu, p5, o);
    }
    if (lane == 0) {
        float a0 = p0 + b_aff[0], a1 = p1 + b_aff[1], a2 = p2 + b_aff[2];
        float a3 = p3 + b_aff[3], a4 = p4 + b_aff[4], a5 = p5 + b_aff[5];
        float x0 = g_xyz[m * 3], x1 = g_xyz[m * 3 + 1], x2 = g_xyz[m * 3 + 2];
        g_xyz[m * 3 + 0] = a3 + (1.f + a0) * x0;
        g_xyz[m * 3 + 1] = a4 + (1.f + a1) * x1;
        g_xyz[m * 3 + 2] = a5 + (1.f + a2) * x2;
    }
}

// ------------------------- decoder layer 0 / final dot -------------------------
__global__ __launch_bounds__(256) void dec0(const float* __restrict__ b0)
{
    __shared__ float sw[768];
    __shared__ float sb[256];
    for (int i = threadIdx.x; i < 768; i += 256) sw[i] = g_w0[i];
    sb[threadIdx.x] = b0[threadIdx.x];
    __syncthreads();
    size_t idx = (size_t)blockIdx.x * 256 + threadIdx.x;
    int m = (int)(idx >> 8), i = (int)(idx & 255);
    float v = sw[i * 3] * g_xyz[m * 3] + sw[i * 3 + 1] * g_xyz[m * 3 + 1]
            + sw[i * 3 + 2] * g_xyz[m * 3 + 2] + sb[i];
    g_act0[idx] = __float2half_rn(fmaxf(v, 0.f));
}
__global__ __launch_bounds__(256) void dec5(const float* __restrict__ W5,
                                            const float* __restrict__ b5,
                                            const __half* __restrict__ x,
                                            float* __restrict__ out)
{
    __shared__ float sw[256];
    sw[threadIdx.x] = W5[threadIdx.x];
    __syncthreads();
    int warp = threadIdx.x >> 5, lane = threadIdx.x & 31;
    int m = blockIdx.x * 8 + warp;
    const __half* xr = x + (size_t)m * 256;
    float s = 0.f;
    for (int k = lane; k < 256; k += 32) s += __half2float(xr[k]) * sw[k];
#pragma unroll
    for (int o = 16; o; o >>= 1) s += __shfl_xor_sync(0xffffffffu, s, o);
    if (lane == 0) out[m] = s + b5[0];
}

// ------------------------- host launcher -------------------------
extern "C" void kernel_launch(void* const* d_in, const int* in_sizes, int n_in,
                              void* d_out, int out_size)
{
    const float* input = (const float*)d_in[0];
    const float* W_ih  = (const float*)d_in[1];
    const float* b_ih  = (const float*)d_in[2];
    const float* W_hh  = (const float*)d_in[3];
    const float* b_hh  = (const float*)d_in[4];
    const float* W_aff = (const float*)d_in[5];
    const float* b_aff = (const float*)d_in[6];
    WnArgs wa;
    const float* bb[5];
    for (int l = 0; l < 5; l++) {
        wa.v[l] = (const float*)d_in[7 + 3 * l];
        wa.g[l] = (const float*)d_in[8 + 3 * l];
        bb[l]   = (const float*)d_in[9 + 3 * l];
    }
    const float* W5 = (const float*)d_in[22];
    const float* b5 = (const float*)d_in[23];

    float *Gc, *cst, *xyz;
    __half *h0, *h1, *codep, *wihp, *whhp, *a0p, *a1p, *wmp;
    cudaGetSymbolAddress((void**)&Gc,    g_Gc);
    cudaGetSymbolAddress((void**)&h0,    g_h);
    cudaGetSymbolAddress((void**)&h1,    g_h2);
    cudaGetSymbolAddress((void**)&cst,   g_c);
    cudaGetSymbolAddress((void**)&xyz,   g_xyz);
    cudaGetSymbolAddress((void**)&codep, g_code);
    cudaGetSymbolAddress((void**)&wihp,  g_wih);
    cudaGetSymbolAddress((void**)&whhp,  g_whh);
    cudaGetSymbolAddress((void**)&a0p,   g_act0);
    cudaGetSymbolAddress((void**)&a1p,   g_act1);
    cudaGetSymbolAddress((void**)&wmp,   g_wm);

    const int SMEM = 2 * (ABUF + BBUF);   // 61440 B
    cudaFuncSetAttribute(gemm_h<0>, cudaFuncAttributeMaxDynamicSharedMemorySize, SMEM);
    cudaFuncSetAttribute(gemm_h<1>, cudaFuncAttributeMaxDynamicSharedMemorySize, SMEM);
    cudaFuncSetAttribute(gemm_h<2>, cudaFuncAttributeMaxDynamicSharedMemorySize, SMEM);

    extract_code<<<NSAMP, 256>>>(input);
    prep_weights<<<NGATE, 256>>>(W_ih, W_hh);
    wnorm_all<<<1280, 128>>>(wa);

    // launch 3 (profiled): fused Gc GEMM + step-0 cell init
    gemm_h<0><<<dim3(NGATE / BN, NSAMP / BM), 512, SMEM>>>(
        codep, 256, wihp, 256, Gc, nullptr, 0, 256 / BK,
        b_ih, b_hh, W_ih, xyz, nullptr, cst, h0);

    affine_xyz<<<NSAMP / 8, 256>>>(h0, W_aff, b_aff);

    __half* hb[2] = { h0, h1 };
    for (int s = 1; s < 8; s++) {
        const __half* hin = hb[(s - 1) & 1];
        __half* hnew = hb[s & 1];
        gemm_h<1><<<dim3(HID / 64, NSAMP / BM), 512, SMEM>>>(
            hin, HID, whhp, HID, nullptr, nullptr, 0, HID / BK,
            nullptr, nullptr, W_ih, xyz, Gc, cst, hnew);
        affine_xyz<<<NSAMP / 8, 256>>>(hnew, W_aff, b_aff);
    }

    dec0<<<NSAMP, 256>>>(bb[0]);
    const __half* bufin = a0p;
    __half* bufout = a1p;
    for (int l = 1; l < 5; l++) {
        gemm_h<2><<<dim3(1, NSAMP / BM), 512, SMEM>>>(
            bufin, 256, wmp + (size_t)(l - 1) * 256 * 256, 256,
            nullptr, bufout, 256, 256 / BK,
            bb[l], nullptr, nullptr, nullptr, nullptr, nullptr, nullptr);
        const __half* tmp = bufout; bufout = (__half*)bufin; bufin = tmp;
    }
    dec5<<<NSAMP / 8, 256>>>(W5, b5, bufin, (float*)d_out);
}

// round 9
// speedup vs baseline: 2.8884x; 1.0378x over previous
#include <cuda_runtime.h>
#include <cuda_fp16.h>
#include <math.h>
#include <stdint.h>

#define NSAMP 65536
#define HID   512
#define NGATE 2048
#define DIN   259
#define BM 128
#define BN 256
#define BK 32
#define RS 20              // smem row stride in words (16 data + 4 pad)
#define ABUF (BM * RS * 4) // bytes per A stage
#define BBUF (BN * RS * 4)
#define NSTAGE 4

// ------------------------- scratch -------------------------
__device__ float  g_Gc  [(size_t)NSAMP * NGATE];
__device__ __half g_h   [(size_t)NSAMP * HID];
__device__ __half g_h2  [(size_t)NSAMP * HID];
__device__ float  g_c   [(size_t)NSAMP * HID];
__device__ float  g_xyz [NSAMP * 3];
__device__ __half g_code[(size_t)NSAMP * 256];
__device__ __half g_wih [(size_t)NGATE * 256];
__device__ __half g_whh [(size_t)NGATE * HID];
__device__ __half g_act0[(size_t)NSAMP * 256];
__device__ __half g_act1[(size_t)NSAMP * 256];
__device__ float  g_w0  [256 * 3];
__device__ __half g_wm  [4 * 256 * 256];

__device__ __forceinline__ float sigm(float x) { return 1.f / (1.f + __expf(-x)); }
__device__ __forceinline__ void cp16(uint32_t d, const void* s) {
    asm volatile("cp.async.cg.shared.global [%0], [%1], 16;" :: "r"(d), "l"(s) : "memory");
}
__device__ __forceinline__ void mma16(float* d, const unsigned* a, unsigned b0, unsigned b1) {
    asm volatile(
        "mma.sync.aligned.m16n8k16.row.col.f32.f16.f16.f32 "
        "{%0,%1,%2,%3}, {%4,%5,%6,%7}, {%8,%9}, {%0,%1,%2,%3};"
        : "+f"(d[0]), "+f"(d[1]), "+f"(d[2]), "+f"(d[3])
        : "r"(a[0]), "r"(a[1]), "r"(a[2]), "r"(a[3]), "r"(b0), "r"(b1));
}
#define LDSM4(R, ADDR)                                                         \
    asm volatile("ldmatrix.sync.aligned.m8n8.x4.shared.b16 {%0,%1,%2,%3}, [%4];" \
        : "=r"((R)[0]), "=r"((R)[1]), "=r"((R)[2]), "=r"((R)[3]) : "r"(ADDR))

// =====================================================================
// FP16 GEMM (fp32 accum), 512 threads = 16 warps (4m x 4n), warp tile
// 32x64, BK=32, 4-stage cp.async pipeline, ldmatrix fragments.
// MODE 0: Gc build + step-0 cell init    MODE 1: LSTM step s>=1
// MODE 2: decoder relu layer
// =====================================================================
template<int MODE>
__global__ void __launch_bounds__(512, 1) gemm_h(
    const __half* __restrict__ A, int lda,
    const __half* __restrict__ B, int ldb,
    float* __restrict__ Cf, __half* __restrict__ Ch, int ldc, int kIters,
    const float* __restrict__ bias, const float* __restrict__ bias2,
    const float* __restrict__ Wih, const float* __restrict__ xyz,
    const float* __restrict__ Gc,
    float* __restrict__ cst, __half* __restrict__ hout)
{
    extern __shared__ uint32_t smw[];
    const int tid = threadIdx.x, lane = tid & 31, wid = tid >> 5;
    const int wm = wid >> 2, wn = wid & 3;
    const int g = lane >> 2, t = lane & 3;
    const int m0 = blockIdx.y * BM;
    const int n0 = blockIdx.x * BN;
    const int j0 = blockIdx.x * 64;

    // ---- load roles ----
    const int arow = tid >> 2, aseg = tid & 3;          // A: 1 cp16/thread
    const int br = tid >> 1, bseg2 = (tid & 1) * 2;     // B: 2 cp16/thread
    int brow;
    if (MODE == 0 || MODE == 1) {
        int w = br >> 6, cw = br & 63;
        brow = (cw >> 4) * HID + j0 + (cw & 15) + (w << 4);
    } else brow = n0 + br;

    const __half* aptr = A + (size_t)(m0 + arow) * lda + aseg * 8;
    const __half* bptr = B + (size_t)brow * ldb + bseg2 * 8;

    const uint32_t asb = (uint32_t)__cvta_generic_to_shared(smw);
    const uint32_t bsb = asb + NSTAGE * ABUF;
    const uint32_t aoff = asb + (arow * RS + aseg * 4) * 4;
    const uint32_t boff = bsb + (br * RS + bseg2 * 4) * 4;

    // ---- fragment addresses (loop-invariant) ----
    const int lr = lane & 15, lw = (lane >> 4) * 16;
    uint32_t aadr[2], badr[4];
#pragma unroll
    for (int mt = 0; mt < 2; mt++)
        aadr[mt] = asb + (uint32_t)((wm * 32 + mt * 16 + lr) * RS * 4) + lw;
#pragma unroll
    for (int p = 0; p < 4; p++)
        badr[p] = bsb + (uint32_t)((wn * 64 + p * 16 + lr) * RS * 4) + lw;

    float acc[2][8][4];
#pragma unroll
    for (int i = 0; i < 2; i++)
#pragma unroll
        for (int j = 0; j < 8; j++)
#pragma unroll
            for (int k = 0; k < 4; k++) acc[i][j][k] = 0.f;

#define LOADTILE(IT, BUF)                                                     \
    do {                                                                      \
        cp16(aoff + (BUF) * ABUF, aptr + (IT) * BK);                          \
        cp16(boff + (BUF) * BBUF, bptr + (IT) * BK);                          \
        cp16(boff + (BUF) * BBUF + 16, bptr + (IT) * BK + 8);                 \
    } while (0)

    // prologue: 3 tiles in flight (kIters >= 8 always)
    LOADTILE(0, 0);
    asm volatile("cp.async.commit_group;" ::: "memory");
    LOADTILE(1, 1);
    asm volatile("cp.async.commit_group;" ::: "memory");
    LOADTILE(2, 2);
    asm volatile("cp.async.commit_group;" ::: "memory");

    for (int it = 0; it < kIters; ++it) {
        asm volatile("cp.async.wait_group 2;" ::: "memory");
        __syncthreads();
        if (it + 3 < kIters) LOADTILE(it + 3, (it + 3) & (NSTAGE - 1));
        asm volatile("cp.async.commit_group;" ::: "memory");   // always: keeps group count exact

        const uint32_t ao = (it & (NSTAGE - 1)) * ABUF;
        const uint32_t bo = (it & (NSTAGE - 1)) * BBUF;
#pragma unroll
        for (int ks = 0; ks < 2; ks++) {
            unsigned af[2][4];
            LDSM4(af[0], aadr[0] + ao + ks * 32);
            LDSM4(af[1], aadr[1] + ao + ks * 32);
#pragma unroll
            for (int p = 0; p < 4; p++) {
                unsigned bb[4];
                LDSM4(bb, badr[p] + bo + ks * 32);
                mma16(acc[0][2 * p],     af[0], bb[0], bb[2]);
                mma16(acc[0][2 * p + 1], af[0], bb[1], bb[3]);
                mma16(acc[1][2 * p],     af[1], bb[0], bb[2]);
                mma16(acc[1][2 * p + 1], af[1], bb[1], bb[3]);
            }
        }
    }
#undef LOADTILE

    // ----------------- epilogue -----------------
    if (MODE == 0 || MODE == 1) {
#pragma unroll
        for (int q = 0; q < 2; q++) {
            const int jc = j0 + wn * 16 + q * 8 + 2 * t;
            float wt[4][2][3];
            float bi[4][2];
#pragma unroll
            for (int gt = 0; gt < 4; gt++)
#pragma unroll
                for (int e = 0; e < 2; e++) {
                    const float* wr = Wih + (size_t)(gt * HID + jc + e) * DIN + 256;
                    wt[gt][e][0] = wr[0]; wt[gt][e][1] = wr[1]; wt[gt][e][2] = wr[2];
                    if (MODE == 0)
                        bi[gt][e] = bias[gt * HID + jc + e] + bias2[gt * HID + jc + e];
                }
#pragma unroll
            for (int mt = 0; mt < 2; mt++)
#pragma unroll
                for (int rr = 0; rr < 2; rr++) {
                    int r = m0 + wm * 32 + mt * 16 + g + rr * 8;
                    float x0 = xyz[r * 3], x1 = xyz[r * 3 + 1], x2 = xyz[r * 3 + 2];
                    float2 cn; __half2 hn;
                    if (MODE == 0) {
                        float* gco = Cf + (size_t)r * NGATE + jc;
                        float2 gcs[4];
#pragma unroll
                        for (int e = 0; e < 2; e++) {
                            int a = rr * 2 + e;
                            float gcv[4], gate[4];
#pragma unroll
                            for (int gt = 0; gt < 4; gt++) {
                                gcv[gt] = acc[mt][2 * gt + q][a] + bi[gt][e];
                                gate[gt] = gcv[gt] + x0 * wt[gt][e][0]
                                         + x1 * wt[gt][e][1] + x2 * wt[gt][e][2];
                            }
                            float c2 = sigm(gate[0]) * tanhf(gate[2]);
                            __half h2 = __float2half_rn(sigm(gate[3]) * tanhf(c2));
                            if (e) {
                                cn.y = c2; hn.y = h2;
                                gcs[0].y = gcv[0]; gcs[1].y = gcv[1];
                                gcs[2].y = gcv[2]; gcs[3].y = gcv[3];
                            } else {
                                cn.x = c2; hn.x = h2;
                                gcs[0].x = gcv[0]; gcs[1].x = gcv[1];
                                gcs[2].x = gcv[2]; gcs[3].x = gcv[3];
                            }
                        }
#pragma unroll
                        for (int gt = 0; gt < 4; gt++)
                            *(float2*)(gco + gt * HID) = gcs[gt];
                    } else {
                        const float* gcr = Gc + (size_t)r * NGATE + jc;
                        float2 co = *(const float2*)(cst + (size_t)r * HID + jc);
#pragma unroll
                        for (int e = 0; e < 2; e++) {
                            int a = rr * 2 + e;
                            float iv = acc[mt][0 + q][a] + gcr[e]
                                     + x0 * wt[0][e][0] + x1 * wt[0][e][1] + x2 * wt[0][e][2];
                            float fv = acc[mt][2 + q][a] + gcr[HID + e]
                                     + x0 * wt[1][e][0] + x1 * wt[1][e][1] + x2 * wt[1][e][2];
                            float gv = acc[mt][4 + q][a] + gcr[2 * HID + e]
                                     + x0 * wt[2][e][0] + x1 * wt[2][e][1] + x2 * wt[2][e][2];
                            float ov = acc[mt][6 + q][a] + gcr[3 * HID + e]
                                     + x0 * wt[3][e][0] + x1 * wt[3][e][1] + x2 * wt[3][e][2];
                            float cold = e ? co.y : co.x;
                            float c2 = sigm(fv) * cold + sigm(iv) * tanhf(gv);
                            __half h2 = __float2half_rn(sigm(ov) * tanhf(c2));
                            if (e) { cn.y = c2; hn.y = h2; } else { cn.x = c2; hn.x = h2; }
                        }
                    }
                    *(float2*)(cst + (size_t)r * HID + jc) = cn;
                    *(__half2*)(hout + (size_t)r * HID + jc) = hn;
                }
        }
    } else {
#pragma unroll
        for (int mt = 0; mt < 2; mt++)
#pragma unroll
            for (int nt = 0; nt < 8; nt++) {
                int c = n0 + wn * 64 + nt * 8 + 2 * t;
                float b0v = bias[c], b1v = bias[c + 1];
#pragma unroll
                for (int rr = 0; rr < 2; rr++) {
                    int r = m0 + wm * 32 + mt * 16 + g + rr * 8;
                    __half2 o;
                    o.x = __float2half_rn(fmaxf(acc[mt][nt][rr * 2 + 0] + b0v, 0.f));
                    o.y = __float2half_rn(fmaxf(acc[mt][nt][rr * 2 + 1] + b1v, 0.f));
                    *(__half2*)(Ch + (size_t)r * ldc + c) = o;
                }
            }
    }
}

// ------------------------- prep kernels -------------------------
__global__ void extract_code(const float* __restrict__ input)
{
    int m = blockIdx.x, k = threadIdx.x;
    g_code[(size_t)m * 256 + k] = __float2half_rn(input[(size_t)m * DIN + k]);
    if (k < 3) g_xyz[m * 3 + k] = input[(size_t)m * DIN + 256 + k];
}
__global__ void prep_weights(const float* __restrict__ W_ih, const float* __restrict__ W_hh)
{
    int r = blockIdx.x, t = threadIdx.x;
    g_wih[(size_t)r * 256 + t] = __float2half_rn(W_ih[(size_t)r * DIN + t]);
    g_whh[(size_t)r * HID + t]       = __float2half_rn(W_hh[(size_t)r * HID + t]);
    g_whh[(size_t)r * HID + 256 + t] = __float2half_rn(W_hh[(size_t)r * HID + 256 + t]);
}
struct WnArgs { const float* v[5]; const float* g[5]; };
__global__ void wnorm_all(WnArgs wa)
{
    int layer = blockIdx.x >> 8, row = blockIdx.x & 255;
    int din = (layer == 0) ? 3 : 256;
    const float* vr = wa.v[layer] + (size_t)row * din;
    float s = 0.f;
    for (int k = threadIdx.x; k < din; k += blockDim.x) { float x = vr[k]; s += x * x; }
    __shared__ float red[4];
#pragma unroll
    for (int o = 16; o; o >>= 1) s += __shfl_xor_sync(0xffffffffu, s, o);
    if ((threadIdx.x & 31) == 0) red[threadIdx.x >> 5] = s;
    __syncthreads();
    float scale = wa.g[layer][row] / sqrtf(red[0] + red[1] + red[2] + red[3]);
    if (layer == 0) {
        for (int k = threadIdx.x; k < din; k += blockDim.x)
            g_w0[(size_t)row * din + k] = vr[k] * scale;
    } else {
        __half* w = g_wm + (size_t)(layer - 1) * 256 * 256 + (size_t)row * 256;
        for (int k = threadIdx.x; k < din; k += blockDim.x)
            w[k] = __float2half_rn(vr[k] * scale);
    }
}

// ------------------------- affine + xyz update -------------------------
__global__ __launch_bounds__(256) void affine_xyz(const __half* __restrict__ h_in,
                                                  const float* __restrict__ W_aff,
                                                  const float* __restrict__ b_aff)
{
    __shared__ float sW[6 * HID];
    for (int i = threadIdx.x; i < 6 * HID; i += 256) sW[i] = W_aff[i];
    __syncthreads();
    int warp = threadIdx.x >> 5, lane = threadIdx.x & 31;
    int m = blockIdx.x * 8 + warp;
    const __half* h = h_in + (size_t)m * HID;
    float p0 = 0, p1 = 0, p2 = 0, p3 = 0, p4 = 0, p5 = 0;
    for (int k = lane; k < HID; k += 32) {
        float hv = __half2float(h[k]);
        p0 += sW[k] * hv;           p1 += sW[HID + k] * hv;
        p2 += sW[2 * HID + k] * hv; p3 += sW[3 * HID + k] * hv;
        p4 += sW[4 * HID + k] * hv; p5 += sW[5 * HID + k] * hv;
    }
#pragma unroll
    for (int o = 16; o; o >>= 1) {
        p0 += __shfl_xor_sync(0xffffffffu, p0, o);
        p1 += __shfl_xor_sync(0xffffffffu, p1, o);
        p2 += __shfl_xor_sync(0xffffffffu, p2, o);
        p3 += __shfl_xor_sync(0xffffffffu, p3, o);
        p4 += __shfl_xor_sync(0xffffffffu, p4, o);
        p5 += __shfl_xor_sync(0xffffffffu, p5, o);
    }
    if (lane == 0) {
        float a0 = p0 + b_aff[0], a1 = p1 + b_aff[1], a2 = p2 + b_aff[2];
        float a3 = p3 + b_aff[3], a4 = p4 + b_aff[4], a5 = p5 + b_aff[5];
        float x0 = g_xyz[m * 3], x1 = g_xyz[m * 3 + 1], x2 = g_xyz[m * 3 + 2];
        g_xyz[m * 3 + 0] = a3 + (1.f + a0) * x0;
        g_xyz[m * 3 + 1] = a4 + (1.f + a1) * x1;
        g_xyz[m * 3 + 2] = a5 + (1.f + a2) * x2;
    }
}

// ------------------------- decoder layer 0 / final dot -------------------------
__global__ __launch_bounds__(256) void dec0(const float* __restrict__ b0)
{
    __shared__ float sw[768];
    __shared__ float sb[256];
    for (int i = threadIdx.x; i < 768; i += 256) sw[i] = g_w0[i];
    sb[threadIdx.x] = b0[threadIdx.x];
    __syncthreads();
    size_t idx = (size_t)blockIdx.x * 256 + threadIdx.x;
    int m = (int)(idx >> 8), i = (int)(idx & 255);
    float v = sw[i * 3] * g_xyz[m * 3] + sw[i * 3 + 1] * g_xyz[m * 3 + 1]
            + sw[i * 3 + 2] * g_xyz[m * 3 + 2] + sb[i];
    g_act0[idx] = __float2half_rn(fmaxf(v, 0.f));
}
__global__ __launch_bounds__(256) void dec5(const float* __restrict__ W5,
                                            const float* __restrict__ b5,
                                            const __half* __restrict__ x,
                                            float* __restrict__ out)
{
    __shared__ float sw[256];
    sw[threadIdx.x] = W5[threadIdx.x];
    __syncthreads();
    int warp = threadIdx.x >> 5, lane = threadIdx.x & 31;
    int m = blockIdx.x * 8 + warp;
    const __half* xr = x + (size_t)m * 256;
    float s = 0.f;
    for (int k = lane; k < 256; k += 32) s += __half2float(xr[k]) * sw[k];
#pragma unroll
    for (int o = 16; o; o >>= 1) s += __shfl_xor_sync(0xffffffffu, s, o);
    if (lane == 0) out[m] = s + b5[0];
}

// ------------------------- host launcher -------------------------
extern "C" void kernel_launch(void* const* d_in, const int* in_sizes, int n_in,
                              void* d_out, int out_size)
{
    const float* input = (const float*)d_in[0];
    const float* W_ih  = (const float*)d_in[1];
    const float* b_ih  = (const float*)d_in[2];
    const float* W_hh  = (const float*)d_in[3];
    const float* b_hh  = (const float*)d_in[4];
    const float* W_aff = (const float*)d_in[5];
    const float* b_aff = (const float*)d_in[6];
    WnArgs wa;
    const float* bb[5];
    for (int l = 0; l < 5; l++) {
        wa.v[l] = (const float*)d_in[7 + 3 * l];
        wa.g[l] = (const float*)d_in[8 + 3 * l];
        bb[l]   = (const float*)d_in[9 + 3 * l];
    }
    const float* W5 = (const float*)d_in[22];
    const float* b5 = (const float*)d_in[23];

    float *Gc, *cst, *xyz;
    __half *h0, *h1, *codep, *wihp, *whhp, *a0p, *a1p, *wmp;
    cudaGetSymbolAddress((void**)&Gc,    g_Gc);
    cudaGetSymbolAddress((void**)&h0,    g_h);
    cudaGetSymbolAddress((void**)&h1,    g_h2);
    cudaGetSymbolAddress((void**)&cst,   g_c);
    cudaGetSymbolAddress((void**)&xyz,   g_xyz);
    cudaGetSymbolAddress((void**)&codep, g_code);
    cudaGetSymbolAddress((void**)&wihp,  g_wih);
    cudaGetSymbolAddress((void**)&whhp,  g_whh);
    cudaGetSymbolAddress((void**)&a0p,   g_act0);
    cudaGetSymbolAddress((void**)&a1p,   g_act1);
    cudaGetSymbolAddress((void**)&wmp,   g_wm);

    const int SMEM = NSTAGE * (ABUF + BBUF);   // 122880 B
    cudaFuncSetAttribute(gemm_h<0>, cudaFuncAttributeMaxDynamicSharedMemorySize, SMEM);
    cudaFuncSetAttribute(gemm_h<1>, cudaFuncAttributeMaxDynamicSharedMemorySize, SMEM);
    cudaFuncSetAttribute(gemm_h<2>, cudaFuncAttributeMaxDynamicSharedMemorySize, SMEM);

    extract_code<<<NSAMP, 256>>>(input);
    prep_weights<<<NGATE, 256>>>(W_ih, W_hh);
    wnorm_all<<<1280, 128>>>(wa);

    // launch 3 (profiled): fused Gc GEMM + step-0 cell init
    gemm_h<0><<<dim3(NGATE / BN, NSAMP / BM), 512, SMEM>>>(
        codep, 256, wihp, 256, Gc, nullptr, 0, 256 / BK,
        b_ih, b_hh, W_ih, xyz, nullptr, cst, h0);

    affine_xyz<<<NSAMP / 8, 256>>>(h0, W_aff, b_aff);

    __half* hb[2] = { h0, h1 };
    for (int s = 1; s < 8; s++) {
        const __half* hin = hb[(s - 1) & 1];
        __half* hnew = hb[s & 1];
        gemm_h<1><<<dim3(HID / 64, NSAMP / BM), 512, SMEM>>>(
            hin, HID, whhp, HID, nullptr, nullptr, 0, HID / BK,
            nullptr, nullptr, W_ih, xyz, Gc, cst, hnew);
        affine_xyz<<<NSAMP / 8, 256>>>(hnew, W_aff, b_aff);
    }

    dec0<<<NSAMP, 256>>>(bb[0]);
    const __half* bufin = a0p;
    __half* bufout = a1p;
    for (int l = 1; l < 5; l++) {
        gemm_h<2><<<dim3(1, NSAMP / BM), 512, SMEM>>>(
            bufin, 256, wmp + (size_t)(l - 1) * 256 * 256, 256,
            nullptr, bufout, 256, 256 / BK,
            bb[l], nullptr, nullptr, nullptr, nullptr, nullptr, nullptr);
        const __half* tmp = bufout; bufout = (__half*)bufin; bufin = tmp;
    }
    dec5<<<NSAMP / 8, 256>>>(W5, b5, bufin, (float*)d_out);
}

// round 10
// speedup vs baseline: 3.0248x; 1.0472x over previous
#include <cuda_runtime.h>
#include <cuda_fp16.h>
#include <math.h>
#include <stdint.h>

#define NSAMP 65536
#define HID   512
#define NGATE 2048
#define DIN   259
#define BM 128
#define BN 128
#define BK 32
#define RS 20              // smem row stride in words (16 data + 4 pad)
#define ABUF (BM * RS * 4) // bytes per A stage (10240)
#define BBUF (BN * RS * 4)
#define NSTAGE 4

// ------------------------- scratch -------------------------
__device__ float  g_Gc  [(size_t)NSAMP * NGATE];
__device__ __half g_h   [(size_t)NSAMP * HID];
__device__ __half g_h2  [(size_t)NSAMP * HID];
__device__ float  g_c   [(size_t)NSAMP * HID];
__device__ float  g_xyz [NSAMP * 3];
__device__ __half g_code[(size_t)NSAMP * 256];
__device__ __half g_wih [(size_t)NGATE * 256];
__device__ __half g_whh [(size_t)NGATE * HID];
__device__ __half g_act0[(size_t)NSAMP * 256];
__device__ __half g_act1[(size_t)NSAMP * 256];
__device__ float  g_w0  [256 * 3];
__device__ __half g_wm  [4 * 256 * 256];

__device__ __forceinline__ float sigm(float x) { return 1.f / (1.f + __expf(-x)); }
__device__ __forceinline__ void cp16(uint32_t d, const void* s) {
    asm volatile("cp.async.cg.shared.global [%0], [%1], 16;" :: "r"(d), "l"(s) : "memory");
}
__device__ __forceinline__ void mma16(float* d, const unsigned* a, unsigned b0, unsigned b1) {
    asm volatile(
        "mma.sync.aligned.m16n8k16.row.col.f32.f16.f16.f32 "
        "{%0,%1,%2,%3}, {%4,%5,%6,%7}, {%8,%9}, {%0,%1,%2,%3};"
        : "+f"(d[0]), "+f"(d[1]), "+f"(d[2]), "+f"(d[3])
        : "r"(a[0]), "r"(a[1]), "r"(a[2]), "r"(a[3]), "r"(b0), "r"(b1));
}
#define LDSM4(R, ADDR)                                                         \
    asm volatile("ldmatrix.sync.aligned.m8n8.x4.shared.b16 {%0,%1,%2,%3}, [%4];" \
        : "=r"((R)[0]), "=r"((R)[1]), "=r"((R)[2]), "=r"((R)[3]) : "r"(ADDR))

// =====================================================================
// FP16 GEMM (fp32 accum), 256 threads = 8 warps (4m x 2n), warp tile
// 32x64, block tile 128x128, BK=32, 4-stage cp.async, 2 CTAs/SM.
// MODE 0: Gc build + step-0 cell init    MODE 1: LSTM step s>=1
// MODE 2: decoder relu layer
// =====================================================================
template<int MODE>
__global__ void __launch_bounds__(256, 2) gemm_h(
    const __half* __restrict__ A, int lda,
    const __half* __restrict__ B, int ldb,
    float* __restrict__ Cf, __half* __restrict__ Ch, int ldc, int kIters,
    const float* __restrict__ bias, const float* __restrict__ bias2,
    const float* __restrict__ Wih, const float* __restrict__ xyz,
    const float* __restrict__ Gc,
    float* __restrict__ cst, __half* __restrict__ hout)
{
    extern __shared__ uint32_t smw[];
    const int tid = threadIdx.x, lane = tid & 31, wid = tid >> 5;
    const int wm = wid >> 1, wn = wid & 1;
    const int g = lane >> 2, t = lane & 3;
    const int m0 = blockIdx.y * BM;
    const int n0 = blockIdx.x * BN;
    const int j0 = blockIdx.x * 32;      // 32 hidden units x 4 gates per block

    // ---- load roles: each thread 2 cp16 for A, 2 for B ----
    const int arow = tid >> 1, seg = tid & 1;   // seg selects 16-half chunk
    int brow;
    if (MODE == 0 || MODE == 1) {
        int w = arow >> 6, cw = arow & 63;      // arow doubles as B smem row
        brow = (cw >> 4) * HID + j0 + (cw & 15) + (w << 4);
    } else brow = n0 + arow;

    const __half* aptr = A + (size_t)(m0 + arow) * lda + seg * 16;
    const __half* bptr = B + (size_t)brow * ldb + seg * 16;

    const uint32_t asb = (uint32_t)__cvta_generic_to_shared(smw);
    const uint32_t bsb = asb + NSTAGE * ABUF;
    const uint32_t aoff = asb + arow * (RS * 4) + seg * 32;
    const uint32_t boff = bsb + arow * (RS * 4) + seg * 32;

    // ---- fragment addresses (loop-invariant) ----
    const int lr = lane & 15, lw = (lane >> 4) * 16;
    uint32_t aadr[2], badr[4];
#pragma unroll
    for (int mt = 0; mt < 2; mt++)
        aadr[mt] = asb + (uint32_t)((wm * 32 + mt * 16 + lr) * RS * 4) + lw;
#pragma unroll
    for (int p = 0; p < 4; p++)
        badr[p] = bsb + (uint32_t)((wn * 64 + p * 16 + lr) * RS * 4) + lw;

    float acc[2][8][4];
#pragma unroll
    for (int i = 0; i < 2; i++)
#pragma unroll
        for (int j = 0; j < 8; j++)
#pragma unroll
            for (int k = 0; k < 4; k++) acc[i][j][k] = 0.f;

#define LOADTILE(IT, BUF)                                                     \
    do {                                                                      \
        cp16(aoff + (BUF) * ABUF, aptr + (IT) * BK);                          \
        cp16(aoff + (BUF) * ABUF + 16, aptr + (IT) * BK + 8);                 \
        cp16(boff + (BUF) * BBUF, bptr + (IT) * BK);                          \
        cp16(boff + (BUF) * BBUF + 16, bptr + (IT) * BK + 8);                 \
    } while (0)

    // prologue: 3 tiles in flight (kIters >= 8 always)
    LOADTILE(0, 0);
    asm volatile("cp.async.commit_group;" ::: "memory");
    LOADTILE(1, 1);
    asm volatile("cp.async.commit_group;" ::: "memory");
    LOADTILE(2, 2);
    asm volatile("cp.async.commit_group;" ::: "memory");

    for (int it = 0; it < kIters; ++it) {
        asm volatile("cp.async.wait_group 2;" ::: "memory");
        __syncthreads();
        if (it + 3 < kIters) LOADTILE(it + 3, (it + 3) & (NSTAGE - 1));
        asm volatile("cp.async.commit_group;" ::: "memory");

        const uint32_t ao = (it & (NSTAGE - 1)) * ABUF;
        const uint32_t bo = (it & (NSTAGE - 1)) * BBUF;
#pragma unroll
        for (int ks = 0; ks < 2; ks++) {
            unsigned af[2][4];
            LDSM4(af[0], aadr[0] + ao + ks * 32);
            LDSM4(af[1], aadr[1] + ao + ks * 32);
#pragma unroll
            for (int p = 0; p < 4; p++) {
                unsigned bb[4];
                LDSM4(bb, badr[p] + bo + ks * 32);
                mma16(acc[0][2 * p],     af[0], bb[0], bb[2]);
                mma16(acc[0][2 * p + 1], af[0], bb[1], bb[3]);
                mma16(acc[1][2 * p],     af[1], bb[0], bb[2]);
                mma16(acc[1][2 * p + 1], af[1], bb[1], bb[3]);
            }
        }
    }
#undef LOADTILE

    // ----------------- epilogue -----------------
    if (MODE == 0 || MODE == 1) {
#pragma unroll
        for (int q = 0; q < 2; q++) {
            const int jc = j0 + wn * 16 + q * 8 + 2 * t;
            float wt[4][2][3];
            float bi[4][2];
#pragma unroll
            for (int gt = 0; gt < 4; gt++)
#pragma unroll
                for (int e = 0; e < 2; e++) {
                    const float* wr = Wih + (size_t)(gt * HID + jc + e) * DIN + 256;
                    wt[gt][e][0] = wr[0]; wt[gt][e][1] = wr[1]; wt[gt][e][2] = wr[2];
                    if (MODE == 0)
                        bi[gt][e] = bias[gt * HID + jc + e] + bias2[gt * HID + jc + e];
                }
#pragma unroll
            for (int mt = 0; mt < 2; mt++)
#pragma unroll
                for (int rr = 0; rr < 2; rr++) {
                    int r = m0 + wm * 32 + mt * 16 + g + rr * 8;
                    float x0 = xyz[r * 3], x1 = xyz[r * 3 + 1], x2 = xyz[r * 3 + 2];
                    float2 cn; __half2 hn;
                    if (MODE == 0) {
                        float* gco = Cf + (size_t)r * NGATE + jc;
                        float2 gcs[4];
#pragma unroll
                        for (int e = 0; e < 2; e++) {
                            int a = rr * 2 + e;
                            float gcv[4], gate[4];
#pragma unroll
                            for (int gt = 0; gt < 4; gt++) {
                                gcv[gt] = acc[mt][2 * gt + q][a] + bi[gt][e];
                                gate[gt] = gcv[gt] + x0 * wt[gt][e][0]
                                         + x1 * wt[gt][e][1] + x2 * wt[gt][e][2];
                            }
                            float c2 = sigm(gate[0]) * tanhf(gate[2]);
                            __half h2 = __float2half_rn(sigm(gate[3]) * tanhf(c2));
                            if (e) {
                                cn.y = c2; hn.y = h2;
                                gcs[0].y = gcv[0]; gcs[1].y = gcv[1];
                                gcs[2].y = gcv[2]; gcs[3].y = gcv[3];
                            } else {
                                cn.x = c2; hn.x = h2;
                                gcs[0].x = gcv[0]; gcs[1].x = gcv[1];
                                gcs[2].x = gcv[2]; gcs[3].x = gcv[3];
                            }
                        }
#pragma unroll
                        for (int gt = 0; gt < 4; gt++)
                            *(float2*)(gco + gt * HID) = gcs[gt];
                    } else {
                        const float* gcr = Gc + (size_t)r * NGATE + jc;
                        float2 co = *(const float2*)(cst + (size_t)r * HID + jc);
#pragma unroll
                        for (int e = 0; e < 2; e++) {
                            int a = rr * 2 + e;
                            float iv = acc[mt][0 + q][a] + gcr[e]
                                     + x0 * wt[0][e][0] + x1 * wt[0][e][1] + x2 * wt[0][e][2];
                            float fv = acc[mt][2 + q][a] + gcr[HID + e]
                                     + x0 * wt[1][e][0] + x1 * wt[1][e][1] + x2 * wt[1][e][2];
                            float gv = acc[mt][4 + q][a] + gcr[2 * HID + e]
                                     + x0 * wt[2][e][0] + x1 * wt[2][e][1] + x2 * wt[2][e][2];
                            float ov = acc[mt][6 + q][a] + gcr[3 * HID + e]
                                     + x0 * wt[3][e][0] + x1 * wt[3][e][1] + x2 * wt[3][e][2];
                            float cold = e ? co.y : co.x;
                            float c2 = sigm(fv) * cold + sigm(iv) * tanhf(gv);
                            __half h2 = __float2half_rn(sigm(ov) * tanhf(c2));
                            if (e) { cn.y = c2; hn.y = h2; } else { cn.x = c2; hn.x = h2; }
                        }
                    }
                    *(float2*)(cst + (size_t)r * HID + jc) = cn;
                    *(__half2*)(hout + (size_t)r * HID + jc) = hn;
                }
        }
    } else {
#pragma unroll
        for (int mt = 0; mt < 2; mt++)
#pragma unroll
            for (int nt = 0; nt < 8; nt++) {
                int c = n0 + wn * 64 + nt * 8 + 2 * t;
                float b0v = bias[c], b1v = bias[c + 1];
#pragma unroll
                for (int rr = 0; rr < 2; rr++) {
                    int r = m0 + wm * 32 + mt * 16 + g + rr * 8;
                    __half2 o;
                    o.x = __float2half_rn(fmaxf(acc[mt][nt][rr * 2 + 0] + b0v, 0.f));
                    o.y = __float2half_rn(fmaxf(acc[mt][nt][rr * 2 + 1] + b1v, 0.f));
                    *(__half2*)(Ch + (size_t)r * ldc + c) = o;
                }
            }
    }
}

// ------------------------- prep kernels -------------------------
__global__ void extract_code(const float* __restrict__ input)
{
    int m = blockIdx.x, k = threadIdx.x;
    g_code[(size_t)m * 256 + k] = __float2half_rn(input[(size_t)m * DIN + k]);
    if (k < 3) g_xyz[m * 3 + k] = input[(size_t)m * DIN + 256 + k];
}
__global__ void prep_weights(const float* __restrict__ W_ih, const float* __restrict__ W_hh)
{
    int r = blockIdx.x, t = threadIdx.x;
    g_wih[(size_t)r * 256 + t] = __float2half_rn(W_ih[(size_t)r * DIN + t]);
    g_whh[(size_t)r * HID + t]       = __float2half_rn(W_hh[(size_t)r * HID + t]);
    g_whh[(size_t)r * HID + 256 + t] = __float2half_rn(W_hh[(size_t)r * HID + 256 + t]);
}
struct WnArgs { const float* v[5]; const float* g[5]; };
__global__ void wnorm_all(WnArgs wa)
{
    int layer = blockIdx.x >> 8, row = blockIdx.x & 255;
    int din = (layer == 0) ? 3 : 256;
    const float* vr = wa.v[layer] + (size_t)row * din;
    float s = 0.f;
    for (int k = threadIdx.x; k < din; k += blockDim.x) { float x = vr[k]; s += x * x; }
    __shared__ float red[4];
#pragma unroll
    for (int o = 16; o; o >>= 1) s += __shfl_xor_sync(0xffffffffu, s, o);
    if ((threadIdx.x & 31) == 0) red[threadIdx.x >> 5] = s;
    __syncthreads();
    float scale = wa.g[layer][row] / sqrtf(red[0] + red[1] + red[2] + red[3]);
    if (layer == 0) {
        for (int k = threadIdx.x; k < din; k += blockDim.x)
            g_w0[(size_t)row * din + k] = vr[k] * scale;
    } else {
        __half* w = g_wm + (size_t)(layer - 1) * 256 * 256 + (size_t)row * 256;
        for (int k = threadIdx.x; k < din; k += blockDim.x)
            w[k] = __float2half_rn(vr[k] * scale);
    }
}

// ------------------------- affine + xyz update -------------------------
__global__ __launch_bounds__(256) void affine_xyz(const __half* __restrict__ h_in,
                                                  const float* __restrict__ W_aff,
                                                  const float* __restrict__ b_aff)
{
    __shared__ float sW[6 * HID];
    for (int i = threadIdx.x; i < 6 * HID; i += 256) sW[i] = W_aff[i];
    __syncthreads();
    int warp = threadIdx.x >> 5, lane = threadIdx.x & 31;
    int m = blockIdx.x * 8 + warp;
    const __half* h = h_in + (size_t)m * HID;
    float p0 = 0, p1 = 0, p2 = 0, p3 = 0, p4 = 0, p5 = 0;
    for (int k = lane; k < HID; k += 32) {
        float hv = __half2float(h[k]);
        p0 += sW[k] * hv;           p1 += sW[HID + k] * hv;
        p2 += sW[2 * HID + k] * hv; p3 += sW[3 * HID + k] * hv;
        p4 += sW[4 * HID + k] * hv; p5 += sW[5 * HID + k] * hv;
    }
#pragma unroll
    for (int o = 16; o; o >>= 1) {
        p0 += __shfl_xor_sync(0xffffffffu, p0, o);
        p1 += __shfl_xor_sync(0xffffffffu, p1, o);
        p2 += __shfl_xor_sync(0xffffffffu, p2, o);
        p3 += __shfl_xor_sync(0xffffffffu, p3, o);
        p4 += __shfl_xor_sync(0xffffffffu, p4, o);
        p5 += __shfl_xor_sync(0xffffffffu, p5, o);
    }
    if (lane == 0) {
        float a0 = p0 + b_aff[0], a1 = p1 + b_aff[1], a2 = p2 + b_aff[2];
        float a3 = p3 + b_aff[3], a4 = p4 + b_aff[4], a5 = p5 + b_aff[5];
        float x0 = g_xyz[m * 3], x1 = g_xyz[m * 3 + 1], x2 = g_xyz[m * 3 + 2];
        g_xyz[m * 3 + 0] = a3 + (1.f + a0) * x0;
        g_xyz[m * 3 + 1] = a4 + (1.f + a1) * x1;
        g_xyz[m * 3 + 2] = a5 + (1.f + a2) * x2;
    }
}

// ------------------------- decoder layer 0 / final dot -------------------------
__global__ __launch_bounds__(256) void dec0(const float* __restrict__ b0)
{
    __shared__ float sw[768];
    __shared__ float sb[256];
    for (int i = threadIdx.x; i < 768; i += 256) sw[i] = g_w0[i];
    sb[threadIdx.x] = b0[threadIdx.x];
    __syncthreads();
    size_t idx = (size_t)blockIdx.x * 256 + threadIdx.x;
    int m = (int)(idx >> 8), i = (int)(idx & 255);
    float v = sw[i * 3] * g_xyz[m * 3] + sw[i * 3 + 1] * g_xyz[m * 3 + 1]
            + sw[i * 3 + 2] * g_xyz[m * 3 + 2] + sb[i];
    g_act0[idx] = __float2half_rn(fmaxf(v, 0.f));
}
__global__ __launch_bounds__(256) void dec5(const float* __restrict__ W5,
                                            const float* __restrict__ b5,
                                            const __half* __restrict__ x,
                                            float* __restrict__ out)
{
    __shared__ float sw[256];
    sw[threadIdx.x] = W5[threadIdx.x];
    __syncthreads();
    int warp = threadIdx.x >> 5, lane = threadIdx.x & 31;
    int m = blockIdx.x * 8 + warp;
    const __half* xr = x + (size_t)m * 256;
    float s = 0.f;
    for (int k = lane; k < 256; k += 32) s += __half2float(xr[k]) * sw[k];
#pragma unroll
    for (int o = 16; o; o >>= 1) s += __shfl_xor_sync(0xffffffffu, s, o);
    if (lane == 0) out[m] = s + b5[0];
}

// ------------------------- host launcher -------------------------
extern "C" void kernel_launch(void* const* d_in, const int* in_sizes, int n_in,
                              void* d_out, int out_size)
{
    const float* input = (const float*)d_in[0];
    const float* W_ih  = (const float*)d_in[1];
    const float* b_ih  = (const float*)d_in[2];
    const float* W_hh  = (const float*)d_in[3];
    const float* b_hh  = (const float*)d_in[4];
    const float* W_aff = (const float*)d_in[5];
    const float* b_aff = (const float*)d_in[6];
    WnArgs wa;
    const float* bb[5];
    for (int l = 0; l < 5; l++) {
        wa.v[l] = (const float*)d_in[7 + 3 * l];
        wa.g[l] = (const float*)d_in[8 + 3 * l];
        bb[l]   = (const float*)d_in[9 + 3 * l];
    }
    const float* W5 = (const float*)d_in[22];
    const float* b5 = (const float*)d_in[23];

    float *Gc, *cst, *xyz;
    __half *h0, *h1, *codep, *wihp, *whhp, *a0p, *a1p, *wmp;
    cudaGetSymbolAddress((void**)&Gc,    g_Gc);
    cudaGetSymbolAddress((void**)&h0,    g_h);
    cudaGetSymbolAddress((void**)&h1,    g_h2);
    cudaGetSymbolAddress((void**)&cst,   g_c);
    cudaGetSymbolAddress((void**)&xyz,   g_xyz);
    cudaGetSymbolAddress((void**)&codep, g_code);
    cudaGetSymbolAddress((void**)&wihp,  g_wih);
    cudaGetSymbolAddress((void**)&whhp,  g_whh);
    cudaGetSymbolAddress((void**)&a0p,   g_act0);
    cudaGetSymbolAddress((void**)&a1p,   g_act1);
    cudaGetSymbolAddress((void**)&wmp,   g_wm);

    const int SMEM = NSTAGE * (ABUF + BBUF);   // 81920 B per CTA
    cudaFuncSetAttribute(gemm_h<0>, cudaFuncAttributeMaxDynamicSharedMemorySize, SMEM);
    cudaFuncSetAttribute(gemm_h<1>, cudaFuncAttributeMaxDynamicSharedMemorySize, SMEM);
    cudaFuncSetAttribute(gemm_h<2>, cudaFuncAttributeMaxDynamicSharedMemorySize, SMEM);

    extract_code<<<NSAMP, 256>>>(input);
    prep_weights<<<NGATE, 256>>>(W_ih, W_hh);
    wnorm_all<<<1280, 128>>>(wa);

    // launch 3 (profiled): fused Gc GEMM + step-0 cell init
    gemm_h<0><<<dim3(NGATE / BN, NSAMP / BM), 256, SMEM>>>(
        codep, 256, wihp, 256, Gc, nullptr, 0, 256 / BK,
        b_ih, b_hh, W_ih, xyz, nullptr, cst, h0);

    affine_xyz<<<NSAMP / 8, 256>>>(h0, W_aff, b_aff);

    __half* hb[2] = { h0, h1 };
    for (int s = 1; s < 8; s++) {
        const __half* hin = hb[(s - 1) & 1];
        __half* hnew = hb[s & 1];
        gemm_h<1><<<dim3(HID / 32, NSAMP / BM), 256, SMEM>>>(
            hin, HID, whhp, HID, nullptr, nullptr, 0, HID / BK,
            nullptr, nullptr, W_ih, xyz, Gc, cst, hnew);
        affine_xyz<<<NSAMP / 8, 256>>>(hnew, W_aff, b_aff);
    }

    dec0<<<NSAMP, 256>>>(bb[0]);
    const __half* bufin = a0p;
    __half* bufout = a1p;
    for (int l = 1; l < 5; l++) {
        gemm_h<2><<<dim3(256 / BN, NSAMP / BM), 256, SMEM>>>(
            bufin, 256, wmp + (size_t)(l - 1) * 256 * 256, 256,
            nullptr, bufout, 256, 256 / BK,
            bb[l], nullptr, nullptr, nullptr, nullptr, nullptr, nullptr);
        const __half* tmp = bufout; bufout = (__half*)bufin; bufin = tmp;
    }
    dec5<<<NSAMP / 8, 256>>>(W5, b5, bufin, (float*)d_out);
}

// round 11
// speedup vs baseline: 3.3538x; 1.1088x over previous
#include <cuda_runtime.h>
#include <cuda_fp16.h>
#include <math.h>
#include <stdint.h>

#define NSAMP 65536
#define HID   512
#define NGATE 2048
#define DIN   259
#define BM 128
#define BN 128
#define BK 32
#define RS 20              // smem row stride in words (16 data + 4 pad)
#define ABUF (BM * RS * 4)
#define BBUF (BN * RS * 4)
#define NSTAGE 4

// ------------------------- scratch -------------------------
__device__ __half g_Gc [(size_t)NSAMP * NGATE];   // gate-interleaved [r][j*4+gate], fp16
__device__ __half g_h  [(size_t)NSAMP * HID];
__device__ __half g_h2 [(size_t)NSAMP * HID];
__device__ float  g_c  [(size_t)NSAMP * HID];
__device__ float  g_xyz[NSAMP * 3];
__device__ __half g_code[(size_t)NSAMP * 256];
__device__ __half g_wih [(size_t)NGATE * 256];
__device__ __half g_whh [(size_t)NGATE * HID];
__device__ __half g_act0[(size_t)NSAMP * 256];
__device__ __half g_act1[(size_t)NSAMP * 256];
__device__ float  g_w0  [256 * 3];
__device__ __half g_wm  [4 * 256 * 256];

__device__ __forceinline__ float sigm(float x) { return 1.f / (1.f + __expf(-x)); }
__device__ __forceinline__ void cp16(uint32_t d, const void* s) {
    asm volatile("cp.async.cg.shared.global [%0], [%1], 16;" :: "r"(d), "l"(s) : "memory");
}
__device__ __forceinline__ void mma16(float* d, const unsigned* a, unsigned b0, unsigned b1) {
    asm volatile(
        "mma.sync.aligned.m16n8k16.row.col.f32.f16.f16.f32 "
        "{%0,%1,%2,%3}, {%4,%5,%6,%7}, {%8,%9}, {%0,%1,%2,%3};"
        : "+f"(d[0]), "+f"(d[1]), "+f"(d[2]), "+f"(d[3])
        : "r"(a[0]), "r"(a[1]), "r"(a[2]), "r"(a[3]), "r"(b0), "r"(b1));
}
#define LDSM4(R, ADDR)                                                         \
    asm volatile("ldmatrix.sync.aligned.m8n8.x4.shared.b16 {%0,%1,%2,%3}, [%4];" \
        : "=r"((R)[0]), "=r"((R)[1]), "=r"((R)[2]), "=r"((R)[3]) : "r"(ADDR))

// =====================================================================
// FP16 GEMM (fp32 accum), 256 threads = 8 warps (4m x 2n), warp tile
// 32x64, block tile 128x128, BK=32, 4-stage cp.async, 2 CTAs/SM.
// MODE 0: Gc build (fp16, gate-interleaved) + step-0 cell init
// MODE 1: LSTM step s>=1 (reads interleaved fp16 Gc)
// MODE 2: decoder relu layer
// =====================================================================
template<int MODE>
__global__ void __launch_bounds__(256, 2) gemm_h(
    const __half* __restrict__ A, int lda,
    const __half* __restrict__ B, int ldb,
    __half* __restrict__ Ch, int ldc, int kIters,
    const float* __restrict__ bias, const float* __restrict__ bias2,
    const float* __restrict__ Wih, const float* __restrict__ xyz,
    __half* __restrict__ Gc,
    float* __restrict__ cst, __half* __restrict__ hout)
{
    extern __shared__ uint32_t smw[];
    const int tid = threadIdx.x, lane = tid & 31, wid = tid >> 5;
    const int wm = wid >> 1, wn = wid & 1;
    const int g = lane >> 2, t = lane & 3;
    const int m0 = blockIdx.y * BM;
    const int n0 = blockIdx.x * BN;
    const int j0 = blockIdx.x * 32;

    // ---- load roles ----
    const int arow = tid >> 1, seg = tid & 1;
    int brow;
    if (MODE == 0 || MODE == 1) {
        int w = arow >> 6, cw = arow & 63;
        brow = (cw >> 4) * HID + j0 + (cw & 15) + (w << 4);
    } else brow = n0 + arow;

    const __half* aptr = A + (size_t)(m0 + arow) * lda + seg * 16;
    const __half* bptr = B + (size_t)brow * ldb + seg * 16;

    const uint32_t asb = (uint32_t)__cvta_generic_to_shared(smw);
    const uint32_t bsb = asb + NSTAGE * ABUF;
    const uint32_t aoff = asb + arow * (RS * 4) + seg * 32;
    const uint32_t boff = bsb + arow * (RS * 4) + seg * 32;

    const int lr = lane & 15, lw = (lane >> 4) * 16;
    uint32_t aadr[2], badr[4];
#pragma unroll
    for (int mt = 0; mt < 2; mt++)
        aadr[mt] = asb + (uint32_t)((wm * 32 + mt * 16 + lr) * RS * 4) + lw;
#pragma unroll
    for (int p = 0; p < 4; p++)
        badr[p] = bsb + (uint32_t)((wn * 64 + p * 16 + lr) * RS * 4) + lw;

    float acc[2][8][4];
#pragma unroll
    for (int i = 0; i < 2; i++)
#pragma unroll
        for (int j = 0; j < 8; j++)
#pragma unroll
            for (int k = 0; k < 4; k++) acc[i][j][k] = 0.f;

#define LOADTILE(IT, BUF)                                                     \
    do {                                                                      \
        cp16(aoff + (BUF) * ABUF, aptr + (IT) * BK);                          \
        cp16(aoff + (BUF) * ABUF + 16, aptr + (IT) * BK + 8);                 \
        cp16(boff + (BUF) * BBUF, bptr + (IT) * BK);                          \
        cp16(boff + (BUF) * BBUF + 16, bptr + (IT) * BK + 8);                 \
    } while (0)

    LOADTILE(0, 0);
    asm volatile("cp.async.commit_group;" ::: "memory");
    LOADTILE(1, 1);
    asm volatile("cp.async.commit_group;" ::: "memory");
    LOADTILE(2, 2);
    asm volatile("cp.async.commit_group;" ::: "memory");

    for (int it = 0; it < kIters; ++it) {
        asm volatile("cp.async.wait_group 2;" ::: "memory");
        __syncthreads();
        if (it + 3 < kIters) LOADTILE(it + 3, (it + 3) & (NSTAGE - 1));
        asm volatile("cp.async.commit_group;" ::: "memory");

        const uint32_t ao = (it & (NSTAGE - 1)) * ABUF;
        const uint32_t bo = (it & (NSTAGE - 1)) * BBUF;
#pragma unroll
        for (int ks = 0; ks < 2; ks++) {
            unsigned af[2][4];
            LDSM4(af[0], aadr[0] + ao + ks * 32);
            LDSM4(af[1], aadr[1] + ao + ks * 32);
#pragma unroll
            for (int p = 0; p < 4; p++) {
                unsigned bb[4];
                LDSM4(bb, badr[p] + bo + ks * 32);
                mma16(acc[0][2 * p],     af[0], bb[0], bb[2]);
                mma16(acc[0][2 * p + 1], af[0], bb[1], bb[3]);
                mma16(acc[1][2 * p],     af[1], bb[0], bb[2]);
                mma16(acc[1][2 * p + 1], af[1], bb[1], bb[3]);
            }
        }
    }
#undef LOADTILE

    // ----------------- epilogue -----------------
    if (MODE == 0 || MODE == 1) {
#pragma unroll
        for (int q = 0; q < 2; q++) {
            const int jc = j0 + wn * 16 + q * 8 + 2 * t;
            float wt[4][2][3];
            float bi[4][2];
#pragma unroll
            for (int gt = 0; gt < 4; gt++)
#pragma unroll
                for (int e = 0; e < 2; e++) {
                    const float* wr = Wih + (size_t)(gt * HID + jc + e) * DIN + 256;
                    wt[gt][e][0] = wr[0]; wt[gt][e][1] = wr[1]; wt[gt][e][2] = wr[2];
                    if (MODE == 0)
                        bi[gt][e] = bias[gt * HID + jc + e] + bias2[gt * HID + jc + e];
                }
#pragma unroll
            for (int mt = 0; mt < 2; mt++)
#pragma unroll
                for (int rr = 0; rr < 2; rr++) {
                    int r = m0 + wm * 32 + mt * 16 + g + rr * 8;
                    float x0 = xyz[r * 3], x1 = xyz[r * 3 + 1], x2 = xyz[r * 3 + 2];
                    float2 cn; __half2 hn;
                    __half* gcp = Gc + (size_t)r * NGATE + jc * 4;  // interleaved, 16B aligned
                    if (MODE == 0) {
                        __align__(16) __half hg[8];
#pragma unroll
                        for (int e = 0; e < 2; e++) {
                            int a = rr * 2 + e;
                            float gcv[4], gate[4];
#pragma unroll
                            for (int gt = 0; gt < 4; gt++) {
                                gcv[gt] = acc[mt][2 * gt + q][a] + bi[gt][e];
                                gate[gt] = gcv[gt] + x0 * wt[gt][e][0]
                                         + x1 * wt[gt][e][1] + x2 * wt[gt][e][2];
                                hg[e * 4 + gt] = __float2half_rn(gcv[gt]);
                            }
                            float c2 = sigm(gate[0]) * tanhf(gate[2]);
                            __half h2 = __float2half_rn(sigm(gate[3]) * tanhf(c2));
                            if (e) { cn.y = c2; hn.y = h2; } else { cn.x = c2; hn.x = h2; }
                        }
                        *(uint4*)gcp = *(const uint4*)hg;
                    } else {
                        __align__(16) __half hg[8];
                        *(uint4*)hg = *(const uint4*)gcp;
                        float2 co = *(const float2*)(cst + (size_t)r * HID + jc);
#pragma unroll
                        for (int e = 0; e < 2; e++) {
                            int a = rr * 2 + e;
                            float iv = acc[mt][0 + q][a] + __half2float(hg[e * 4 + 0])
                                     + x0 * wt[0][e][0] + x1 * wt[0][e][1] + x2 * wt[0][e][2];
                            float fv = acc[mt][2 + q][a] + __half2float(hg[e * 4 + 1])
                                     + x0 * wt[1][e][0] + x1 * wt[1][e][1] + x2 * wt[1][e][2];
                            float gv = acc[mt][4 + q][a] + __half2float(hg[e * 4 + 2])
                                     + x0 * wt[2][e][0] + x1 * wt[2][e][1] + x2 * wt[2][e][2];
                            float ov = acc[mt][6 + q][a] + __half2float(hg[e * 4 + 3])
                                     + x0 * wt[3][e][0] + x1 * wt[3][e][1] + x2 * wt[3][e][2];
                            float cold = e ? co.y : co.x;
                            float c2 = sigm(fv) * cold + sigm(iv) * tanhf(gv);
                            __half h2 = __float2half_rn(sigm(ov) * tanhf(c2));
                            if (e) { cn.y = c2; hn.y = h2; } else { cn.x = c2; hn.x = h2; }
                        }
                    }
                    *(float2*)(cst + (size_t)r * HID + jc) = cn;
                    *(__half2*)(hout + (size_t)r * HID + jc) = hn;
                }
        }
    } else {
#pragma unroll
        for (int mt = 0; mt < 2; mt++)
#pragma unroll
            for (int nt = 0; nt < 8; nt++) {
                int c = n0 + wn * 64 + nt * 8 + 2 * t;
                float b0v = bias[c], b1v = bias[c + 1];
#pragma unroll
                for (int rr = 0; rr < 2; rr++) {
                    int r = m0 + wm * 32 + mt * 16 + g + rr * 8;
                    __half2 o;
                    o.x = __float2half_rn(fmaxf(acc[mt][nt][rr * 2 + 0] + b0v, 0.f));
                    o.y = __float2half_rn(fmaxf(acc[mt][nt][rr * 2 + 1] + b1v, 0.f));
                    *(__half2*)(Ch + (size_t)r * ldc + c) = o;
                }
            }
    }
}

// ------------------------- prep kernels -------------------------
__global__ void extract_code(const float* __restrict__ input)
{
    int m = blockIdx.x, k = threadIdx.x;
    g_code[(size_t)m * 256 + k] = __float2half_rn(input[(size_t)m * DIN + k]);
    if (k < 3) g_xyz[m * 3 + k] = input[(size_t)m * DIN + 256 + k];
}
__global__ void prep_weights(const float* __restrict__ W_ih, const float* __restrict__ W_hh)
{
    int r = blockIdx.x, t = threadIdx.x;
    g_wih[(size_t)r * 256 + t] = __float2half_rn(W_ih[(size_t)r * DIN + t]);
    g_whh[(size_t)r * HID + t]       = __float2half_rn(W_hh[(size_t)r * HID + t]);
    g_whh[(size_t)r * HID + 256 + t] = __float2half_rn(W_hh[(size_t)r * HID + 256 + t]);
}
struct WnArgs { const float* v[5]; const float* g[5]; };
__global__ void wnorm_all(WnArgs wa)
{
    int layer = blockIdx.x >> 8, row = blockIdx.x & 255;
    int din = (layer == 0) ? 3 : 256;
    const float* vr = wa.v[layer] + (size_t)row * din;
    float s = 0.f;
    for (int k = threadIdx.x; k < din; k += blockDim.x) { float x = vr[k]; s += x * x; }
    __shared__ float red[4];
#pragma unroll
    for (int o = 16; o; o >>= 1) s += __shfl_xor_sync(0xffffffffu, s, o);
    if ((threadIdx.x & 31) == 0) red[threadIdx.x >> 5] = s;
    __syncthreads();
    float scale = wa.g[layer][row] / sqrtf(red[0] + red[1] + red[2] + red[3]);
    if (layer == 0) {
        for (int k = threadIdx.x; k < din; k += blockDim.x)
            g_w0[(size_t)row * din + k] = vr[k] * scale;
    } else {
        __half* w = g_wm + (size_t)(layer - 1) * 256 * 256 + (size_t)row * 256;
        for (int k = threadIdx.x; k < din; k += blockDim.x)
            w[k] = __float2half_rn(vr[k] * scale);
    }
}

// ------------------------- affine + xyz update -------------------------
__global__ __launch_bounds__(256) void affine_xyz(const __half* __restrict__ h_in,
                                                  const float* __restrict__ W_aff,
                                                  const float* __restrict__ b_aff)
{
    __shared__ float sW[6 * HID];
    for (int i = threadIdx.x; i < 6 * HID; i += 256) sW[i] = W_aff[i];
    __syncthreads();
    int warp = threadIdx.x >> 5, lane = threadIdx.x & 31;
    int m = blockIdx.x * 8 + warp;
    const __half* h = h_in + (size_t)m * HID;
    float p0 = 0, p1 = 0, p2 = 0, p3 = 0, p4 = 0, p5 = 0;
    for (int k = lane; k < HID; k += 32) {
        float hv = __half2float(h[k]);
        p0 += sW[k] * hv;           p1 += sW[HID + k] * hv;
        p2 += sW[2 * HID + k] * hv; p3 += sW[3 * HID + k] * hv;
        p4 += sW[4 * HID + k] * hv; p5 += sW[5 * HID + k] * hv;
    }
#pragma unroll
    for (int o = 16; o; o >>= 1) {
        p0 += __shfl_xor_sync(0xffffffffu, p0, o);
        p1 += __shfl_xor_sync(0xffffffffu, p1, o);
        p2 += __shfl_xor_sync(0xffffffffu, p2, o);
        p3 += __shfl_xor_sync(0xffffffffu, p3, o);
        p4 += __shfl_xor_sync(0xffffffffu, p4, o);
        p5 += __shfl_xor_sync(0xffffffffu, p5, o);
    }
    if (lane == 0) {
        float a0 = p0 + b_aff[0], a1 = p1 + b_aff[1], a2 = p2 + b_aff[2];
        float a3 = p3 + b_aff[3], a4 = p4 + b_aff[4], a5 = p5 + b_aff[5];
        float x0 = g_xyz[m * 3], x1 = g_xyz[m * 3 + 1], x2 = g_xyz[m * 3 + 2];
        g_xyz[m * 3 + 0] = a3 + (1.f + a0) * x0;
        g_xyz[m * 3 + 1] = a4 + (1.f + a1) * x1;
        g_xyz[m * 3 + 2] = a5 + (1.f + a2) * x2;
    }
}

// ------------------------- decoder layer 0 / final dot -------------------------
__global__ __launch_bounds__(256) void dec0(const float* __restrict__ b0)
{
    __shared__ float sw[768];
    __shared__ float sb[256];
    for (int i = threadIdx.x; i < 768; i += 256) sw[i] = g_w0[i];
    sb[threadIdx.x] = b0[threadIdx.x];
    __syncthreads();
    size_t idx = (size_t)blockIdx.x * 256 + threadIdx.x;
    int m = (int)(idx >> 8), i = (int)(idx & 255);
    float v = sw[i * 3] * g_xyz[m * 3] + sw[i * 3 + 1] * g_xyz[m * 3 + 1]
            + sw[i * 3 + 2] * g_xyz[m * 3 + 2] + sb[i];
    g_act0[idx] = __float2half_rn(fmaxf(v, 0.f));
}
__global__ __launch_bounds__(256) void dec5(const float* __restrict__ W5,
                                            const float* __restrict__ b5,
                                            const __half* __restrict__ x,
                                            float* __restrict__ out)
{
    __shared__ float sw[256];
    sw[threadIdx.x] = W5[threadIdx.x];
    __syncthreads();
    int warp = threadIdx.x >> 5, lane = threadIdx.x & 31;
    int m = blockIdx.x * 8 + warp;
    const __half* xr = x + (size_t)m * 256;
    float s = 0.f;
    for (int k = lane; k < 256; k += 32) s += __half2float(xr[k]) * sw[k];
#pragma unroll
    for (int o = 16; o; o >>= 1) s += __shfl_xor_sync(0xffffffffu, s, o);
    if (lane == 0) out[m] = s + b5[0];
}

// ------------------------- host launcher -------------------------
extern "C" void kernel_launch(void* const* d_in, const int* in_sizes, int n_in,
                              void* d_out, int out_size)
{
    const float* input = (const float*)d_in[0];
    const float* W_ih  = (const float*)d_in[1];
    const float* b_ih  = (const float*)d_in[2];
    const float* W_hh  = (const float*)d_in[3];
    const float* b_hh  = (const float*)d_in[4];
    const float* W_aff = (const float*)d_in[5];
    const float* b_aff = (const float*)d_in[6];
    WnArgs wa;
    const float* bb[5];
    for (int l = 0; l < 5; l++) {
        wa.v[l] = (const float*)d_in[7 + 3 * l];
        wa.g[l] = (const float*)d_in[8 + 3 * l];
        bb[l]   = (const float*)d_in[9 + 3 * l];
    }
    const float* W5 = (const float*)d_in[22];
    const float* b5 = (const float*)d_in[23];

    float *cst, *xyz;
    __half *Gc, *h0, *h1, *codep, *wihp, *whhp, *a0p, *a1p, *wmp;
    cudaGetSymbolAddress((void**)&Gc,    g_Gc);
    cudaGetSymbolAddress((void**)&h0,    g_h);
    cudaGetSymbolAddress((void**)&h1,    g_h2);
    cudaGetSymbolAddress((void**)&cst,   g_c);
    cudaGetSymbolAddress((void**)&xyz,   g_xyz);
    cudaGetSymbolAddress((void**)&codep, g_code);
    cudaGetSymbolAddress((void**)&wihp,  g_wih);
    cudaGetSymbolAddress((void**)&whhp,  g_whh);
    cudaGetSymbolAddress((void**)&a0p,   g_act0);
    cudaGetSymbolAddress((void**)&a1p,   g_act1);
    cudaGetSymbolAddress((void**)&wmp,   g_wm);

    const int SMEM = NSTAGE * (ABUF + BBUF);   // 81920 B per CTA
    cudaFuncSetAttribute(gemm_h<0>, cudaFuncAttributeMaxDynamicSharedMemorySize, SMEM);
    cudaFuncSetAttribute(gemm_h<1>, cudaFuncAttributeMaxDynamicSharedMemorySize, SMEM);
    cudaFuncSetAttribute(gemm_h<2>, cudaFuncAttributeMaxDynamicSharedMemorySize, SMEM);

    extract_code<<<NSAMP, 256>>>(input);
    prep_weights<<<NGATE, 256>>>(W_ih, W_hh);
    wnorm_all<<<1280, 128>>>(wa);

    // launch 3 (profiled): fused Gc GEMM + step-0 cell init
    gemm_h<0><<<dim3(NGATE / BN, NSAMP / BM), 256, SMEM>>>(
        codep, 256, wihp, 256, nullptr, 0, 256 / BK,
        b_ih, b_hh, W_ih, xyz, Gc, cst, h0);

    affine_xyz<<<NSAMP / 8, 256>>>(h0, W_aff, b_aff);

    __half* hb[2] = { h0, h1 };
    for (int s = 1; s < 8; s++) {
        const __half* hin = hb[(s - 1) & 1];
        __half* hnew = hb[s & 1];
        gemm_h<1><<<dim3(HID / 32, NSAMP / BM), 256, SMEM>>>(
            hin, HID, whhp, HID, nullptr, 0, HID / BK,
            nullptr, nullptr, W_ih, xyz, Gc, cst, hnew);
        affine_xyz<<<NSAMP / 8, 256>>>(hnew, W_aff, b_aff);
    }

    dec0<<<NSAMP, 256>>>(bb[0]);
    const __half* bufin = a0p;
    __half* bufout = a1p;
    for (int l = 1; l < 5; l++) {
        gemm_h<2><<<dim3(256 / BN, NSAMP / BM), 256, SMEM>>>(
            bufin, 256, wmp + (size_t)(l - 1) * 256 * 256, 256,
            bufout, 256, 256 / BK,
            bb[l], nullptr, nullptr, nullptr, nullptr, nullptr, nullptr);
        const __half* tmp = bufout; bufout = (__half*)bufin; bufin = tmp;
    }
    dec5<<<NSAMP / 8, 256>>>(W5, b5, bufin, (float*)d_out);
}